// round 3
// baseline (speedup 1.0000x reference)
#include <cuda_runtime.h>
#include <cuda_bf16.h>
#include <math.h>

// Problem constants
#define BB 2
#define TT 2048
#define DD 1024
#define HH 16
#define HD 64
#define N3 3072
#define MTOT (BB*TT)          // 4096

// Scratch (device globals: allocation-free contract)
__device__ float g_q[BB*HH*TT*HD];     // (b,h,t,hd)
__device__ float g_k[BB*HH*TT*HD];
__device__ float g_v[BB*HH*TT*HD];
__device__ float g_att[BB*TT*DD];      // (b,t,d) pre-projection attention output

// ---------------------------------------------------------------------------
// Kernel 1: QKV GEMM.  C[m][n] = x[m][:] . w_qkv[:][n] + b_qkv[n]
// M=4096, N=3072, K=1024.  128x128 block tile, BK=16, 256 threads, 8x8/thread.
// Epilogue scatters into g_q/g_k/g_v laid out (b,h,t,hd).
// ---------------------------------------------------------------------------
__global__ __launch_bounds__(256) void qkv_gemm_kernel(
    const float* __restrict__ X, const float* __restrict__ W,
    const float* __restrict__ bias)
{
    __shared__ __align__(16) float As[16][132];
    __shared__ __align__(16) float Bs[16][128];

    const int tid = threadIdx.x;
    const int tx = tid & 15;
    const int ty = tid >> 4;
    const int m0 = blockIdx.y * 128;
    const int n0 = blockIdx.x * 128;

    float c[8][8];
#pragma unroll
    for (int i = 0; i < 8; ++i)
#pragma unroll
        for (int j = 0; j < 8; ++j) c[i][j] = 0.f;

    for (int k0 = 0; k0 < DD; k0 += 16) {
        // Load A tile 128x16 (transposed into As)
#pragma unroll
        for (int ii = 0; ii < 2; ++ii) {
            int idx = tid + ii * 256;          // 0..511 float4 slots
            int aRow = idx >> 2;
            int aCol = (idx & 3) << 2;
            float4 t = *(const float4*)(X + (size_t)(m0 + aRow) * DD + k0 + aCol);
            As[aCol + 0][aRow] = t.x;
            As[aCol + 1][aRow] = t.y;
            As[aCol + 2][aRow] = t.z;
            As[aCol + 3][aRow] = t.w;
        }
        // Load B tile 16x128
#pragma unroll
        for (int ii = 0; ii < 2; ++ii) {
            int idx = tid + ii * 256;
            int bRow = idx >> 5;
            int bCol = (idx & 31) << 2;
            *(float4*)(&Bs[bRow][bCol]) =
                *(const float4*)(W + (size_t)(k0 + bRow) * N3 + n0 + bCol);
        }
        __syncthreads();
#pragma unroll
        for (int kk = 0; kk < 16; ++kk) {
            float a[8], bv[8];
            *(float4*)(a)     = *(const float4*)(&As[kk][ty * 8]);
            *(float4*)(a + 4) = *(const float4*)(&As[kk][ty * 8 + 4]);
            *(float4*)(bv)     = *(const float4*)(&Bs[kk][tx * 8]);
            *(float4*)(bv + 4) = *(const float4*)(&Bs[kk][tx * 8 + 4]);
#pragma unroll
            for (int i = 0; i < 8; ++i)
#pragma unroll
                for (int j = 0; j < 8; ++j) c[i][j] += a[i] * bv[j];
        }
        __syncthreads();
    }

    // Epilogue: which tensor (q/k/v) is block-constant (128 | 1024)
    const int which = n0 >> 10;
    float* dst = (which == 0) ? g_q : ((which == 1) ? g_k : g_v);

#pragma unroll
    for (int i = 0; i < 8; ++i) {
        int m  = m0 + ty * 8 + i;
        int b_ = m >> 11;          // /T
        int t_ = m & (TT - 1);
#pragma unroll
        for (int j = 0; j < 8; j += 4) {
            int n  = n0 + tx * 8 + j;
            int nn = n & (DD - 1);
            int h  = nn >> 6;
            int hd = nn & (HD - 1);
            float4 v;
            v.x = c[i][j]     + bias[n];
            v.y = c[i][j + 1] + bias[n + 1];
            v.z = c[i][j + 2] + bias[n + 2];
            v.w = c[i][j + 3] + bias[n + 3];
            *(float4*)(dst + (((size_t)(b_ * HH + h) * TT + t_) << 6) + hd) = v;
        }
    }
}

// ---------------------------------------------------------------------------
// Kernel 2: periodic-sparse flash attention over residue-class subsequences.
// For (b,h) with period p, queries i = r + p*m form p independent dense
// causal attentions over subsequences of length L = ceil((T-r)/p).
// Block: 64 subsequence queries; 128 threads = 2 threads/query (32 dims each).
// Grid: (qtile=32, residue=16, bh=32); blocks with r>=p or tile>=L exit.
// ---------------------------------------------------------------------------
__global__ __launch_bounds__(128) void attn_kernel(const void* __restrict__ periods_raw)
{
    const int bh = blockIdx.z;
    const int b_ = bh >> 4;
    const int h  = bh & 15;

    // Detect int32 vs int64 periods buffer (values are in [0,16)).
    const int* pw = (const int*)periods_raw;
    bool is64 = true;
#pragma unroll
    for (int k2 = 1; k2 < 32; k2 += 2) is64 = is64 && (pw[k2] == 0);
    int p = is64 ? pw[2 * bh] : pw[bh];
    if (p < 1) p = 1;

    const int r = blockIdx.y;
    if (r >= p) return;
    const int L = (TT - r + p - 1) / p;
    const int m0 = blockIdx.x * 64;
    if (m0 >= L) return;
    const int m_max = min(m0 + 63, L - 1);

    __shared__ __align__(16) float Ks[64][64];
    __shared__ __align__(16) float Vs[64][64];

    const int tid  = threadIdx.x;
    const int ql   = tid >> 1;
    const int half = tid & 1;
    const int m    = m0 + ql;
    const bool active = (m < L);
    const int i_glob = r + p * (active ? m : 0);

    // Load query row (pre-scaled by 1/sqrt(HD))
    const float* qptr = g_q + ((size_t)bh * TT + i_glob) * HD + half * 32;
    float qreg[32];
#pragma unroll
    for (int d = 0; d < 32; d += 4) {
        float4 t = *(const float4*)(qptr + d);
        qreg[d]     = t.x * 0.125f;
        qreg[d + 1] = t.y * 0.125f;
        qreg[d + 2] = t.z * 0.125f;
        qreg[d + 3] = t.w * 0.125f;
    }

    float mi = -INFINITY, l = 0.f;
    float acc[32];
#pragma unroll
    for (int d = 0; d < 32; ++d) acc[d] = 0.f;

    const float* kbase = g_k + (size_t)bh * TT * HD;
    const float* vbase = g_v + (size_t)bh * TT * HD;

    const int ntiles = (m_max >> 6) + 1;
    for (int nt = 0; nt < ntiles; ++nt) {
        __syncthreads();
        {   // cooperative tile load: thread -> row ql, half-row of 32 floats
            int n = nt * 64 + ql;
            if (n <= m_max) {
                int jg = r + p * n;
                const float* ks = kbase + (size_t)jg * HD + half * 32;
                const float* vs = vbase + (size_t)jg * HD + half * 32;
#pragma unroll
                for (int d = 0; d < 32; d += 4) {
                    *(float4*)(&Ks[ql][half * 32 + d]) = *(const float4*)(ks + d);
                    *(float4*)(&Vs[ql][half * 32 + d]) = *(const float4*)(vs + d);
                }
            }
        }
        __syncthreads();

        const int jmax = min(63, m_max - nt * 64);
        for (int j = 0; j <= jmax; ++j) {
            float sp = 0.f;
#pragma unroll
            for (int d = 0; d < 32; ++d) sp += qreg[d] * Ks[j][half * 32 + d];
            float s = sp + __shfl_xor_sync(0xffffffffu, sp, 1);
            int n_ = nt * 64 + j;
            s = (active && n_ <= m) ? s : -INFINITY;
            float mn   = fmaxf(mi, s);
            float corr = __expf(mi - mn);
            float pe   = __expf(s - mn);
            l  = l * corr + pe;
            mi = mn;
#pragma unroll
            for (int d = 0; d < 32; ++d)
                acc[d] = acc[d] * corr + pe * Vs[j][half * 32 + d];
        }
    }

    if (active) {
        float inv = 1.f / l;   // diagonal key always valid -> l > 0
        float* optr = g_att + ((size_t)(b_ * TT + i_glob)) * DD + h * HD + half * 32;
#pragma unroll
        for (int d = 0; d < 32; d += 4) {
            float4 t;
            t.x = acc[d]     * inv;
            t.y = acc[d + 1] * inv;
            t.z = acc[d + 2] * inv;
            t.w = acc[d + 3] * inv;
            *(float4*)(optr + d) = t;
        }
    }
}

// ---------------------------------------------------------------------------
// Kernel 3: output projection.  out[m][n] = g_att[m][:] . w_out[:][n] + b_out[n]
// M=4096, N=1024, K=1024.
// ---------------------------------------------------------------------------
__global__ __launch_bounds__(256) void out_gemm_kernel(
    const float* __restrict__ W, const float* __restrict__ bias,
    float* __restrict__ Y)
{
    __shared__ __align__(16) float As[16][132];
    __shared__ __align__(16) float Bs[16][128];

    const int tid = threadIdx.x;
    const int tx = tid & 15;
    const int ty = tid >> 4;
    const int m0 = blockIdx.y * 128;
    const int n0 = blockIdx.x * 128;

    float c[8][8];
#pragma unroll
    for (int i = 0; i < 8; ++i)
#pragma unroll
        for (int j = 0; j < 8; ++j) c[i][j] = 0.f;

    for (int k0 = 0; k0 < DD; k0 += 16) {
#pragma unroll
        for (int ii = 0; ii < 2; ++ii) {
            int idx = tid + ii * 256;
            int aRow = idx >> 2;
            int aCol = (idx & 3) << 2;
            float4 t = *(const float4*)(g_att + (size_t)(m0 + aRow) * DD + k0 + aCol);
            As[aCol + 0][aRow] = t.x;
            As[aCol + 1][aRow] = t.y;
            As[aCol + 2][aRow] = t.z;
            As[aCol + 3][aRow] = t.w;
        }
#pragma unroll
        for (int ii = 0; ii < 2; ++ii) {
            int idx = tid + ii * 256;
            int bRow = idx >> 5;
            int bCol = (idx & 31) << 2;
            *(float4*)(&Bs[bRow][bCol]) =
                *(const float4*)(W + (size_t)(k0 + bRow) * DD + n0 + bCol);
        }
        __syncthreads();
#pragma unroll
        for (int kk = 0; kk < 16; ++kk) {
            float a[8], bv[8];
            *(float4*)(a)     = *(const float4*)(&As[kk][ty * 8]);
            *(float4*)(a + 4) = *(const float4*)(&As[kk][ty * 8 + 4]);
            *(float4*)(bv)     = *(const float4*)(&Bs[kk][tx * 8]);
            *(float4*)(bv + 4) = *(const float4*)(&Bs[kk][tx * 8 + 4]);
#pragma unroll
            for (int i = 0; i < 8; ++i)
#pragma unroll
                for (int j = 0; j < 8; ++j) c[i][j] += a[i] * bv[j];
        }
        __syncthreads();
    }

#pragma unroll
    for (int i = 0; i < 8; ++i) {
        int m = m0 + ty * 8 + i;
#pragma unroll
        for (int j = 0; j < 8; j += 4) {
            int n = n0 + tx * 8 + j;
            float4 v;
            v.x = c[i][j]     + bias[n];
            v.y = c[i][j + 1] + bias[n + 1];
            v.z = c[i][j + 2] + bias[n + 2];
            v.w = c[i][j + 3] + bias[n + 3];
            *(float4*)(Y + (size_t)m * DD + n) = v;
        }
    }
}

// ---------------------------------------------------------------------------
extern "C" void kernel_launch(void* const* d_in, const int* in_sizes, int n_in,
                              void* d_out, int out_size)
{
    const float* x      = (const float*)d_in[0];
    const void*  per    = d_in[1];                  // int32 or int64, detected on device
    const float* w_qkv  = (const float*)d_in[2];
    const float* b_qkv  = (const float*)d_in[3];
    const float* w_out  = (const float*)d_in[4];
    const float* b_out  = (const float*)d_in[5];
    float* out = (float*)d_out;

    dim3 g1(N3 / 128, MTOT / 128);   // 24 x 32
    qkv_gemm_kernel<<<g1, 256>>>(x, w_qkv, b_qkv);

    dim3 g2(32, 16, BB * HH);        // qtile, residue, bh
    attn_kernel<<<g2, 128>>>(per);

    dim3 g3(DD / 128, MTOT / 128);   // 8 x 32
    out_gemm_kernel<<<g3, 256>>>(w_out, b_out, out);
}

// round 4
// speedup vs baseline: 2.0023x; 2.0023x over previous
#include <cuda_runtime.h>
#include <cuda_bf16.h>
#include <math.h>
#include <stdint.h>

// Problem constants
#define BB 2
#define TT 2048
#define DD 1024
#define HH 16
#define HD 64
#define N3 3072
#define MTOT (BB*TT)          // 4096
#define KK 1024

typedef __nv_bfloat16 bf16;

// ---------------------------------------------------------------------------
// Device-global scratch (allocation-free contract)
// ---------------------------------------------------------------------------
__device__ bf16  g_xhi[MTOT*DD];        // x split hi/lo, row-major [m][k]
__device__ bf16  g_xlo[MTOT*DD];
__device__ bf16  g_wqT_hi[N3*KK];       // w_qkv^T split, [n][k]
__device__ bf16  g_wqT_lo[N3*KK];
__device__ bf16  g_woT_hi[DD*KK];       // w_out^T split, [n][k]
__device__ bf16  g_woT_lo[DD*KK];
__device__ float g_q[BB*HH*TT*HD];      // (b,h,t,hd) fp32
__device__ float g_k[BB*HH*TT*HD];
__device__ float g_v[BB*HH*TT*HD];
__device__ bf16  g_atthi[MTOT*DD];      // attention output split, [m][d]
__device__ bf16  g_attlo[MTOT*DD];

// ---------------------------------------------------------------------------
// bf16 hi/lo split helpers
// ---------------------------------------------------------------------------
__device__ __forceinline__ void split_bf16(float x, bf16& hi, bf16& lo) {
    hi = __float2bfloat16_rn(x);
    lo = __float2bfloat16_rn(x - __bfloat162float(hi));
}

// ---------------------------------------------------------------------------
// Pre-pass 1: elementwise split of x (layout preserved)
// ---------------------------------------------------------------------------
__global__ __launch_bounds__(256) void convert_split_kernel(
    const float* __restrict__ src, bf16* __restrict__ hi, bf16* __restrict__ lo, int n4)
{
    int i = blockIdx.x * 256 + threadIdx.x;
    if (i >= n4) return;
    float4 v = ((const float4*)src)[i];
    bf16 h0,h1,h2,h3,l0,l1,l2,l3;
    split_bf16(v.x,h0,l0); split_bf16(v.y,h1,l1);
    split_bf16(v.z,h2,l2); split_bf16(v.w,h3,l3);
    __nv_bfloat162* ph = (__nv_bfloat162*)hi;
    __nv_bfloat162* pl = (__nv_bfloat162*)lo;
    ph[2*i]   = __nv_bfloat162(h0,h1);
    ph[2*i+1] = __nv_bfloat162(h2,h3);
    pl[2*i]   = __nv_bfloat162(l0,l1);
    pl[2*i+1] = __nv_bfloat162(l2,l3);
}

// ---------------------------------------------------------------------------
// Pre-pass 2: transpose + split weights  src[K][N] fp32 -> dst[N][K] bf16 hi/lo
// ---------------------------------------------------------------------------
__global__ __launch_bounds__(256) void transpose_split_kernel(
    const float* __restrict__ src, bf16* __restrict__ dh, bf16* __restrict__ dl, int Kdim, int Ndim)
{
    __shared__ float t[32][33];
    int tx = threadIdx.x, ty = threadIdx.y;
    int n0 = blockIdx.x * 32, k0 = blockIdx.y * 32;
#pragma unroll
    for (int i = 0; i < 4; ++i)
        t[ty + 8*i][tx] = src[(size_t)(k0 + ty + 8*i) * Ndim + n0 + tx];
    __syncthreads();
#pragma unroll
    for (int i = 0; i < 4; ++i) {
        float v = t[tx][ty + 8*i];
        bf16 h, l; split_bf16(v, h, l);
        size_t o = (size_t)(n0 + ty + 8*i) * Kdim + k0 + tx;
        dh[o] = h; dl[o] = l;
    }
}

// ---------------------------------------------------------------------------
// mma.sync m16n8k16 bf16 -> f32
// ---------------------------------------------------------------------------
__device__ __forceinline__ void mma16816(float* c,
    uint32_t a0, uint32_t a1, uint32_t a2, uint32_t a3, uint32_t b0, uint32_t b1)
{
    asm volatile(
        "mma.sync.aligned.m16n8k16.row.col.f32.bf16.bf16.f32 "
        "{%0,%1,%2,%3}, {%4,%5,%6,%7}, {%8,%9}, {%0,%1,%2,%3};\n"
        : "+f"(c[0]), "+f"(c[1]), "+f"(c[2]), "+f"(c[3])
        : "r"(a0), "r"(a1), "r"(a2), "r"(a3), "r"(b0), "r"(b1));
}

// ---------------------------------------------------------------------------
// GEMM core: C(128x128) = A[m0..][:] * B^T[n0..][:] with bf16x3 split.
// A row-major [m][1024] (hi/lo), BT row-major [n][1024] (hi/lo).
// 256 threads = 8 warps in 2(M)x4(N); warp tile 64x32; BK=32.
// ---------------------------------------------------------------------------
struct GemmSmem {
    bf16 Ah[128][40];
    bf16 Al[128][40];
    bf16 Bh[128][40];
    bf16 Bl[128][40];
};

__device__ __forceinline__ void gemm_core(
    const bf16* __restrict__ Ahi, const bf16* __restrict__ Alo,
    const bf16* __restrict__ BThi, const bf16* __restrict__ BTlo,
    int m0, int n0, GemmSmem& s, float c[4][4][4])
{
    const int tid  = threadIdx.x;
    const int lane = tid & 31;
    const int warp = tid >> 5;
    const int wm = warp >> 2;          // 0..1
    const int wn = warp & 3;           // 0..3
    const int ro = lane >> 2;          // 0..7
    const int co = (lane & 3) * 2;     // 0,2,4,6

#pragma unroll
    for (int i = 0; i < 4; ++i)
#pragma unroll
        for (int j = 0; j < 4; ++j)
#pragma unroll
            for (int q = 0; q < 4; ++q) c[i][j][q] = 0.f;

    for (int k0 = 0; k0 < KK; k0 += 32) {
        // ---- stage tiles ----
#pragma unroll
        for (int it = 0; it < 2; ++it) {
            int ch  = tid + it * 256;           // 0..511
            int row = ch >> 2;
            int c8  = (ch & 3) * 8;
            size_t ao = (size_t)(m0 + row) * KK + k0 + c8;
            size_t bo = (size_t)(n0 + row) * KK + k0 + c8;
            *(uint4*)&s.Ah[row][c8] = *(const uint4*)(Ahi  + ao);
            *(uint4*)&s.Al[row][c8] = *(const uint4*)(Alo  + ao);
            *(uint4*)&s.Bh[row][c8] = *(const uint4*)(BThi + bo);
            *(uint4*)&s.Bl[row][c8] = *(const uint4*)(BTlo + bo);
        }
        __syncthreads();

        // ---- compute ----
#pragma unroll
        for (int ks = 0; ks < 2; ++ks) {
            const int kw = ks * 16 + co;
            uint32_t bh[4][2], bl[4][2];
#pragma unroll
            for (int ni = 0; ni < 4; ++ni) {
                int nr = wn * 32 + ni * 8 + ro;
                bh[ni][0] = *(const uint32_t*)&s.Bh[nr][kw];
                bh[ni][1] = *(const uint32_t*)&s.Bh[nr][kw + 8];
                bl[ni][0] = *(const uint32_t*)&s.Bl[nr][kw];
                bl[ni][1] = *(const uint32_t*)&s.Bl[nr][kw + 8];
            }
#pragma unroll
            for (int mi = 0; mi < 4; ++mi) {
                int mr = wm * 64 + mi * 16 + ro;
                uint32_t ah0 = *(const uint32_t*)&s.Ah[mr][kw];
                uint32_t ah1 = *(const uint32_t*)&s.Ah[mr + 8][kw];
                uint32_t ah2 = *(const uint32_t*)&s.Ah[mr][kw + 8];
                uint32_t ah3 = *(const uint32_t*)&s.Ah[mr + 8][kw + 8];
                uint32_t al0 = *(const uint32_t*)&s.Al[mr][kw];
                uint32_t al1 = *(const uint32_t*)&s.Al[mr + 8][kw];
                uint32_t al2 = *(const uint32_t*)&s.Al[mr][kw + 8];
                uint32_t al3 = *(const uint32_t*)&s.Al[mr + 8][kw + 8];
#pragma unroll
                for (int ni = 0; ni < 4; ++ni) {
                    mma16816(c[mi][ni], ah0, ah1, ah2, ah3, bh[ni][0], bh[ni][1]);
                    mma16816(c[mi][ni], ah0, ah1, ah2, ah3, bl[ni][0], bl[ni][1]);
                    mma16816(c[mi][ni], al0, al1, al2, al3, bh[ni][0], bh[ni][1]);
                }
            }
        }
        __syncthreads();
    }
}

// ---------------------------------------------------------------------------
// Kernel 1: QKV GEMM (bf16x3) with scatter epilogue into g_q/g_k/g_v
// ---------------------------------------------------------------------------
__global__ __launch_bounds__(256, 2) void qkv_gemm_bf16(const float* __restrict__ bias)
{
    __shared__ GemmSmem s;
    float c[4][4][4];
    const int m0 = blockIdx.y * 128;
    const int n0 = blockIdx.x * 128;
    gemm_core(g_xhi, g_xlo, g_wqT_hi, g_wqT_lo, m0, n0, s, c);

    const int tid  = threadIdx.x;
    const int lane = tid & 31;
    const int warp = tid >> 5;
    const int wm = warp >> 2, wn = warp & 3;
    const int ro = lane >> 2, co = (lane & 3) * 2;

    const int which = n0 >> 10;
    float* dst = (which == 0) ? g_q : ((which == 1) ? g_k : g_v);

#pragma unroll
    for (int mi = 0; mi < 4; ++mi) {
#pragma unroll
        for (int ni = 0; ni < 4; ++ni) {
            int n_a = n0 + wn * 32 + ni * 8 + co;
            int nn = n_a & (DD - 1);
            int hh = nn >> 6;
            int hd = nn & (HD - 1);
            float b0v = bias[n_a], b1v = bias[n_a + 1];
#pragma unroll
            for (int half = 0; half < 2; ++half) {
                int m = m0 + wm * 64 + mi * 16 + ro + half * 8;
                int b_ = m >> 11;
                int t_ = m & (TT - 1);
                float2 v;
                v.x = c[mi][ni][half * 2]     + b0v;
                v.y = c[mi][ni][half * 2 + 1] + b1v;
                *(float2*)(dst + (((size_t)(b_ * HH + hh) * TT + t_) << 6) + hd) = v;
            }
        }
    }
}

// ---------------------------------------------------------------------------
// Kernel 3: output projection (bf16x3) -> d_out fp32
// ---------------------------------------------------------------------------
__global__ __launch_bounds__(256, 2) void out_gemm_bf16(
    const float* __restrict__ bias, float* __restrict__ Y)
{
    __shared__ GemmSmem s;
    float c[4][4][4];
    const int m0 = blockIdx.y * 128;
    const int n0 = blockIdx.x * 128;
    gemm_core(g_atthi, g_attlo, g_woT_hi, g_woT_lo, m0, n0, s, c);

    const int tid  = threadIdx.x;
    const int lane = tid & 31;
    const int warp = tid >> 5;
    const int wm = warp >> 2, wn = warp & 3;
    const int ro = lane >> 2, co = (lane & 3) * 2;

#pragma unroll
    for (int mi = 0; mi < 4; ++mi) {
#pragma unroll
        for (int ni = 0; ni < 4; ++ni) {
            int n_a = n0 + wn * 32 + ni * 8 + co;
            float b0v = bias[n_a], b1v = bias[n_a + 1];
#pragma unroll
            for (int half = 0; half < 2; ++half) {
                int m = m0 + wm * 64 + mi * 16 + ro + half * 8;
                float2 v;
                v.x = c[mi][ni][half * 2]     + b0v;
                v.y = c[mi][ni][half * 2 + 1] + b1v;
                *(float2*)(Y + (size_t)m * DD + n_a) = v;
            }
        }
    }
}

// ---------------------------------------------------------------------------
// Kernel 2: periodic-sparse flash attention.
// 64 queries/block, 256 threads: 2 key-split groups of 128 (2 threads/query).
// Group g processes key tiles (32 keys each) nt = g, g+2, ...; online-softmax
// partials merged via shared memory at the end. 8-key batching in inner loop.
// Epilogue writes bf16 hi/lo split directly (feeds out_gemm).
// ---------------------------------------------------------------------------
__global__ __launch_bounds__(256) void attn_kernel(const void* __restrict__ periods_raw)
{
    const int bh = blockIdx.z;
    const int b_ = bh >> 4;
    const int h  = bh & 15;

    // Detect int32 vs int64 periods buffer (values in [0,16)).
    const int* pw = (const int*)periods_raw;
    bool is64 = true;
#pragma unroll
    for (int k2 = 1; k2 < 32; k2 += 2) is64 = is64 && (pw[k2] == 0);
    int p = is64 ? pw[2 * bh] : pw[bh];
    if (p < 1) p = 1;

    const int r = blockIdx.y;
    if (r >= p) return;
    const int L = (TT - r + p - 1) / p;
    const int m0 = blockIdx.x * 64;
    if (m0 >= L) return;
    const int m_max = min(m0 + 63, L - 1);

    __shared__ float KV[2][2][32][64];   // [group][K/V][row][dim] ; reused as merge buffer
    __shared__ float sM[256], sL[256];

    const int tid  = threadIdx.x;
    const int g    = tid >> 7;           // key-split group
    const int lt   = tid & 127;
    const int ql   = lt >> 1;
    const int half = lt & 1;
    const int m    = m0 + ql;
    const bool active = (m < L);
    const int i_glob = r + p * (active ? m : 0);

    // Query row (pre-scaled by 1/sqrt(HD))
    const float* qptr = g_q + ((size_t)bh * TT + i_glob) * HD + half * 32;
    float qreg[32];
#pragma unroll
    for (int d = 0; d < 32; d += 4) {
        float4 t = *(const float4*)(qptr + d);
        qreg[d]     = t.x * 0.125f;
        qreg[d + 1] = t.y * 0.125f;
        qreg[d + 2] = t.z * 0.125f;
        qreg[d + 3] = t.w * 0.125f;
    }

    float mi = -1e30f, l = 0.f;
    float acc[32];
#pragma unroll
    for (int d = 0; d < 32; ++d) acc[d] = 0.f;

    const float* kbase = g_k + (size_t)bh * TT * HD;
    const float* vbase = g_v + (size_t)bh * TT * HD;

    const int ntiles = (m_max >> 5) + 1;
    const int iters  = (ntiles + 1) >> 1;

    for (int it = 0; it < iters; ++it) {
        const int nt = it * 2 + g;
        const bool vt = (nt < ntiles);
        __syncthreads();
        if (vt) {   // load 32 keys x 64 dims (K and V), zero-fill past m_max
            int row = lt >> 2;
            int q4  = lt & 3;
            int n   = nt * 32 + row;
            float4* kd = (float4*)&KV[g][0][row][q4 * 16];
            float4* vd = (float4*)&KV[g][1][row][q4 * 16];
            if (n <= m_max) {
                int jg = r + p * n;
                const float4* ks = (const float4*)(kbase + (size_t)jg * HD + q4 * 16);
                const float4* vs = (const float4*)(vbase + (size_t)jg * HD + q4 * 16);
#pragma unroll
                for (int q = 0; q < 4; ++q) { kd[q] = ks[q]; vd[q] = vs[q]; }
            } else {
                float4 z = make_float4(0.f, 0.f, 0.f, 0.f);
#pragma unroll
                for (int q = 0; q < 4; ++q) { kd[q] = z; vd[q] = z; }
            }
        }
        __syncthreads();
        if (!vt) continue;

        const int jmax = min(31, m_max - nt * 32);
        for (int jb = 0; jb <= jmax; jb += 8) {
            float sc[8];
#pragma unroll
            for (int jj = 0; jj < 8; ++jj) {
                float sp = 0.f;
                const float4* kr = (const float4*)&KV[g][0][jb + jj][half * 32];
#pragma unroll
                for (int d4 = 0; d4 < 8; ++d4) {
                    float4 kk = kr[d4];
                    sp += qreg[d4*4]   * kk.x + qreg[d4*4+1] * kk.y
                        + qreg[d4*4+2] * kk.z + qreg[d4*4+3] * kk.w;
                }
                sc[jj] = sp + __shfl_xor_sync(0xffffffffu, sp, 1);
            }
            float gm = -INFINITY;
#pragma unroll
            for (int jj = 0; jj < 8; ++jj) {
                int n_ = nt * 32 + jb + jj;
                bool val = active && (n_ <= m);
                sc[jj] = val ? sc[jj] : -INFINITY;
                gm = fmaxf(gm, sc[jj]);
            }
            float mn   = fmaxf(mi, gm);          // mi >= -1e30 keeps mn finite
            float corr = __expf(mi - mn);
            float pe[8];
            float psum = 0.f;
#pragma unroll
            for (int jj = 0; jj < 8; ++jj) { pe[jj] = __expf(sc[jj] - mn); psum += pe[jj]; }
            l  = l * corr + psum;
            mi = mn;
#pragma unroll
            for (int d = 0; d < 32; ++d) acc[d] *= corr;
#pragma unroll
            for (int jj = 0; jj < 8; ++jj) {
                float pj = pe[jj];
                const float4* vr = (const float4*)&KV[g][1][jb + jj][half * 32];
#pragma unroll
                for (int d4 = 0; d4 < 8; ++d4) {
                    float4 vv = vr[d4];
                    acc[d4*4]   += pj * vv.x;
                    acc[d4*4+1] += pj * vv.y;
                    acc[d4*4+2] += pj * vv.z;
                    acc[d4*4+3] += pj * vv.w;
                }
            }
        }
    }

    // ---- merge the two key-split groups ----
    __syncthreads();
    sM[g * 128 + lt] = mi;
    sL[g * 128 + lt] = l;
    float* sP = &KV[0][0][0][0];     // reuse as [g][ql][64]
    {
        float* dstp = &sP[((g * 64 + ql) * 64) + half * 32];
#pragma unroll
        for (int d = 0; d < 32; ++d) dstp[d] = acc[d];
    }
    __syncthreads();

    if (g == 0 && active) {
        float m1 = sM[128 + lt];
        float l1 = sL[128 + lt];
        float mo = fmaxf(mi, m1);
        float c0 = __expf(mi - mo);
        float c1 = __expf(m1 - mo);
        float lt_ = l * c0 + l1 * c1;   // diagonal key guarantees lt_ > 0
        float inv = 1.f / lt_;
        const float* a1p = &sP[((64 + ql) * 64) + half * 32];
        size_t ob = ((size_t)(b_ * TT + i_glob)) * DD + h * HD + half * 32;
        __nv_bfloat162* oh = (__nv_bfloat162*)(g_atthi + ob);
        __nv_bfloat162* ol = (__nv_bfloat162*)(g_attlo + ob);
#pragma unroll
        for (int d = 0; d < 32; d += 2) {
            float v0 = (acc[d]     * c0 + a1p[d]     * c1) * inv;
            float v1 = (acc[d + 1] * c0 + a1p[d + 1] * c1) * inv;
            bf16 h0, l0, h1, l1b;
            split_bf16(v0, h0, l0);
            split_bf16(v1, h1, l1b);
            oh[d >> 1] = __nv_bfloat162(h0, h1);
            ol[d >> 1] = __nv_bfloat162(l0, l1b);
        }
    }
}

// ---------------------------------------------------------------------------
extern "C" void kernel_launch(void* const* d_in, const int* in_sizes, int n_in,
                              void* d_out, int out_size)
{
    const float* x      = (const float*)d_in[0];
    const void*  per    = d_in[1];                  // int32 or int64, detected on device
    const float* w_qkv  = (const float*)d_in[2];
    const float* b_qkv  = (const float*)d_in[3];
    const float* w_out  = (const float*)d_in[4];
    const float* b_out  = (const float*)d_in[5];
    float* out = (float*)d_out;

    bf16 *xhi, *xlo, *wqh, *wql, *woh, *wol;
    cudaGetSymbolAddress((void**)&xhi, g_xhi);
    cudaGetSymbolAddress((void**)&xlo, g_xlo);
    cudaGetSymbolAddress((void**)&wqh, g_wqT_hi);
    cudaGetSymbolAddress((void**)&wql, g_wqT_lo);
    cudaGetSymbolAddress((void**)&woh, g_woT_hi);
    cudaGetSymbolAddress((void**)&wol, g_woT_lo);

    // Pre-passes: split x; transpose+split weights
    convert_split_kernel<<<(MTOT*DD/4 + 255)/256, 256>>>(x, xhi, xlo, MTOT*DD/4);
    {
        dim3 b(32, 8);
        dim3 gq(N3/32, KK/32);
        transpose_split_kernel<<<gq, b>>>(w_qkv, wqh, wql, KK, N3);
        dim3 go(DD/32, KK/32);
        transpose_split_kernel<<<go, b>>>(w_out, woh, wol, KK, DD);
    }

    dim3 g1(N3/128, MTOT/128);        // 24 x 32
    qkv_gemm_bf16<<<g1, 256>>>(b_qkv);

    dim3 g2(32, 16, BB*HH);           // qtile, residue, bh
    attn_kernel<<<g2, 256>>>(per);

    dim3 g3(DD/128, MTOT/128);        // 8 x 32
    out_gemm_bf16<<<g3, 256>>>(b_out, out);
}

// round 8
// speedup vs baseline: 2.0630x; 1.0303x over previous
#include <cuda_runtime.h>
#include <cuda_bf16.h>
#include <math.h>
#include <stdint.h>

// Problem constants
#define BB 2
#define TT 2048
#define DD 1024
#define HH 16
#define HD 64
#define N3 3072
#define MTOT (BB*TT)          // 4096
#define KK 1024

typedef __nv_bfloat16 bf16;

// ---------------------------------------------------------------------------
// Device-global scratch (allocation-free contract)
// ---------------------------------------------------------------------------
__device__ bf16  g_xhi[MTOT*DD];        // x split hi/lo, row-major [m][k]
__device__ bf16  g_xlo[MTOT*DD];
__device__ bf16  g_wqT_hi[N3*KK];       // w_qkv^T split, [n][k]
__device__ bf16  g_wqT_lo[N3*KK];
__device__ bf16  g_woT_hi[DD*KK];       // w_out^T split, [n][k]
__device__ bf16  g_woT_lo[DD*KK];
__device__ float g_q[BB*HH*TT*HD];      // (b,h,t,hd) fp32
__device__ float g_k[BB*HH*TT*HD];
__device__ float g_v[BB*HH*TT*HD];
__device__ bf16  g_atthi[MTOT*DD];      // attention output split, [m][d]
__device__ bf16  g_attlo[MTOT*DD];
__device__ float g_num[MTOT*DD];        // multi-chunk partial numerator (b,t,d)
__device__ float g_den[BB*HH*TT];       // multi-chunk partial denominator [bh][t]
__device__ int      g_nwork;
__device__ uint32_t g_work[2600];

// ---------------------------------------------------------------------------
// helpers
// ---------------------------------------------------------------------------
__device__ __forceinline__ void split_bf16(float x, bf16& hi, bf16& lo) {
    hi = __float2bfloat16_rn(x);
    lo = __float2bfloat16_rn(x - __bfloat162float(hi));
}
__device__ __forceinline__ void cp16(void* smp, const void* g) {
    uint32_t s = (uint32_t)__cvta_generic_to_shared(smp);
    asm volatile("cp.async.cg.shared.global [%0], [%1], 16;\n" :: "r"(s), "l"(g));
}
__device__ __forceinline__ void cp_commit() { asm volatile("cp.async.commit_group;\n"); }
__device__ __forceinline__ void cp_wait0()  { asm volatile("cp.async.wait_group 0;\n"); }

__device__ __forceinline__ void mma16816(float* c,
    uint32_t a0, uint32_t a1, uint32_t a2, uint32_t a3, uint32_t b0, uint32_t b1)
{
    asm volatile(
        "mma.sync.aligned.m16n8k16.row.col.f32.bf16.bf16.f32 "
        "{%0,%1,%2,%3}, {%4,%5,%6,%7}, {%8,%9}, {%0,%1,%2,%3};\n"
        : "+f"(c[0]), "+f"(c[1]), "+f"(c[2]), "+f"(c[3])
        : "r"(a0), "r"(a1), "r"(a2), "r"(a3), "r"(b0), "r"(b1));
}

// ---------------------------------------------------------------------------
// Pre-pass 1: elementwise split of x
// ---------------------------------------------------------------------------
__global__ __launch_bounds__(256) void convert_split_kernel(
    const float* __restrict__ src, bf16* __restrict__ hi, bf16* __restrict__ lo, int n4)
{
    int i = blockIdx.x * 256 + threadIdx.x;
    if (i >= n4) return;
    float4 v = ((const float4*)src)[i];
    bf16 h0,h1,h2,h3,l0,l1,l2,l3;
    split_bf16(v.x,h0,l0); split_bf16(v.y,h1,l1);
    split_bf16(v.z,h2,l2); split_bf16(v.w,h3,l3);
    __nv_bfloat162* ph = (__nv_bfloat162*)hi;
    __nv_bfloat162* pl = (__nv_bfloat162*)lo;
    ph[2*i]   = __nv_bfloat162(h0,h1);
    ph[2*i+1] = __nv_bfloat162(h2,h3);
    pl[2*i]   = __nv_bfloat162(l0,l1);
    pl[2*i+1] = __nv_bfloat162(l2,l3);
}

// ---------------------------------------------------------------------------
// Pre-pass 2: transpose + split weights  src[K][N] -> dst[N][K] bf16 hi/lo
// ---------------------------------------------------------------------------
__global__ __launch_bounds__(256) void transpose_split_kernel(
    const float* __restrict__ src, bf16* __restrict__ dh, bf16* __restrict__ dl, int Kdim, int Ndim)
{
    __shared__ float t[32][33];
    int tx = threadIdx.x, ty = threadIdx.y;
    int n0 = blockIdx.x * 32, k0 = blockIdx.y * 32;
#pragma unroll
    for (int i = 0; i < 4; ++i)
        t[ty + 8*i][tx] = src[(size_t)(k0 + ty + 8*i) * Ndim + n0 + tx];
    __syncthreads();
#pragma unroll
    for (int i = 0; i < 4; ++i) {
        float v = t[tx][ty + 8*i];
        bf16 h, l; split_bf16(v, h, l);
        size_t o = (size_t)(n0 + ty + 8*i) * Kdim + k0 + tx;
        dh[o] = h; dl[o] = l;
    }
}

// ---------------------------------------------------------------------------
// Zero scratch for attention atomic merge
// ---------------------------------------------------------------------------
__global__ __launch_bounds__(256) void zero_scratch_kernel()
{
    int i = blockIdx.x * 256 + threadIdx.x;
    float4 z = make_float4(0.f, 0.f, 0.f, 0.f);
    if (i < MTOT*DD/4)     ((float4*)g_num)[i] = z;
    if (i < BB*HH*TT/4)    ((float4*)g_den)[i] = z;
}

// ---------------------------------------------------------------------------
// Worklist builder: one thread per (b,h).  Entries: bh|r|qt|kc|p|nch packed.
// Key-chunk size 512 subsequence positions -> max 2560 entries total.
// ---------------------------------------------------------------------------
__global__ void worklist_kernel(const void* __restrict__ periods_raw)
{
    int tid = threadIdx.x;   // 32 threads
    if (tid == 0) g_nwork = 0;
    __syncthreads();

    const int* pw = (const int*)periods_raw;
    bool is64 = true;
#pragma unroll
    for (int k2 = 1; k2 < 32; k2 += 2) is64 = is64 && (pw[k2] == 0);
    int p = is64 ? pw[2*tid] : pw[tid];
    if (p < 1) p = 1;

    // count entries
    int cnt = 0;
    for (int r = 0; r < p; ++r) {
        int L = (TT - r + p - 1) / p;
        int qts = (L + 63) >> 6;
        for (int qt = 0; qt < qts; ++qt) {
            int m_max = min(qt*64 + 63, L - 1);
            cnt += (m_max >> 9) + 1;
        }
    }
    int base = atomicAdd(&g_nwork, cnt);
    for (int r = 0; r < p; ++r) {
        int L = (TT - r + p - 1) / p;
        int qts = (L + 63) >> 6;
        for (int qt = 0; qt < qts; ++qt) {
            int m_max = min(qt*64 + 63, L - 1);
            int nch = (m_max >> 9) + 1;
            for (int kc = 0; kc < nch; ++kc)
                g_work[base++] = (uint32_t)tid | ((uint32_t)r << 5) |
                                 ((uint32_t)qt << 9) | ((uint32_t)kc << 14) |
                                 ((uint32_t)p << 17) | ((uint32_t)nch << 21);
        }
    }
}

// ---------------------------------------------------------------------------
// GEMM core: 128x128 C-tile, bf16x3 split, BK=32, 2-stage cp.async pipeline.
// Dynamic smem: 2 stages x {Ah,Al,Bh,Bl}[128][40] bf16 = 81920 B.
// ---------------------------------------------------------------------------
#define ST_STRIDE 20480
#define OFF_AH 0
#define OFF_AL 5120
#define OFF_BH 10240
#define OFF_BL 15360
#define GEMM_SMEM_BYTES (2*ST_STRIDE*2)

__device__ __forceinline__ void gemm_issue_stage(
    bf16* st, const bf16* Ahi, const bf16* Alo,
    const bf16* BThi, const bf16* BTlo, int m0, int n0, int k0, int tid)
{
#pragma unroll
    for (int it = 0; it < 2; ++it) {
        int ch  = tid + it * 256;          // 0..511
        int row = ch >> 2;
        int c8  = (ch & 3) * 8;
        size_t ao = (size_t)(m0 + row) * KK + k0 + c8;
        size_t bo = (size_t)(n0 + row) * KK + k0 + c8;
        int so = row * 40 + c8;
        cp16(st + OFF_AH + so, Ahi  + ao);
        cp16(st + OFF_AL + so, Alo  + ao);
        cp16(st + OFF_BH + so, BThi + bo);
        cp16(st + OFF_BL + so, BTlo + bo);
    }
}

__device__ __forceinline__ void gemm_core(
    const bf16* __restrict__ Ahi, const bf16* __restrict__ Alo,
    const bf16* __restrict__ BThi, const bf16* __restrict__ BTlo,
    int m0, int n0, bf16* sm, float c[4][4][4])
{
    const int tid  = threadIdx.x;
    const int lane = tid & 31;
    const int warp = tid >> 5;
    const int wm = warp >> 2;
    const int wn = warp & 3;
    const int ro = lane >> 2;
    const int co = (lane & 3) * 2;

#pragma unroll
    for (int i = 0; i < 4; ++i)
#pragma unroll
        for (int j = 0; j < 4; ++j)
#pragma unroll
            for (int q = 0; q < 4; ++q) c[i][j][q] = 0.f;

    gemm_issue_stage(sm, Ahi, Alo, BThi, BTlo, m0, n0, 0, tid);
    cp_commit();

    int s = 0;
    for (int k0 = 0; k0 < KK; k0 += 32, s ^= 1) {
        cp_wait0();
        __syncthreads();
        if (k0 + 32 < KK) {
            gemm_issue_stage(sm + (s^1)*ST_STRIDE, Ahi, Alo, BThi, BTlo, m0, n0, k0 + 32, tid);
            cp_commit();
        }
        bf16* st = sm + s * ST_STRIDE;
#pragma unroll
        for (int ks = 0; ks < 2; ++ks) {
            const int kw = ks * 16 + co;
            uint32_t bh[4][2], bl[4][2];
#pragma unroll
            for (int ni = 0; ni < 4; ++ni) {
                int nr = wn * 32 + ni * 8 + ro;
                bh[ni][0] = *(const uint32_t*)&st[OFF_BH + nr*40 + kw];
                bh[ni][1] = *(const uint32_t*)&st[OFF_BH + nr*40 + kw + 8];
                bl[ni][0] = *(const uint32_t*)&st[OFF_BL + nr*40 + kw];
                bl[ni][1] = *(const uint32_t*)&st[OFF_BL + nr*40 + kw + 8];
            }
#pragma unroll
            for (int mi = 0; mi < 4; ++mi) {
                int mr = wm * 64 + mi * 16 + ro;
                uint32_t ah0 = *(const uint32_t*)&st[OFF_AH + mr*40 + kw];
                uint32_t ah1 = *(const uint32_t*)&st[OFF_AH + (mr+8)*40 + kw];
                uint32_t ah2 = *(const uint32_t*)&st[OFF_AH + mr*40 + kw + 8];
                uint32_t ah3 = *(const uint32_t*)&st[OFF_AH + (mr+8)*40 + kw + 8];
                uint32_t al0 = *(const uint32_t*)&st[OFF_AL + mr*40 + kw];
                uint32_t al1 = *(const uint32_t*)&st[OFF_AL + (mr+8)*40 + kw];
                uint32_t al2 = *(const uint32_t*)&st[OFF_AL + mr*40 + kw + 8];
                uint32_t al3 = *(const uint32_t*)&st[OFF_AL + (mr+8)*40 + kw + 8];
#pragma unroll
                for (int ni = 0; ni < 4; ++ni) {
                    mma16816(c[mi][ni], ah0, ah1, ah2, ah3, bh[ni][0], bh[ni][1]);
                    mma16816(c[mi][ni], ah0, ah1, ah2, ah3, bl[ni][0], bl[ni][1]);
                    mma16816(c[mi][ni], al0, al1, al2, al3, bh[ni][0], bh[ni][1]);
                }
            }
        }
        __syncthreads();
    }
}

// ---------------------------------------------------------------------------
// Kernel 1: QKV GEMM with scatter epilogue into g_q/g_k/g_v
// ---------------------------------------------------------------------------
__global__ __launch_bounds__(256, 2) void qkv_gemm_bf16(const float* __restrict__ bias)
{
    extern __shared__ __align__(16) bf16 dyns[];
    float c[4][4][4];
    const int m0 = blockIdx.y * 128;
    const int n0 = blockIdx.x * 128;
    gemm_core(g_xhi, g_xlo, g_wqT_hi, g_wqT_lo, m0, n0, dyns, c);

    const int tid  = threadIdx.x;
    const int lane = tid & 31;
    const int warp = tid >> 5;
    const int wm = warp >> 2, wn = warp & 3;
    const int ro = lane >> 2, co = (lane & 3) * 2;

    const int which = n0 >> 10;
    float* dst = (which == 0) ? g_q : ((which == 1) ? g_k : g_v);

#pragma unroll
    for (int mi = 0; mi < 4; ++mi) {
#pragma unroll
        for (int ni = 0; ni < 4; ++ni) {
            int n_a = n0 + wn * 32 + ni * 8 + co;
            int nn = n_a & (DD - 1);
            int hh = nn >> 6;
            int hd = nn & (HD - 1);
            float b0v = bias[n_a], b1v = bias[n_a + 1];
#pragma unroll
            for (int half = 0; half < 2; ++half) {
                int m = m0 + wm * 64 + mi * 16 + ro + half * 8;
                int b_ = m >> 11;
                int t_ = m & (TT - 1);
                float2 v;
                v.x = c[mi][ni][half * 2]     + b0v;
                v.y = c[mi][ni][half * 2 + 1] + b1v;
                *(float2*)(dst + (((size_t)(b_ * HH + hh) * TT + t_) << 6) + hd) = v;
            }
        }
    }
}

// ---------------------------------------------------------------------------
// Kernel 3: output projection -> d_out fp32
// ---------------------------------------------------------------------------
__global__ __launch_bounds__(256, 2) void out_gemm_bf16(
    const float* __restrict__ bias, float* __restrict__ Y)
{
    extern __shared__ __align__(16) bf16 dyns[];
    float c[4][4][4];
    const int m0 = blockIdx.y * 128;
    const int n0 = blockIdx.x * 128;
    gemm_core(g_atthi, g_attlo, g_woT_hi, g_woT_lo, m0, n0, dyns, c);

    const int tid  = threadIdx.x;
    const int lane = tid & 31;
    const int warp = tid >> 5;
    const int wm = warp >> 2, wn = warp & 3;
    const int ro = lane >> 2, co = (lane & 3) * 2;

#pragma unroll
    for (int mi = 0; mi < 4; ++mi) {
#pragma unroll
        for (int ni = 0; ni < 4; ++ni) {
            int n_a = n0 + wn * 32 + ni * 8 + co;
            float b0v = bias[n_a], b1v = bias[n_a + 1];
#pragma unroll
            for (int half = 0; half < 2; ++half) {
                int m = m0 + wm * 64 + mi * 16 + ro + half * 8;
                float2 v;
                v.x = c[mi][ni][half * 2]     + b0v;
                v.y = c[mi][ni][half * 2 + 1] + b1v;
                *(float2*)(Y + (size_t)m * DD + n_a) = v;
            }
        }
    }
}

// ---------------------------------------------------------------------------
// Kernel 2: periodic-sparse attention, worklist-driven, no max-subtraction
// (scores bounded |s|<~6 by construction -> exp safe, sums associative).
// Block = one work item: 64 queries x <=512 keys. 128 thr = 2/query.
// Single-chunk items write final (bf16 split); multi-chunk atomicAdd partials.
// ---------------------------------------------------------------------------
__global__ __launch_bounds__(128, 4) void attn_kernel()
{
    if ((int)blockIdx.x >= g_nwork) return;
    const uint32_t e = g_work[blockIdx.x];
    const int bh  = e & 31;
    const int r   = (e >> 5)  & 15;
    const int qt  = (e >> 9)  & 31;
    const int kc  = (e >> 14) & 7;
    const int p   = (e >> 17) & 15;
    const int nch = (e >> 21) & 7;

    const int b_ = bh >> 4;
    const int h  = bh & 15;
    const int L  = (TT - r + p - 1) / p;
    const int m0 = qt * 64;
    const int m_max = min(m0 + 63, L - 1);
    const int n_lo = kc << 9;
    const int n_hi = min(n_lo + 511, m_max);

    __shared__ __align__(16) float Ks[32][64];
    __shared__ __align__(16) float Vs[32][64];

    const int tid  = threadIdx.x;
    const int ql   = tid >> 1;
    const int half = tid & 1;
    const int m    = m0 + ql;
    const bool active = (m < L);
    const int i_glob = r + p * (active ? m : 0);

    const float* qptr = g_q + ((size_t)bh * TT + i_glob) * HD + half * 32;
    float qreg[32];
#pragma unroll
    for (int d = 0; d < 32; d += 4) {
        float4 t = *(const float4*)(qptr + d);
        qreg[d]     = t.x * 0.125f;
        qreg[d + 1] = t.y * 0.125f;
        qreg[d + 2] = t.z * 0.125f;
        qreg[d + 3] = t.w * 0.125f;
    }

    float l = 0.f;
    float acc[32];
#pragma unroll
    for (int d = 0; d < 32; ++d) acc[d] = 0.f;

    const float* kbase = g_k + (size_t)bh * TT * HD;
    const float* vbase = g_v + (size_t)bh * TT * HD;

    const int row = tid >> 2, q4 = tid & 3;

    for (int tb = n_lo; tb <= n_hi; tb += 32) {
        __syncthreads();
        {
            int n = tb + row;
            if (n <= n_hi) {
                int jg = r + p * n;
                const float4* ks = (const float4*)(kbase + (size_t)jg * HD + q4 * 16);
                const float4* vs = (const float4*)(vbase + (size_t)jg * HD + q4 * 16);
                float4* kd = (float4*)&Ks[row][q4 * 16];
                float4* vd = (float4*)&Vs[row][q4 * 16];
#pragma unroll
                for (int q = 0; q < 4; ++q) { kd[q] = ks[q]; vd[q] = vs[q]; }
            }
        }
        __syncthreads();

        const bool full = (tb + 31 <= n_hi) && (tb + 31 <= m0);
        if (full) {
#pragma unroll 4
            for (int j = 0; j < 32; ++j) {
                float sp = 0.f;
                const float4* kr = (const float4*)&Ks[j][half * 32];
#pragma unroll
                for (int d4 = 0; d4 < 8; ++d4) {
                    float4 kk = kr[d4];
                    sp += qreg[d4*4]   * kk.x + qreg[d4*4+1] * kk.y
                        + qreg[d4*4+2] * kk.z + qreg[d4*4+3] * kk.w;
                }
                float s = sp + __shfl_xor_sync(0xffffffffu, sp, 1);
                float pe = __expf(s);
                l += pe;
                const float4* vr = (const float4*)&Vs[j][half * 32];
#pragma unroll
                for (int d4 = 0; d4 < 8; ++d4) {
                    float4 vv = vr[d4];
                    acc[d4*4]   += pe * vv.x;
                    acc[d4*4+1] += pe * vv.y;
                    acc[d4*4+2] += pe * vv.z;
                    acc[d4*4+3] += pe * vv.w;
                }
            }
        } else {
            const int cnt = min(32, n_hi - tb + 1);
            for (int j = 0; j < cnt; ++j) {
                float sp = 0.f;
                const float4* kr = (const float4*)&Ks[j][half * 32];
#pragma unroll
                for (int d4 = 0; d4 < 8; ++d4) {
                    float4 kk = kr[d4];
                    sp += qreg[d4*4]   * kk.x + qreg[d4*4+1] * kk.y
                        + qreg[d4*4+2] * kk.z + qreg[d4*4+3] * kk.w;
                }
                float s = sp + __shfl_xor_sync(0xffffffffu, sp, 1);
                float pe = (tb + j <= m) ? __expf(s) : 0.f;
                l += pe;
                const float4* vr = (const float4*)&Vs[j][half * 32];
#pragma unroll
                for (int d4 = 0; d4 < 8; ++d4) {
                    float4 vv = vr[d4];
                    acc[d4*4]   += pe * vv.x;
                    acc[d4*4+1] += pe * vv.y;
                    acc[d4*4+2] += pe * vv.z;
                    acc[d4*4+3] += pe * vv.w;
                }
            }
        }
    }

    if (!active) return;

    if (nch == 1) {
        float inv = 1.f / l;    // diagonal key always present -> l > 0
        size_t ob = ((size_t)(b_ * TT + i_glob)) * DD + h * HD + half * 32;
        __nv_bfloat162* oh = (__nv_bfloat162*)(g_atthi + ob);
        __nv_bfloat162* ol = (__nv_bfloat162*)(g_attlo + ob);
#pragma unroll
        for (int d = 0; d < 32; d += 2) {
            float v0 = acc[d] * inv;
            float v1 = acc[d+1] * inv;
            bf16 h0, l0b, h1, l1b;
            split_bf16(v0, h0, l0b);
            split_bf16(v1, h1, l1b);
            oh[d >> 1] = __nv_bfloat162(h0, h1);
            ol[d >> 1] = __nv_bfloat162(l0b, l1b);
        }
    } else {
        if (half == 0) atomicAdd(&g_den[bh * TT + i_glob], l);
        float* np = g_num + ((size_t)(b_ * TT + i_glob)) * DD + h * HD + half * 32;
#pragma unroll
        for (int d = 0; d < 32; ++d) atomicAdd(np + d, acc[d]);
    }
}

// ---------------------------------------------------------------------------
// Finalize: normalize multi-chunk queries (den>0) and write bf16 split
// ---------------------------------------------------------------------------
__global__ __launch_bounds__(256) void finalize_kernel()
{
    int g = blockIdx.x * 256 + threadIdx.x;     // one float4 of num
    if (g >= MTOT*DD/4) return;
    int q   = g >> 4;              // query id: bh*2048 + t
    int dg  = (g & 15) * 4;        // dim group within head (0..60)
    float den = g_den[q];
    if (den == 0.f) return;
    int bh = q >> 11, t = q & (TT - 1);
    int b_ = bh >> 4, h = bh & 15;
    size_t base = ((size_t)(b_ * TT + t)) * DD + h * HD + dg;
    float4 nm = *(const float4*)(g_num + base);
    float inv = 1.f / den;
    bf16 h0,h1,h2,h3,l0,l1,l2,l3;
    split_bf16(nm.x * inv, h0, l0);
    split_bf16(nm.y * inv, h1, l1);
    split_bf16(nm.z * inv, h2, l2);
    split_bf16(nm.w * inv, h3, l3);
    __nv_bfloat162* oh = (__nv_bfloat162*)(g_atthi + base);
    __nv_bfloat162* ol = (__nv_bfloat162*)(g_attlo + base);
    oh[0] = __nv_bfloat162(h0, h1);
    oh[1] = __nv_bfloat162(h2, h3);
    ol[0] = __nv_bfloat162(l0, l1);
    ol[1] = __nv_bfloat162(l2, l3);
}

// ---------------------------------------------------------------------------
extern "C" void kernel_launch(void* const* d_in, const int* in_sizes, int n_in,
                              void* d_out, int out_size)
{
    const float* x      = (const float*)d_in[0];
    const void*  per    = d_in[1];                  // int32 or int64, detected on device
    const float* w_qkv  = (const float*)d_in[2];
    const float* b_qkv  = (const float*)d_in[3];
    const float* w_out  = (const float*)d_in[4];
    const float* b_out  = (const float*)d_in[5];
    float* out = (float*)d_out;

    bf16 *xhi, *xlo, *wqh, *wql, *woh, *wol;
    cudaGetSymbolAddress((void**)&xhi, g_xhi);
    cudaGetSymbolAddress((void**)&xlo, g_xlo);
    cudaGetSymbolAddress((void**)&wqh, g_wqT_hi);
    cudaGetSymbolAddress((void**)&wql, g_wqT_lo);
    cudaGetSymbolAddress((void**)&woh, g_woT_hi);
    cudaGetSymbolAddress((void**)&wol, g_woT_lo);

    cudaFuncSetAttribute(qkv_gemm_bf16, cudaFuncAttributeMaxDynamicSharedMemorySize, GEMM_SMEM_BYTES);
    cudaFuncSetAttribute(out_gemm_bf16, cudaFuncAttributeMaxDynamicSharedMemorySize, GEMM_SMEM_BYTES);

    // Pre-passes
    convert_split_kernel<<<(MTOT*DD/4 + 255)/256, 256>>>(x, xhi, xlo, MTOT*DD/4);
    {
        dim3 b(32, 8);
        dim3 gq(N3/32, KK/32);
        transpose_split_kernel<<<gq, b>>>(w_qkv, wqh, wql, KK, N3);
        dim3 go(DD/32, KK/32);
        transpose_split_kernel<<<go, b>>>(w_out, woh, wol, KK, DD);
    }
    zero_scratch_kernel<<<(MTOT*DD/4 + 255)/256, 256>>>();
    worklist_kernel<<<1, 32>>>(per);

    dim3 g1(N3/128, MTOT/128);        // 24 x 32
    qkv_gemm_bf16<<<g1, 256, GEMM_SMEM_BYTES>>>(b_qkv);

    attn_kernel<<<2560, 128>>>();
    finalize_kernel<<<(MTOT*DD/4 + 255)/256, 256>>>();

    dim3 g3(DD/128, MTOT/128);        // 8 x 32
    out_gemm_bf16<<<g3, 256, GEMM_SMEM_BYTES>>>(b_out, out);
}

// round 11
// speedup vs baseline: 3.1002x; 1.5027x over previous
#include <cuda_runtime.h>
#include <cuda_bf16.h>
#include <math.h>
#include <stdint.h>

// Problem constants
#define BB 2
#define TT 2048
#define DD 1024
#define HH 16
#define HD 64
#define N3 3072
#define MTOT (BB*TT)          // 4096
#define KK 1024

typedef __nv_bfloat16 bf16;

// ---------------------------------------------------------------------------
// Device-global scratch (allocation-free contract)
// ---------------------------------------------------------------------------
__device__ bf16  g_xhi[MTOT*DD];        // x split hi/lo, row-major [m][k]
__device__ bf16  g_xlo[MTOT*DD];
__device__ bf16  g_wqT_hi[N3*KK];       // w_qkv^T split, [n][k]
__device__ bf16  g_wqT_lo[N3*KK];
__device__ bf16  g_woT_hi[DD*KK];       // w_out^T split, [n][k]
__device__ bf16  g_woT_lo[DD*KK];
__device__ bf16  g_qhi[BB*HH*TT*HD];    // (b,h,t,hd) bf16 split, q pre-scaled 1/8
__device__ bf16  g_qlo[BB*HH*TT*HD];
__device__ bf16  g_khi[BB*HH*TT*HD];
__device__ bf16  g_klo[BB*HH*TT*HD];
__device__ bf16  g_vhi[BB*HH*TT*HD];
__device__ bf16  g_vlo[BB*HH*TT*HD];
__device__ bf16  g_atthi[MTOT*DD];      // attention output split, [m][d]
__device__ bf16  g_attlo[MTOT*DD];
__device__ float g_num[MTOT*DD];        // multi-chunk partial numerator (b,t,d)
__device__ float g_den[BB*HH*TT];       // multi-chunk partial denominator [bh][t]
__device__ int      g_nwork;
__device__ uint32_t g_work[2600];

// ---------------------------------------------------------------------------
// helpers
// ---------------------------------------------------------------------------
__device__ __forceinline__ void split_bf16(float x, bf16& hi, bf16& lo) {
    hi = __float2bfloat16_rn(x);
    lo = __float2bfloat16_rn(x - __bfloat162float(hi));
}
__device__ __forceinline__ uint32_t pack_bf2(bf16 a, bf16 b) {
    __nv_bfloat162 t(a, b);
    return *(uint32_t*)&t;
}
__device__ __forceinline__ void cp16(void* smp, const void* g) {
    uint32_t s = (uint32_t)__cvta_generic_to_shared(smp);
    asm volatile("cp.async.cg.shared.global [%0], [%1], 16;\n" :: "r"(s), "l"(g));
}
__device__ __forceinline__ void cp_commit() { asm volatile("cp.async.commit_group;\n"); }
__device__ __forceinline__ void cp_wait0()  { asm volatile("cp.async.wait_group 0;\n"); }

__device__ __forceinline__ void mma16816(float* c,
    uint32_t a0, uint32_t a1, uint32_t a2, uint32_t a3, uint32_t b0, uint32_t b1)
{
    asm volatile(
        "mma.sync.aligned.m16n8k16.row.col.f32.bf16.bf16.f32 "
        "{%0,%1,%2,%3}, {%4,%5,%6,%7}, {%8,%9}, {%0,%1,%2,%3};\n"
        : "+f"(c[0]), "+f"(c[1]), "+f"(c[2]), "+f"(c[3])
        : "r"(a0), "r"(a1), "r"(a2), "r"(a3), "r"(b0), "r"(b1));
}

// ---------------------------------------------------------------------------
// Pre-pass 1: elementwise split of x
// ---------------------------------------------------------------------------
__global__ __launch_bounds__(256) void convert_split_kernel(
    const float* __restrict__ src, bf16* __restrict__ hi, bf16* __restrict__ lo, int n4)
{
    int i = blockIdx.x * 256 + threadIdx.x;
    if (i >= n4) return;
    float4 v = ((const float4*)src)[i];
    bf16 h0,h1,h2,h3,l0,l1,l2,l3;
    split_bf16(v.x,h0,l0); split_bf16(v.y,h1,l1);
    split_bf16(v.z,h2,l2); split_bf16(v.w,h3,l3);
    __nv_bfloat162* ph = (__nv_bfloat162*)hi;
    __nv_bfloat162* pl = (__nv_bfloat162*)lo;
    ph[2*i]   = __nv_bfloat162(h0,h1);
    ph[2*i+1] = __nv_bfloat162(h2,h3);
    pl[2*i]   = __nv_bfloat162(l0,l1);
    pl[2*i+1] = __nv_bfloat162(l2,l3);
}

// ---------------------------------------------------------------------------
// Pre-pass 2: transpose + split weights  src[K][N] -> dst[N][K] bf16 hi/lo
// ---------------------------------------------------------------------------
__global__ __launch_bounds__(256) void transpose_split_kernel(
    const float* __restrict__ src, bf16* __restrict__ dh, bf16* __restrict__ dl, int Kdim, int Ndim)
{
    __shared__ float t[32][33];
    int tx = threadIdx.x, ty = threadIdx.y;
    int n0 = blockIdx.x * 32, k0 = blockIdx.y * 32;
#pragma unroll
    for (int i = 0; i < 4; ++i)
        t[ty + 8*i][tx] = src[(size_t)(k0 + ty + 8*i) * Ndim + n0 + tx];
    __syncthreads();
#pragma unroll
    for (int i = 0; i < 4; ++i) {
        float v = t[tx][ty + 8*i];
        bf16 h, l; split_bf16(v, h, l);
        size_t o = (size_t)(n0 + ty + 8*i) * Kdim + k0 + tx;
        dh[o] = h; dl[o] = l;
    }
}

// ---------------------------------------------------------------------------
// Zero scratch for attention atomic merge
// ---------------------------------------------------------------------------
__global__ __launch_bounds__(256) void zero_scratch_kernel()
{
    int i = blockIdx.x * 256 + threadIdx.x;
    float4 z = make_float4(0.f, 0.f, 0.f, 0.f);
    if (i < MTOT*DD/4)     ((float4*)g_num)[i] = z;
    if (i < BB*HH*TT/4)    ((float4*)g_den)[i] = z;
}

// ---------------------------------------------------------------------------
// Worklist builder: one thread per (b,h).  Entries: bh|r|qt|kc|p|nch packed.
// ---------------------------------------------------------------------------
__global__ void worklist_kernel(const void* __restrict__ periods_raw)
{
    int tid = threadIdx.x;   // 32 threads
    if (tid == 0) g_nwork = 0;
    __syncthreads();

    const int* pw = (const int*)periods_raw;
    bool is64 = true;
#pragma unroll
    for (int k2 = 1; k2 < 32; k2 += 2) is64 = is64 && (pw[k2] == 0);
    int p = is64 ? pw[2*tid] : pw[tid];
    if (p < 1) p = 1;

    int cnt = 0;
    for (int r = 0; r < p; ++r) {
        int L = (TT - r + p - 1) / p;
        int qts = (L + 63) >> 6;
        for (int qt = 0; qt < qts; ++qt) {
            int m_max = min(qt*64 + 63, L - 1);
            cnt += (m_max >> 9) + 1;
        }
    }
    int base = atomicAdd(&g_nwork, cnt);
    for (int r = 0; r < p; ++r) {
        int L = (TT - r + p - 1) / p;
        int qts = (L + 63) >> 6;
        for (int qt = 0; qt < qts; ++qt) {
            int m_max = min(qt*64 + 63, L - 1);
            int nch = (m_max >> 9) + 1;
            for (int kc = 0; kc < nch; ++kc)
                g_work[base++] = (uint32_t)tid | ((uint32_t)r << 5) |
                                 ((uint32_t)qt << 9) | ((uint32_t)kc << 14) |
                                 ((uint32_t)p << 17) | ((uint32_t)nch << 21);
        }
    }
}

// ---------------------------------------------------------------------------
// GEMM core: 128x128 C-tile, bf16x3 split, BK=32, 2-stage cp.async pipeline.
// ---------------------------------------------------------------------------
#define ST_STRIDE 20480
#define OFF_AH 0
#define OFF_AL 5120
#define OFF_BH 10240
#define OFF_BL 15360
#define GEMM_SMEM_BYTES (2*ST_STRIDE*2)

__device__ __forceinline__ void gemm_issue_stage(
    bf16* st, const bf16* Ahi, const bf16* Alo,
    const bf16* BThi, const bf16* BTlo, int m0, int n0, int k0, int tid)
{
#pragma unroll
    for (int it = 0; it < 2; ++it) {
        int ch  = tid + it * 256;          // 0..511
        int row = ch >> 2;
        int c8  = (ch & 3) * 8;
        size_t ao = (size_t)(m0 + row) * KK + k0 + c8;
        size_t bo = (size_t)(n0 + row) * KK + k0 + c8;
        int so = row * 40 + c8;
        cp16(st + OFF_AH + so, Ahi  + ao);
        cp16(st + OFF_AL + so, Alo  + ao);
        cp16(st + OFF_BH + so, BThi + bo);
        cp16(st + OFF_BL + so, BTlo + bo);
    }
}

__device__ __forceinline__ void gemm_core(
    const bf16* __restrict__ Ahi, const bf16* __restrict__ Alo,
    const bf16* __restrict__ BThi, const bf16* __restrict__ BTlo,
    int m0, int n0, bf16* sm, float c[4][4][4])
{
    const int tid  = threadIdx.x;
    const int lane = tid & 31;
    const int warp = tid >> 5;
    const int wm = warp >> 2;
    const int wn = warp & 3;
    const int ro = lane >> 2;
    const int co = (lane & 3) * 2;

#pragma unroll
    for (int i = 0; i < 4; ++i)
#pragma unroll
        for (int j = 0; j < 4; ++j)
#pragma unroll
            for (int q = 0; q < 4; ++q) c[i][j][q] = 0.f;

    gemm_issue_stage(sm, Ahi, Alo, BThi, BTlo, m0, n0, 0, tid);
    cp_commit();

    int s = 0;
    for (int k0 = 0; k0 < KK; k0 += 32, s ^= 1) {
        cp_wait0();
        __syncthreads();
        if (k0 + 32 < KK) {
            gemm_issue_stage(sm + (s^1)*ST_STRIDE, Ahi, Alo, BThi, BTlo, m0, n0, k0 + 32, tid);
            cp_commit();
        }
        bf16* st = sm + s * ST_STRIDE;
#pragma unroll
        for (int ks = 0; ks < 2; ++ks) {
            const int kw = ks * 16 + co;
            uint32_t bh[4][2], bl[4][2];
#pragma unroll
            for (int ni = 0; ni < 4; ++ni) {
                int nr = wn * 32 + ni * 8 + ro;
                bh[ni][0] = *(const uint32_t*)&st[OFF_BH + nr*40 + kw];
                bh[ni][1] = *(const uint32_t*)&st[OFF_BH + nr*40 + kw + 8];
                bl[ni][0] = *(const uint32_t*)&st[OFF_BL + nr*40 + kw];
                bl[ni][1] = *(const uint32_t*)&st[OFF_BL + nr*40 + kw + 8];
            }
#pragma unroll
            for (int mi = 0; mi < 4; ++mi) {
                int mr = wm * 64 + mi * 16 + ro;
                uint32_t ah0 = *(const uint32_t*)&st[OFF_AH + mr*40 + kw];
                uint32_t ah1 = *(const uint32_t*)&st[OFF_AH + (mr+8)*40 + kw];
                uint32_t ah2 = *(const uint32_t*)&st[OFF_AH + mr*40 + kw + 8];
                uint32_t ah3 = *(const uint32_t*)&st[OFF_AH + (mr+8)*40 + kw + 8];
                uint32_t al0 = *(const uint32_t*)&st[OFF_AL + mr*40 + kw];
                uint32_t al1 = *(const uint32_t*)&st[OFF_AL + (mr+8)*40 + kw];
                uint32_t al2 = *(const uint32_t*)&st[OFF_AL + mr*40 + kw + 8];
                uint32_t al3 = *(const uint32_t*)&st[OFF_AL + (mr+8)*40 + kw + 8];
#pragma unroll
                for (int ni = 0; ni < 4; ++ni) {
                    mma16816(c[mi][ni], ah0, ah1, ah2, ah3, bh[ni][0], bh[ni][1]);
                    mma16816(c[mi][ni], ah0, ah1, ah2, ah3, bl[ni][0], bl[ni][1]);
                    mma16816(c[mi][ni], al0, al1, al2, al3, bh[ni][0], bh[ni][1]);
                }
            }
        }
        __syncthreads();
    }
}

// ---------------------------------------------------------------------------
// Kernel 1: QKV GEMM; epilogue emits bf16 hi/lo q/k/v (q pre-scaled 1/8)
// ---------------------------------------------------------------------------
__global__ __launch_bounds__(256, 2) void qkv_gemm_bf16(const float* __restrict__ bias)
{
    extern __shared__ __align__(16) bf16 dyns[];
    float c[4][4][4];
    const int m0 = blockIdx.y * 128;
    const int n0 = blockIdx.x * 128;
    gemm_core(g_xhi, g_xlo, g_wqT_hi, g_wqT_lo, m0, n0, dyns, c);

    const int tid  = threadIdx.x;
    const int lane = tid & 31;
    const int warp = tid >> 5;
    const int wm = warp >> 2, wn = warp & 3;
    const int ro = lane >> 2, co = (lane & 3) * 2;

    const int which = n0 >> 10;
    bf16* dhi = (which == 0) ? g_qhi : ((which == 1) ? g_khi : g_vhi);
    bf16* dlo = (which == 0) ? g_qlo : ((which == 1) ? g_klo : g_vlo);
    const float scl = (which == 0) ? 0.125f : 1.0f;

#pragma unroll
    for (int mi = 0; mi < 4; ++mi) {
#pragma unroll
        for (int ni = 0; ni < 4; ++ni) {
            int n_a = n0 + wn * 32 + ni * 8 + co;
            int nn = n_a & (DD - 1);
            int hh = nn >> 6;
            int hd = nn & (HD - 1);
            float b0v = bias[n_a], b1v = bias[n_a + 1];
#pragma unroll
            for (int half = 0; half < 2; ++half) {
                int m = m0 + wm * 64 + mi * 16 + ro + half * 8;
                int b_ = m >> 11;
                int t_ = m & (TT - 1);
                float v0 = (c[mi][ni][half*2]     + b0v) * scl;
                float v1 = (c[mi][ni][half*2 + 1] + b1v) * scl;
                bf16 h0,l0,h1,l1;
                split_bf16(v0, h0, l0);
                split_bf16(v1, h1, l1);
                size_t off = (((size_t)(b_ * HH + hh) * TT + t_) << 6) + hd;
                *(__nv_bfloat162*)(dhi + off) = __nv_bfloat162(h0, h1);
                *(__nv_bfloat162*)(dlo + off) = __nv_bfloat162(l0, l1);
            }
        }
    }
}

// ---------------------------------------------------------------------------
// Kernel 3: output projection -> d_out fp32
// ---------------------------------------------------------------------------
__global__ __launch_bounds__(256, 2) void out_gemm_bf16(
    const float* __restrict__ bias, float* __restrict__ Y)
{
    extern __shared__ __align__(16) bf16 dyns[];
    float c[4][4][4];
    const int m0 = blockIdx.y * 128;
    const int n0 = blockIdx.x * 128;
    gemm_core(g_atthi, g_attlo, g_woT_hi, g_woT_lo, m0, n0, dyns, c);

    const int tid  = threadIdx.x;
    const int lane = tid & 31;
    const int warp = tid >> 5;
    const int wm = warp >> 2, wn = warp & 3;
    const int ro = lane >> 2, co = (lane & 3) * 2;

#pragma unroll
    for (int mi = 0; mi < 4; ++mi) {
#pragma unroll
        for (int ni = 0; ni < 4; ++ni) {
            int n_a = n0 + wn * 32 + ni * 8 + co;
            float b0v = bias[n_a], b1v = bias[n_a + 1];
#pragma unroll
            for (int half = 0; half < 2; ++half) {
                int m = m0 + wm * 64 + mi * 16 + ro + half * 8;
                float2 v;
                v.x = c[mi][ni][half * 2]     + b0v;
                v.y = c[mi][ni][half * 2 + 1] + b1v;
                *(float2*)(Y + (size_t)m * DD + n_a) = v;
            }
        }
    }
}

// ---------------------------------------------------------------------------
// Kernel 2: periodic-sparse attention on TENSOR CORES (bf16x3 split).
// Work item: 64 queries x <=512 keys. 128 threads = 4 warps, warp = 16 queries.
// Per 32-key tile: S = Q.K^T via mma (3-term), mask+exp in-register,
// P repacked to A-fragments (FA-2 layout identity), O += P.V via mma (3-term).
// No max-subtraction (scores bounded). Single-chunk -> direct bf16 split
// output; multi-chunk -> fp32 atomic partials merged by finalize_kernel.
// ---------------------------------------------------------------------------
__global__ __launch_bounds__(128) void attn_kernel()
{
    if ((int)blockIdx.x >= g_nwork) return;
    const uint32_t e = g_work[blockIdx.x];
    const int bh  = e & 31;
    const int r   = (e >> 5)  & 15;
    const int qt  = (e >> 9)  & 31;
    const int kc  = (e >> 14) & 7;
    const int p   = (e >> 17) & 15;
    const int nch = (e >> 21) & 7;

    const int b_ = bh >> 4;
    const int h  = bh & 15;
    const int L  = (TT - r + p - 1) / p;
    const int m0 = qt * 64;
    const int m_max = min(m0 + 63, L - 1);
    const int n_lo = kc << 9;
    const int n_hi = min(n_lo + 511, m_max);

    __shared__ __align__(16) bf16 Qh[64][72], Ql[64][72];
    __shared__ __align__(16) bf16 Kh[32][72], Kl[32][72];
    __shared__ __align__(16) bf16 VTh[64][40], VTl[64][40];

    const int tid  = threadIdx.x;
    const int warp = tid >> 5;
    const int lane = tid & 31;
    const int ro = lane >> 2;
    const int co = (lane & 3) * 2;

    const size_t hb = (size_t)bh * TT;

    // ---- stage Q tile (clamped rows for padded queries; masked later) ----
    {
        int row = tid >> 1, hf = tid & 1;
        int mq = min(m0 + row, m_max);
        size_t off = (hb + (size_t)(r + p * mq)) * HD + hf * 32;
        const uint4* sh = (const uint4*)(g_qhi + off);
        const uint4* sl = (const uint4*)(g_qlo + off);
        uint4* dh_ = (uint4*)&Qh[row][hf * 32];
        uint4* dl_ = (uint4*)&Ql[row][hf * 32];
#pragma unroll
        for (int q = 0; q < 4; ++q) { dh_[q] = sh[q]; dl_[q] = sl[q]; }
    }
    __syncthreads();

    // ---- hoist Q fragments (A-frags, 4 k-steps covering 64 dims) ----
    uint32_t qh[4][4], ql[4][4];
    {
        const int mr = warp * 16 + ro;
#pragma unroll
        for (int ks = 0; ks < 4; ++ks) {
            int kw = ks * 16 + co;
            qh[ks][0] = *(const uint32_t*)&Qh[mr][kw];
            qh[ks][1] = *(const uint32_t*)&Qh[mr + 8][kw];
            qh[ks][2] = *(const uint32_t*)&Qh[mr][kw + 8];
            qh[ks][3] = *(const uint32_t*)&Qh[mr + 8][kw + 8];
            ql[ks][0] = *(const uint32_t*)&Ql[mr][kw];
            ql[ks][1] = *(const uint32_t*)&Ql[mr + 8][kw];
            ql[ks][2] = *(const uint32_t*)&Ql[mr][kw + 8];
            ql[ks][3] = *(const uint32_t*)&Ql[mr + 8][kw + 8];
        }
    }

    float o[8][4];
#pragma unroll
    for (int nd = 0; nd < 8; ++nd)
#pragma unroll
        for (int q = 0; q < 4; ++q) o[nd][q] = 0.f;
    float l0 = 0.f, l1 = 0.f;
    const int mq0 = m0 + warp * 16 + ro;
    const int mq1 = mq0 + 8;

    for (int tb = n_lo; tb <= n_hi; tb += 32) {
        __syncthreads();
        {   // stage K rows + transpose V into VT
            int jrow = tid >> 2, q4 = tid & 3;
            int n = tb + jrow;
            if (n <= n_hi) {
                size_t off = (hb + (size_t)(r + p * n)) * HD + q4 * 16;
                const uint4* sh = (const uint4*)(g_khi + off);
                const uint4* sl = (const uint4*)(g_klo + off);
                *(uint4*)&Kh[jrow][q4*16]     = sh[0];
                *(uint4*)&Kh[jrow][q4*16 + 8] = sh[1];
                *(uint4*)&Kl[jrow][q4*16]     = sl[0];
                *(uint4*)&Kl[jrow][q4*16 + 8] = sl[1];
                const uint32_t* vh = (const uint32_t*)(g_vhi + off);
                const uint32_t* vl = (const uint32_t*)(g_vlo + off);
#pragma unroll
                for (int dd = 0; dd < 8; ++dd) {
                    uint32_t wh = vh[dd], wl = vl[dd];
                    int d = q4 * 16 + dd * 2;
                    __nv_bfloat162 th = *(__nv_bfloat162*)&wh;
                    __nv_bfloat162 tl = *(__nv_bfloat162*)&wl;
                    VTh[d][jrow]     = th.x;
                    VTh[d + 1][jrow] = th.y;
                    VTl[d][jrow]     = tl.x;
                    VTl[d + 1][jrow] = tl.y;
                }
            } else {
                uint4 z = make_uint4(0,0,0,0);
                *(uint4*)&Kh[jrow][q4*16]     = z;
                *(uint4*)&Kh[jrow][q4*16 + 8] = z;
                *(uint4*)&Kl[jrow][q4*16]     = z;
                *(uint4*)&Kl[jrow][q4*16 + 8] = z;
                bf16 zb = __float2bfloat16_rn(0.f);
#pragma unroll
                for (int dd = 0; dd < 16; ++dd) {
                    int d = q4 * 16 + dd;
                    VTh[d][jrow] = zb;
                    VTl[d][jrow] = zb;
                }
            }
        }
        __syncthreads();

        // ---- S = Q.K^T (3-term split) ----
        float sc[4][4];
#pragma unroll
        for (int ni = 0; ni < 4; ++ni)
#pragma unroll
            for (int q = 0; q < 4; ++q) sc[ni][q] = 0.f;
#pragma unroll
        for (int ks = 0; ks < 4; ++ks) {
            int kw = ks * 16 + co;
#pragma unroll
            for (int ni = 0; ni < 4; ++ni) {
                int nr = ni * 8 + ro;
                uint32_t bh0 = *(const uint32_t*)&Kh[nr][kw];
                uint32_t bh1 = *(const uint32_t*)&Kh[nr][kw + 8];
                uint32_t bl0 = *(const uint32_t*)&Kl[nr][kw];
                uint32_t bl1 = *(const uint32_t*)&Kl[nr][kw + 8];
                mma16816(sc[ni], qh[ks][0], qh[ks][1], qh[ks][2], qh[ks][3], bh0, bh1);
                mma16816(sc[ni], qh[ks][0], qh[ks][1], qh[ks][2], qh[ks][3], bl0, bl1);
                mma16816(sc[ni], ql[ks][0], ql[ks][1], ql[ks][2], ql[ks][3], bh0, bh1);
            }
        }

        // ---- mask + exp + pack P fragments ----
        uint32_t pah[2][4], pal[2][4];
        const int nlim0 = min(mq0, n_hi);
        const int nlim1 = min(mq1, n_hi);
#pragma unroll
        for (int ni = 0; ni < 4; ++ni) {
            int nb = tb + ni * 8 + co;
            float p0 = (nb     <= nlim0) ? __expf(sc[ni][0]) : 0.f;
            float p1 = (nb + 1 <= nlim0) ? __expf(sc[ni][1]) : 0.f;
            float p2 = (nb     <= nlim1) ? __expf(sc[ni][2]) : 0.f;
            float p3 = (nb + 1 <= nlim1) ? __expf(sc[ni][3]) : 0.f;
            l0 += p0 + p1;
            l1 += p2 + p3;
            bf16 h0,lo0,h1,lo1,h2,lo2,h3,lo3;
            split_bf16(p0, h0, lo0);
            split_bf16(p1, h1, lo1);
            split_bf16(p2, h2, lo2);
            split_bf16(p3, h3, lo3);
            int kp = ni >> 1;
            int i0 = (ni & 1) * 2;
            pah[kp][i0]     = pack_bf2(h0, h1);
            pah[kp][i0 + 1] = pack_bf2(h2, h3);
            pal[kp][i0]     = pack_bf2(lo0, lo1);
            pal[kp][i0 + 1] = pack_bf2(lo2, lo3);
        }

        // ---- O += P.V (3-term split) ----
#pragma unroll
        for (int kp = 0; kp < 2; ++kp) {
            int kw = kp * 16 + co;
#pragma unroll
            for (int nd = 0; nd < 8; ++nd) {
                int nr = nd * 8 + ro;
                uint32_t vh0 = *(const uint32_t*)&VTh[nr][kw];
                uint32_t vh1 = *(const uint32_t*)&VTh[nr][kw + 8];
                uint32_t vl0 = *(const uint32_t*)&VTl[nr][kw];
                uint32_t vl1 = *(const uint32_t*)&VTl[nr][kw + 8];
                mma16816(o[nd], pah[kp][0], pah[kp][1], pah[kp][2], pah[kp][3], vh0, vh1);
                mma16816(o[nd], pah[kp][0], pah[kp][1], pah[kp][2], pah[kp][3], vl0, vl1);
                mma16816(o[nd], pal[kp][0], pal[kp][1], pal[kp][2], pal[kp][3], vh0, vh1);
            }
        }
    }

    // ---- reduce denominators across lane quads ----
    l0 += __shfl_xor_sync(0xffffffffu, l0, 1);
    l0 += __shfl_xor_sync(0xffffffffu, l0, 2);
    l1 += __shfl_xor_sync(0xffffffffu, l1, 1);
    l1 += __shfl_xor_sync(0xffffffffu, l1, 2);

    // ---- store (two row-halves per lane) ----
#pragma unroll
    for (int half = 0; half < 2; ++half) {
        int m = (half == 0) ? mq0 : mq1;
        if (m > m_max) continue;
        float lsum = (half == 0) ? l0 : l1;
        int i_glob = r + p * m;
        if (nch == 1) {
            float inv = 1.f / lsum;   // diagonal key always present
            size_t base = ((size_t)(b_ * TT + i_glob)) * DD + h * HD;
#pragma unroll
            for (int nd = 0; nd < 8; ++nd) {
                int d = nd * 8 + co;
                float v0 = o[nd][half * 2]     * inv;
                float v1 = o[nd][half * 2 + 1] * inv;
                bf16 h0,lo0,h1,lo1;
                split_bf16(v0, h0, lo0);
                split_bf16(v1, h1, lo1);
                *(__nv_bfloat162*)(g_atthi + base + d) = __nv_bfloat162(h0, h1);
                *(__nv_bfloat162*)(g_attlo + base + d) = __nv_bfloat162(lo0, lo1);
            }
        } else {
            if ((lane & 3) == 0) atomicAdd(&g_den[bh * TT + i_glob], lsum);
            float* np = g_num + ((size_t)(b_ * TT + i_glob)) * DD + h * HD;
#pragma unroll
            for (int nd = 0; nd < 8; ++nd) {
                int d = nd * 8 + co;
                atomicAdd(np + d,     o[nd][half * 2]);
                atomicAdd(np + d + 1, o[nd][half * 2 + 1]);
            }
        }
    }
}

// ---------------------------------------------------------------------------
// Finalize: normalize multi-chunk queries (den>0) and write bf16 split
// ---------------------------------------------------------------------------
__global__ __launch_bounds__(256) void finalize_kernel()
{
    int g = blockIdx.x * 256 + threadIdx.x;     // one float4 of num
    if (g >= MTOT*DD/4) return;
    int q   = g >> 4;              // query id: bh*2048 + t
    int dg  = (g & 15) * 4;        // dim group within head (0..60)
    float den = g_den[q];
    if (den == 0.f) return;
    int bh = q >> 11, t = q & (TT - 1);
    int b_ = bh >> 4, h = bh & 15;
    size_t base = ((size_t)(b_ * TT + t)) * DD + h * HD + dg;
    float4 nm = *(const float4*)(g_num + base);
    float inv = 1.f / den;
    bf16 h0,h1,h2,h3,l0,l1,l2,l3;
    split_bf16(nm.x * inv, h0, l0);
    split_bf16(nm.y * inv, h1, l1);
    split_bf16(nm.z * inv, h2, l2);
    split_bf16(nm.w * inv, h3, l3);
    __nv_bfloat162* oh = (__nv_bfloat162*)(g_atthi + base);
    __nv_bfloat162* ol = (__nv_bfloat162*)(g_attlo + base);
    oh[0] = __nv_bfloat162(h0, h1);
    oh[1] = __nv_bfloat162(h2, h3);
    ol[0] = __nv_bfloat162(l0, l1);
    ol[1] = __nv_bfloat162(l2, l3);
}

// ---------------------------------------------------------------------------
extern "C" void kernel_launch(void* const* d_in, const int* in_sizes, int n_in,
                              void* d_out, int out_size)
{
    const float* x      = (const float*)d_in[0];
    const void*  per    = d_in[1];                  // int32 or int64, detected on device
    const float* w_qkv  = (const float*)d_in[2];
    const float* b_qkv  = (const float*)d_in[3];
    const float* w_out  = (const float*)d_in[4];
    const float* b_out  = (const float*)d_in[5];
    float* out = (float*)d_out;

    bf16 *xhi, *xlo, *wqh, *wql, *woh, *wol;
    cudaGetSymbolAddress((void**)&xhi, g_xhi);
    cudaGetSymbolAddress((void**)&xlo, g_xlo);
    cudaGetSymbolAddress((void**)&wqh, g_wqT_hi);
    cudaGetSymbolAddress((void**)&wql, g_wqT_lo);
    cudaGetSymbolAddress((void**)&woh, g_woT_hi);
    cudaGetSymbolAddress((void**)&wol, g_woT_lo);

    cudaFuncSetAttribute(qkv_gemm_bf16, cudaFuncAttributeMaxDynamicSharedMemorySize, GEMM_SMEM_BYTES);
    cudaFuncSetAttribute(out_gemm_bf16, cudaFuncAttributeMaxDynamicSharedMemorySize, GEMM_SMEM_BYTES);

    // Pre-passes
    convert_split_kernel<<<(MTOT*DD/4 + 255)/256, 256>>>(x, xhi, xlo, MTOT*DD/4);
    {
        dim3 b(32, 8);
        dim3 gq(N3/32, KK/32);
        transpose_split_kernel<<<gq, b>>>(w_qkv, wqh, wql, KK, N3);
        dim3 go(DD/32, KK/32);
        transpose_split_kernel<<<go, b>>>(w_out, woh, wol, KK, DD);
    }
    zero_scratch_kernel<<<(MTOT*DD/4 + 255)/256, 256>>>();
    worklist_kernel<<<1, 32>>>(per);

    dim3 g1(N3/128, MTOT/128);        // 24 x 32
    qkv_gemm_bf16<<<g1, 256, GEMM_SMEM_BYTES>>>(b_qkv);

    attn_kernel<<<2560, 128>>>();
    finalize_kernel<<<(MTOT*DD/4 + 255)/256, 256>>>();

    dim3 g3(DD/128, MTOT/128);        // 8 x 32
    out_gemm_bf16<<<g3, 256, GEMM_SMEM_BYTES>>>(b_out, out);
}

// round 13
// speedup vs baseline: 3.2873x; 1.0604x over previous
#include <cuda_runtime.h>
#include <cuda_bf16.h>
#include <math.h>
#include <stdint.h>

// Problem constants
#define BB 2
#define TT 2048
#define DD 1024
#define HH 16
#define HD 64
#define N3 3072
#define MTOT (BB*TT)          // 4096
#define KK 1024

typedef __nv_bfloat16 bf16;

// ---------------------------------------------------------------------------
// Device-global scratch (allocation-free contract)
// ---------------------------------------------------------------------------
__device__ bf16  g_xhi[MTOT*DD];        // x split hi/lo, row-major [m][k]
__device__ bf16  g_xlo[MTOT*DD];
__device__ bf16  g_wqT_hi[N3*KK];       // w_qkv^T split, [n][k]
__device__ bf16  g_wqT_lo[N3*KK];
__device__ bf16  g_woT_hi[DD*KK];       // w_out^T split, [n][k]
__device__ bf16  g_woT_lo[DD*KK];
__device__ bf16  g_qhi[BB*HH*TT*HD];    // (b,h,t,hd) bf16 split, q pre-scaled 1/8
__device__ bf16  g_qlo[BB*HH*TT*HD];
__device__ bf16  g_khi[BB*HH*TT*HD];
__device__ bf16  g_klo[BB*HH*TT*HD];
__device__ bf16  g_vhi[BB*HH*TT*HD];
__device__ bf16  g_vlo[BB*HH*TT*HD];
__device__ bf16  g_atthi[MTOT*DD];      // attention output split, [m][d]
__device__ bf16  g_attlo[MTOT*DD];
__device__ float g_num[MTOT*DD];        // multi-chunk partial numerator (b,t,d)
__device__ float g_den[BB*HH*TT];       // multi-chunk partial denominator [bh][t]
__device__ int      g_nwork;
__device__ uint32_t g_work[2600];

// ---------------------------------------------------------------------------
// helpers
// ---------------------------------------------------------------------------
__device__ __forceinline__ void split_bf16(float x, bf16& hi, bf16& lo) {
    hi = __float2bfloat16_rn(x);
    lo = __float2bfloat16_rn(x - __bfloat162float(hi));
}
__device__ __forceinline__ uint32_t pack_bf2(bf16 a, bf16 b) {
    __nv_bfloat162 t(a, b);
    return *(uint32_t*)&t;
}
__device__ __forceinline__ uint32_t smem_u32(const void* p) {
    uint32_t a;
    asm("{ .reg .u64 t; cvta.to.shared.u64 t, %1; cvt.u32.u64 %0, t; }" : "=r"(a) : "l"(p));
    return a;
}
__device__ __forceinline__ void cp16(void* smp, const void* g) {
    uint32_t s = (uint32_t)__cvta_generic_to_shared(smp);
    asm volatile("cp.async.cg.shared.global [%0], [%1], 16;\n" :: "r"(s), "l"(g));
}
__device__ __forceinline__ void cp_commit() { asm volatile("cp.async.commit_group;\n"); }
__device__ __forceinline__ void cp_wait0()  { asm volatile("cp.async.wait_group 0;\n"); }

__device__ __forceinline__ void mma16816(float* c,
    uint32_t a0, uint32_t a1, uint32_t a2, uint32_t a3, uint32_t b0, uint32_t b1)
{
    asm volatile(
        "mma.sync.aligned.m16n8k16.row.col.f32.bf16.bf16.f32 "
        "{%0,%1,%2,%3}, {%4,%5,%6,%7}, {%8,%9}, {%0,%1,%2,%3};\n"
        : "+f"(c[0]), "+f"(c[1]), "+f"(c[2]), "+f"(c[3])
        : "r"(a0), "r"(a1), "r"(a2), "r"(a3), "r"(b0), "r"(b1));
}
__device__ __forceinline__ void ldsm_x4(uint32_t& r0, uint32_t& r1, uint32_t& r2, uint32_t& r3,
                                        uint32_t addr)
{
    asm volatile("ldmatrix.sync.aligned.m8n8.x4.shared.b16 {%0,%1,%2,%3}, [%4];"
                 : "=r"(r0), "=r"(r1), "=r"(r2), "=r"(r3) : "r"(addr));
}
__device__ __forceinline__ void ldsm_x2(uint32_t& r0, uint32_t& r1, uint32_t addr)
{
    asm volatile("ldmatrix.sync.aligned.m8n8.x2.shared.b16 {%0,%1}, [%2];"
                 : "=r"(r0), "=r"(r1) : "r"(addr));
}

// ---------------------------------------------------------------------------
// Pre-pass 1: elementwise split of x
// ---------------------------------------------------------------------------
__global__ __launch_bounds__(256) void convert_split_kernel(
    const float* __restrict__ src, bf16* __restrict__ hi, bf16* __restrict__ lo, int n4)
{
    int i = blockIdx.x * 256 + threadIdx.x;
    if (i >= n4) return;
    float4 v = ((const float4*)src)[i];
    bf16 h0,h1,h2,h3,l0,l1,l2,l3;
    split_bf16(v.x,h0,l0); split_bf16(v.y,h1,l1);
    split_bf16(v.z,h2,l2); split_bf16(v.w,h3,l3);
    __nv_bfloat162* ph = (__nv_bfloat162*)hi;
    __nv_bfloat162* pl = (__nv_bfloat162*)lo;
    ph[2*i]   = __nv_bfloat162(h0,h1);
    ph[2*i+1] = __nv_bfloat162(h2,h3);
    pl[2*i]   = __nv_bfloat162(l0,l1);
    pl[2*i+1] = __nv_bfloat162(l2,l3);
}

// ---------------------------------------------------------------------------
// Pre-pass 2: transpose + split weights  src[K][N] -> dst[N][K] bf16 hi/lo
// ---------------------------------------------------------------------------
__global__ __launch_bounds__(256) void transpose_split_kernel(
    const float* __restrict__ src, bf16* __restrict__ dh, bf16* __restrict__ dl, int Kdim, int Ndim)
{
    __shared__ float t[32][33];
    int tx = threadIdx.x, ty = threadIdx.y;
    int n0 = blockIdx.x * 32, k0 = blockIdx.y * 32;
#pragma unroll
    for (int i = 0; i < 4; ++i)
        t[ty + 8*i][tx] = src[(size_t)(k0 + ty + 8*i) * Ndim + n0 + tx];
    __syncthreads();
#pragma unroll
    for (int i = 0; i < 4; ++i) {
        float v = t[tx][ty + 8*i];
        bf16 h, l; split_bf16(v, h, l);
        size_t o = (size_t)(n0 + ty + 8*i) * Kdim + k0 + tx;
        dh[o] = h; dl[o] = l;
    }
}

// ---------------------------------------------------------------------------
// Zero scratch for attention atomic merge
// ---------------------------------------------------------------------------
__global__ __launch_bounds__(256) void zero_scratch_kernel()
{
    int i = blockIdx.x * 256 + threadIdx.x;
    float4 z = make_float4(0.f, 0.f, 0.f, 0.f);
    if (i < MTOT*DD/4)     ((float4*)g_num)[i] = z;
    if (i < BB*HH*TT/4)    ((float4*)g_den)[i] = z;
}

// ---------------------------------------------------------------------------
// Worklist builder: one thread per (b,h).  Entries: bh|r|qt|kc|p|nch packed.
// ---------------------------------------------------------------------------
__global__ void worklist_kernel(const void* __restrict__ periods_raw)
{
    int tid = threadIdx.x;   // 32 threads
    if (tid == 0) g_nwork = 0;
    __syncthreads();

    const int* pw = (const int*)periods_raw;
    bool is64 = true;
#pragma unroll
    for (int k2 = 1; k2 < 32; k2 += 2) is64 = is64 && (pw[k2] == 0);
    int p = is64 ? pw[2*tid] : pw[tid];
    if (p < 1) p = 1;

    int cnt = 0;
    for (int r = 0; r < p; ++r) {
        int L = (TT - r + p - 1) / p;
        int qts = (L + 63) >> 6;
        for (int qt = 0; qt < qts; ++qt) {
            int m_max = min(qt*64 + 63, L - 1);
            cnt += (m_max >> 9) + 1;
        }
    }
    int base = atomicAdd(&g_nwork, cnt);
    for (int r = 0; r < p; ++r) {
        int L = (TT - r + p - 1) / p;
        int qts = (L + 63) >> 6;
        for (int qt = 0; qt < qts; ++qt) {
            int m_max = min(qt*64 + 63, L - 1);
            int nch = (m_max >> 9) + 1;
            for (int kc = 0; kc < nch; ++kc)
                g_work[base++] = (uint32_t)tid | ((uint32_t)r << 5) |
                                 ((uint32_t)qt << 9) | ((uint32_t)kc << 14) |
                                 ((uint32_t)p << 17) | ((uint32_t)nch << 21);
        }
    }
}

// ---------------------------------------------------------------------------
// GEMM core: 128x128 C-tile, bf16x3 split, BK=32, 2-stage cp.async pipeline,
// fragment loads via ldmatrix (x4 for A, x2 for B).
// ---------------------------------------------------------------------------
#define ST_STRIDE 20480
#define OFF_AH 0
#define OFF_AL 5120
#define OFF_BH 10240
#define OFF_BL 15360
#define GEMM_SMEM_BYTES (2*ST_STRIDE*2)

__device__ __forceinline__ void gemm_issue_stage(
    bf16* st, const bf16* Ahi, const bf16* Alo,
    const bf16* BThi, const bf16* BTlo, int m0, int n0, int k0, int tid)
{
#pragma unroll
    for (int it = 0; it < 2; ++it) {
        int ch  = tid + it * 256;          // 0..511
        int row = ch >> 2;
        int c8  = (ch & 3) << 3;
        size_t ao = (size_t)(m0 + row) * KK + k0 + c8;
        size_t bo = (size_t)(n0 + row) * KK + k0 + c8;
        int so = row * 40 + c8;
        cp16(st + OFF_AH + so, Ahi  + ao);
        cp16(st + OFF_AL + so, Alo  + ao);
        cp16(st + OFF_BH + so, BThi + bo);
        cp16(st + OFF_BL + so, BTlo + bo);
    }
}

__device__ __forceinline__ void gemm_core(
    const bf16* __restrict__ Ahi, const bf16* __restrict__ Alo,
    const bf16* __restrict__ BThi, const bf16* __restrict__ BTlo,
    int m0, int n0, bf16* sm, float c[4][4][4])
{
    const int tid  = threadIdx.x;
    const int lane = tid & 31;
    const int warp = tid >> 5;
    const int wm = warp >> 2;
    const int wn = warp & 3;

    // ldmatrix per-lane offsets (elements)
    const int a_lrow = lane & 15;             // row within 16-row tile
    const int a_lcol = (lane >> 4) << 3;      // 0 or 8 (k-halves)
    const int b_lrow = lane & 7;
    const int b_lcol = ((lane >> 3) & 1) << 3;

#pragma unroll
    for (int i = 0; i < 4; ++i)
#pragma unroll
        for (int j = 0; j < 4; ++j)
#pragma unroll
            for (int q = 0; q < 4; ++q) c[i][j][q] = 0.f;

    gemm_issue_stage(sm, Ahi, Alo, BThi, BTlo, m0, n0, 0, tid);
    cp_commit();

    const uint32_t sbase = smem_u32(sm);

    int s = 0;
    for (int k0 = 0; k0 < KK; k0 += 32, s ^= 1) {
        cp_wait0();
        __syncthreads();
        if (k0 + 32 < KK) {
            gemm_issue_stage(sm + (s^1)*ST_STRIDE, Ahi, Alo, BThi, BTlo, m0, n0, k0 + 32, tid);
            cp_commit();
        }
        const uint32_t stb = sbase + (uint32_t)s * (ST_STRIDE * 2);   // bytes
#pragma unroll
        for (int ks = 0; ks < 2; ++ks) {
            const int kw = ks * 16;
            // ---- B fragments via ldmatrix.x2 ----
            uint32_t bh[4][2], bl[4][2];
#pragma unroll
            for (int ni = 0; ni < 4; ++ni) {
                uint32_t boff = (uint32_t)((wn*32 + ni*8 + b_lrow) * 40 + kw + b_lcol) * 2;
                ldsm_x2(bh[ni][0], bh[ni][1], stb + OFF_BH*2 + boff);
                ldsm_x2(bl[ni][0], bl[ni][1], stb + OFF_BL*2 + boff);
            }
#pragma unroll
            for (int mi = 0; mi < 4; ++mi) {
                // ---- A fragments via ldmatrix.x4 ----
                uint32_t aoff = (uint32_t)((wm*64 + mi*16 + a_lrow) * 40 + kw + a_lcol) * 2;
                uint32_t ah0, ah1, ah2, ah3, al0, al1, al2, al3;
                ldsm_x4(ah0, ah1, ah2, ah3, stb + OFF_AH*2 + aoff);
                ldsm_x4(al0, al1, al2, al3, stb + OFF_AL*2 + aoff);
#pragma unroll
                for (int ni = 0; ni < 4; ++ni) {
                    mma16816(c[mi][ni], ah0, ah1, ah2, ah3, bh[ni][0], bh[ni][1]);
                    mma16816(c[mi][ni], ah0, ah1, ah2, ah3, bl[ni][0], bl[ni][1]);
                    mma16816(c[mi][ni], al0, al1, al2, al3, bh[ni][0], bh[ni][1]);
                }
            }
        }
        __syncthreads();
    }
}

// ---------------------------------------------------------------------------
// Kernel 1: QKV GEMM; epilogue emits bf16 hi/lo q/k/v (q pre-scaled 1/8)
// ---------------------------------------------------------------------------
__global__ __launch_bounds__(256, 2) void qkv_gemm_bf16(const float* __restrict__ bias)
{
    extern __shared__ __align__(16) bf16 dyns[];
    float c[4][4][4];
    const int m0 = blockIdx.y * 128;
    const int n0 = blockIdx.x * 128;
    gemm_core(g_xhi, g_xlo, g_wqT_hi, g_wqT_lo, m0, n0, dyns, c);

    const int tid  = threadIdx.x;
    const int lane = tid & 31;
    const int warp = tid >> 5;
    const int wm = warp >> 2, wn = warp & 3;
    const int ro = lane >> 2, co = (lane & 3) * 2;

    const int which = n0 >> 10;
    bf16* dhi = (which == 0) ? g_qhi : ((which == 1) ? g_khi : g_vhi);
    bf16* dlo = (which == 0) ? g_qlo : ((which == 1) ? g_klo : g_vlo);
    const float scl = (which == 0) ? 0.125f : 1.0f;

#pragma unroll
    for (int mi = 0; mi < 4; ++mi) {
#pragma unroll
        for (int ni = 0; ni < 4; ++ni) {
            int n_a = n0 + wn * 32 + ni * 8 + co;
            int nn = n_a & (DD - 1);
            int hh = nn >> 6;
            int hd = nn & (HD - 1);
            float b0v = bias[n_a], b1v = bias[n_a + 1];
#pragma unroll
            for (int half = 0; half < 2; ++half) {
                int m = m0 + wm * 64 + mi * 16 + ro + half * 8;
                int b_ = m >> 11;
                int t_ = m & (TT - 1);
                float v0 = (c[mi][ni][half*2]     + b0v) * scl;
                float v1 = (c[mi][ni][half*2 + 1] + b1v) * scl;
                bf16 h0,l0,h1,l1;
                split_bf16(v0, h0, l0);
                split_bf16(v1, h1, l1);
                size_t off = (((size_t)(b_ * HH + hh) * TT + t_) << 6) + hd;
                *(__nv_bfloat162*)(dhi + off) = __nv_bfloat162(h0, h1);
                *(__nv_bfloat162*)(dlo + off) = __nv_bfloat162(l0, l1);
            }
        }
    }
}

// ---------------------------------------------------------------------------
// Kernel 3: output projection -> d_out fp32
// ---------------------------------------------------------------------------
__global__ __launch_bounds__(256, 2) void out_gemm_bf16(
    const float* __restrict__ bias, float* __restrict__ Y)
{
    extern __shared__ __align__(16) bf16 dyns[];
    float c[4][4][4];
    const int m0 = blockIdx.y * 128;
    const int n0 = blockIdx.x * 128;
    gemm_core(g_atthi, g_attlo, g_woT_hi, g_woT_lo, m0, n0, dyns, c);

    const int tid  = threadIdx.x;
    const int lane = tid & 31;
    const int warp = tid >> 5;
    const int wm = warp >> 2, wn = warp & 3;
    const int ro = lane >> 2, co = (lane & 3) * 2;

#pragma unroll
    for (int mi = 0; mi < 4; ++mi) {
#pragma unroll
        for (int ni = 0; ni < 4; ++ni) {
            int n_a = n0 + wn * 32 + ni * 8 + co;
            float b0v = bias[n_a], b1v = bias[n_a + 1];
#pragma unroll
            for (int half = 0; half < 2; ++half) {
                int m = m0 + wm * 64 + mi * 16 + ro + half * 8;
                float2 v;
                v.x = c[mi][ni][half * 2]     + b0v;
                v.y = c[mi][ni][half * 2 + 1] + b1v;
                *(float2*)(Y + (size_t)m * DD + n_a) = v;
            }
        }
    }
}

// ---------------------------------------------------------------------------
// Kernel 2: periodic-sparse attention on mma.sync tensor cores (bf16x3).
// ---------------------------------------------------------------------------
__global__ __launch_bounds__(128) void attn_kernel()
{
    if ((int)blockIdx.x >= g_nwork) return;
    const uint32_t e = g_work[blockIdx.x];
    const int bh  = e & 31;
    const int r   = (e >> 5)  & 15;
    const int qt  = (e >> 9)  & 31;
    const int kc  = (e >> 14) & 7;
    const int p   = (e >> 17) & 15;
    const int nch = (e >> 21) & 7;

    const int b_ = bh >> 4;
    const int h  = bh & 15;
    const int L  = (TT - r + p - 1) / p;
    const int m0 = qt * 64;
    const int m_max = min(m0 + 63, L - 1);
    const int n_lo = kc << 9;
    const int n_hi = min(n_lo + 511, m_max);

    __shared__ __align__(16) bf16 Qh[64][72], Ql[64][72];
    __shared__ __align__(16) bf16 Kh[32][72], Kl[32][72];
    __shared__ __align__(16) bf16 VTh[64][40], VTl[64][40];

    const int tid  = threadIdx.x;
    const int warp = tid >> 5;
    const int lane = tid & 31;
    const int ro = lane >> 2;
    const int co = (lane & 3) * 2;

    const size_t hb = (size_t)bh * TT;

    {
        int row = tid >> 1, hf = tid & 1;
        int mq = min(m0 + row, m_max);
        size_t off = (hb + (size_t)(r + p * mq)) * HD + hf * 32;
        const uint4* sh = (const uint4*)(g_qhi + off);
        const uint4* sl = (const uint4*)(g_qlo + off);
        uint4* dh_ = (uint4*)&Qh[row][hf * 32];
        uint4* dl_ = (uint4*)&Ql[row][hf * 32];
#pragma unroll
        for (int q = 0; q < 4; ++q) { dh_[q] = sh[q]; dl_[q] = sl[q]; }
    }
    __syncthreads();

    uint32_t qh[4][4], ql[4][4];
    {
        const int mr = warp * 16 + ro;
#pragma unroll
        for (int ks = 0; ks < 4; ++ks) {
            int kw = ks * 16 + co;
            qh[ks][0] = *(const uint32_t*)&Qh[mr][kw];
            qh[ks][1] = *(const uint32_t*)&Qh[mr + 8][kw];
            qh[ks][2] = *(const uint32_t*)&Qh[mr][kw + 8];
            qh[ks][3] = *(const uint32_t*)&Qh[mr + 8][kw + 8];
            ql[ks][0] = *(const uint32_t*)&Ql[mr][kw];
            ql[ks][1] = *(const uint32_t*)&Ql[mr + 8][kw];
            ql[ks][2] = *(const uint32_t*)&Ql[mr][kw + 8];
            ql[ks][3] = *(const uint32_t*)&Ql[mr + 8][kw + 8];
        }
    }

    float o[8][4];
#pragma unroll
    for (int nd = 0; nd < 8; ++nd)
#pragma unroll
        for (int q = 0; q < 4; ++q) o[nd][q] = 0.f;
    float l0 = 0.f, l1 = 0.f;
    const int mq0 = m0 + warp * 16 + ro;
    const int mq1 = mq0 + 8;

    for (int tb = n_lo; tb <= n_hi; tb += 32) {
        __syncthreads();
        {
            int jrow = tid >> 2, q4 = tid & 3;
            int n = tb + jrow;
            if (n <= n_hi) {
                size_t off = (hb + (size_t)(r + p * n)) * HD + q4 * 16;
                const uint4* sh = (const uint4*)(g_khi + off);
                const uint4* sl = (const uint4*)(g_klo + off);
                *(uint4*)&Kh[jrow][q4*16]     = sh[0];
                *(uint4*)&Kh[jrow][q4*16 + 8] = sh[1];
                *(uint4*)&Kl[jrow][q4*16]     = sl[0];
                *(uint4*)&Kl[jrow][q4*16 + 8] = sl[1];
                const uint32_t* vh = (const uint32_t*)(g_vhi + off);
                const uint32_t* vl = (const uint32_t*)(g_vlo + off);
#pragma unroll
                for (int dd = 0; dd < 8; ++dd) {
                    uint32_t wh = vh[dd], wl = vl[dd];
                    int d = q4 * 16 + dd * 2;
                    __nv_bfloat162 th = *(__nv_bfloat162*)&wh;
                    __nv_bfloat162 tl = *(__nv_bfloat162*)&wl;
                    VTh[d][jrow]     = th.x;
                    VTh[d + 1][jrow] = th.y;
                    VTl[d][jrow]     = tl.x;
                    VTl[d + 1][jrow] = tl.y;
                }
            } else {
                uint4 z = make_uint4(0,0,0,0);
                *(uint4*)&Kh[jrow][q4*16]     = z;
                *(uint4*)&Kh[jrow][q4*16 + 8] = z;
                *(uint4*)&Kl[jrow][q4*16]     = z;
                *(uint4*)&Kl[jrow][q4*16 + 8] = z;
                bf16 zb = __float2bfloat16_rn(0.f);
#pragma unroll
                for (int dd = 0; dd < 16; ++dd) {
                    int d = q4 * 16 + dd;
                    VTh[d][jrow] = zb;
                    VTl[d][jrow] = zb;
                }
            }
        }
        __syncthreads();

        float sc[4][4];
#pragma unroll
        for (int ni = 0; ni < 4; ++ni)
#pragma unroll
            for (int q = 0; q < 4; ++q) sc[ni][q] = 0.f;
#pragma unroll
        for (int ks = 0; ks < 4; ++ks) {
            int kw = ks * 16 + co;
#pragma unroll
            for (int ni = 0; ni < 4; ++ni) {
                int nr = ni * 8 + ro;
                uint32_t bh0 = *(const uint32_t*)&Kh[nr][kw];
                uint32_t bh1 = *(const uint32_t*)&Kh[nr][kw + 8];
                uint32_t bl0 = *(const uint32_t*)&Kl[nr][kw];
                uint32_t bl1 = *(const uint32_t*)&Kl[nr][kw + 8];
                mma16816(sc[ni], qh[ks][0], qh[ks][1], qh[ks][2], qh[ks][3], bh0, bh1);
                mma16816(sc[ni], qh[ks][0], qh[ks][1], qh[ks][2], qh[ks][3], bl0, bl1);
                mma16816(sc[ni], ql[ks][0], ql[ks][1], ql[ks][2], ql[ks][3], bh0, bh1);
            }
        }

        uint32_t pah[2][4], pal[2][4];
        const int nlim0 = min(mq0, n_hi);
        const int nlim1 = min(mq1, n_hi);
#pragma unroll
        for (int ni = 0; ni < 4; ++ni) {
            int nb = tb + ni * 8 + co;
            float p0 = (nb     <= nlim0) ? __expf(sc[ni][0]) : 0.f;
            float p1 = (nb + 1 <= nlim0) ? __expf(sc[ni][1]) : 0.f;
            float p2 = (nb     <= nlim1) ? __expf(sc[ni][2]) : 0.f;
            float p3 = (nb + 1 <= nlim1) ? __expf(sc[ni][3]) : 0.f;
            l0 += p0 + p1;
            l1 += p2 + p3;
            bf16 h0,lo0,h1,lo1,h2,lo2,h3,lo3;
            split_bf16(p0, h0, lo0);
            split_bf16(p1, h1, lo1);
            split_bf16(p2, h2, lo2);
            split_bf16(p3, h3, lo3);
            int kp = ni >> 1;
            int i0 = (ni & 1) * 2;
            pah[kp][i0]     = pack_bf2(h0, h1);
            pah[kp][i0 + 1] = pack_bf2(h2, h3);
            pal[kp][i0]     = pack_bf2(lo0, lo1);
            pal[kp][i0 + 1] = pack_bf2(lo2, lo3);
        }

#pragma unroll
        for (int kp = 0; kp < 2; ++kp) {
            int kw = kp * 16 + co;
#pragma unroll
            for (int nd = 0; nd < 8; ++nd) {
                int nr = nd * 8 + ro;
                uint32_t vh0 = *(const uint32_t*)&VTh[nr][kw];
                uint32_t vh1 = *(const uint32_t*)&VTh[nr][kw + 8];
                uint32_t vl0 = *(const uint32_t*)&VTl[nr][kw];
                uint32_t vl1 = *(const uint32_t*)&VTl[nr][kw + 8];
                mma16816(o[nd], pah[kp][0], pah[kp][1], pah[kp][2], pah[kp][3], vh0, vh1);
                mma16816(o[nd], pah[kp][0], pah[kp][1], pah[kp][2], pah[kp][3], vl0, vl1);
                mma16816(o[nd], pal[kp][0], pal[kp][1], pal[kp][2], pal[kp][3], vh0, vh1);
            }
        }
    }

    l0 += __shfl_xor_sync(0xffffffffu, l0, 1);
    l0 += __shfl_xor_sync(0xffffffffu, l0, 2);
    l1 += __shfl_xor_sync(0xffffffffu, l1, 1);
    l1 += __shfl_xor_sync(0xffffffffu, l1, 2);

#pragma unroll
    for (int half = 0; half < 2; ++half) {
        int m = (half == 0) ? mq0 : mq1;
        if (m > m_max) continue;
        float lsum = (half == 0) ? l0 : l1;
        int i_glob = r + p * m;
        if (nch == 1) {
            float inv = 1.f / lsum;   // diagonal key always present
            size_t base = ((size_t)(b_ * TT + i_glob)) * DD + h * HD;
#pragma unroll
            for (int nd = 0; nd < 8; ++nd) {
                int d = nd * 8 + co;
                float v0 = o[nd][half * 2]     * inv;
                float v1 = o[nd][half * 2 + 1] * inv;
                bf16 h0,lo0,h1,lo1;
                split_bf16(v0, h0, lo0);
                split_bf16(v1, h1, lo1);
                *(__nv_bfloat162*)(g_atthi + base + d) = __nv_bfloat162(h0, h1);
                *(__nv_bfloat162*)(g_attlo + base + d) = __nv_bfloat162(lo0, lo1);
            }
        } else {
            if ((lane & 3) == 0) atomicAdd(&g_den[bh * TT + i_glob], lsum);
            float* np = g_num + ((size_t)(b_ * TT + i_glob)) * DD + h * HD;
#pragma unroll
            for (int nd = 0; nd < 8; ++nd) {
                int d = nd * 8 + co;
                atomicAdd(np + d,     o[nd][half * 2]);
                atomicAdd(np + d + 1, o[nd][half * 2 + 1]);
            }
        }
    }
}

// ---------------------------------------------------------------------------
// Finalize: normalize multi-chunk queries (den>0) and write bf16 split
// ---------------------------------------------------------------------------
__global__ __launch_bounds__(256) void finalize_kernel()
{
    int g = blockIdx.x * 256 + threadIdx.x;     // one float4 of num
    if (g >= MTOT*DD/4) return;
    int q   = g >> 4;              // query id: bh*2048 + t
    int dg  = (g & 15) * 4;        // dim group within head (0..60)
    float den = g_den[q];
    if (den == 0.f) return;
    int bh = q >> 11, t = q & (TT - 1);
    int b_ = bh >> 4, h = bh & 15;
    size_t base = ((size_t)(b_ * TT + t)) * DD + h * HD + dg;
    float4 nm = *(const float4*)(g_num + base);
    float inv = 1.f / den;
    bf16 h0,h1,h2,h3,l0,l1,l2,l3;
    split_bf16(nm.x * inv, h0, l0);
    split_bf16(nm.y * inv, h1, l1);
    split_bf16(nm.z * inv, h2, l2);
    split_bf16(nm.w * inv, h3, l3);
    __nv_bfloat162* oh = (__nv_bfloat162*)(g_atthi + base);
    __nv_bfloat162* ol = (__nv_bfloat162*)(g_attlo + base);
    oh[0] = __nv_bfloat162(h0, h1);
    oh[1] = __nv_bfloat162(h2, h3);
    ol[0] = __nv_bfloat162(l0, l1);
    ol[1] = __nv_bfloat162(l2, l3);
}

// ---------------------------------------------------------------------------
extern "C" void kernel_launch(void* const* d_in, const int* in_sizes, int n_in,
                              void* d_out, int out_size)
{
    const float* x      = (const float*)d_in[0];
    const void*  per    = d_in[1];                  // int32 or int64, detected on device
    const float* w_qkv  = (const float*)d_in[2];
    const float* b_qkv  = (const float*)d_in[3];
    const float* w_out  = (const float*)d_in[4];
    const float* b_out  = (const float*)d_in[5];
    float* out = (float*)d_out;

    bf16 *xhi, *xlo, *wqh, *wql, *woh, *wol;
    cudaGetSymbolAddress((void**)&xhi, g_xhi);
    cudaGetSymbolAddress((void**)&xlo, g_xlo);
    cudaGetSymbolAddress((void**)&wqh, g_wqT_hi);
    cudaGetSymbolAddress((void**)&wql, g_wqT_lo);
    cudaGetSymbolAddress((void**)&woh, g_woT_hi);
    cudaGetSymbolAddress((void**)&wol, g_woT_lo);

    cudaFuncSetAttribute(qkv_gemm_bf16, cudaFuncAttributeMaxDynamicSharedMemorySize, GEMM_SMEM_BYTES);
    cudaFuncSetAttribute(out_gemm_bf16, cudaFuncAttributeMaxDynamicSharedMemorySize, GEMM_SMEM_BYTES);

    // Pre-passes
    convert_split_kernel<<<(MTOT*DD/4 + 255)/256, 256>>>(x, xhi, xlo, MTOT*DD/4);
    {
        dim3 b(32, 8);
        dim3 gq(N3/32, KK/32);
        transpose_split_kernel<<<gq, b>>>(w_qkv, wqh, wql, KK, N3);
        dim3 go(DD/32, KK/32);
        transpose_split_kernel<<<go, b>>>(w_out, woh, wol, KK, DD);
    }
    zero_scratch_kernel<<<(MTOT*DD/4 + 255)/256, 256>>>();
    worklist_kernel<<<1, 32>>>(per);

    dim3 g1(N3/128, MTOT/128);        // 24 x 32
    qkv_gemm_bf16<<<g1, 256, GEMM_SMEM_BYTES>>>(b_qkv);

    attn_kernel<<<2560, 128>>>();
    finalize_kernel<<<(MTOT*DD/4 + 255)/256, 256>>>();

    dim3 g3(DD/128, MTOT/128);        // 8 x 32
    out_gemm_bf16<<<g3, 256, GEMM_SMEM_BYTES>>>(b_out, out);
}

// round 14
// speedup vs baseline: 4.0755x; 1.2398x over previous
#include <cuda_runtime.h>
#include <cuda_bf16.h>
#include <cuda_fp16.h>
#include <math.h>
#include <stdint.h>

// Problem constants
#define BB 2
#define TT 2048
#define DD 1024
#define HH 16
#define HD 64
#define N3 3072
#define MTOT (BB*TT)          // 4096
#define KK 1024

typedef __nv_bfloat16 bf16;
typedef __half f16;

// ---------------------------------------------------------------------------
// Device-global scratch (allocation-free contract)
// ---------------------------------------------------------------------------
__device__ f16   g_xhi[MTOT*DD];        // x split hi/lo (fp16), row-major [m][k]
__device__ f16   g_xlo[MTOT*DD];
__device__ f16   g_wqT_hi[N3*KK];       // w_qkv^T fp16 (hi only), [n][k]
__device__ f16   g_woT_hi[DD*KK];       // w_out^T fp16 (hi only), [n][k]
__device__ bf16  g_qhi[BB*HH*TT*HD];    // (b,h,t,hd) bf16 split, q pre-scaled 1/8
__device__ bf16  g_qlo[BB*HH*TT*HD];
__device__ bf16  g_khi[BB*HH*TT*HD];
__device__ bf16  g_klo[BB*HH*TT*HD];
__device__ bf16  g_vhi[BB*HH*TT*HD];
__device__ bf16  g_vlo[BB*HH*TT*HD];
__device__ f16   g_atthi[MTOT*DD];      // attention output split (fp16), [m][d]
__device__ f16   g_attlo[MTOT*DD];
__device__ float g_num[MTOT*DD];        // multi-chunk partial numerator (b,t,d)
__device__ float g_den[BB*HH*TT];       // multi-chunk partial denominator [bh][t]
__device__ int      g_nwork;
__device__ uint32_t g_work[2600];

// ---------------------------------------------------------------------------
// helpers
// ---------------------------------------------------------------------------
__device__ __forceinline__ void split_bf16(float x, bf16& hi, bf16& lo) {
    hi = __float2bfloat16_rn(x);
    lo = __float2bfloat16_rn(x - __bfloat162float(hi));
}
__device__ __forceinline__ void split_f16(float x, f16& hi, f16& lo) {
    hi = __float2half_rn(x);
    lo = __float2half_rn(x - __half2float(hi));
}
__device__ __forceinline__ uint32_t pack_bf2(bf16 a, bf16 b) {
    __nv_bfloat162 t(a, b);
    return *(uint32_t*)&t;
}
__device__ __forceinline__ uint32_t smem_u32(const void* p) {
    uint32_t a;
    asm("{ .reg .u64 t; cvta.to.shared.u64 t, %1; cvt.u32.u64 %0, t; }" : "=r"(a) : "l"(p));
    return a;
}
__device__ __forceinline__ void cp16(void* smp, const void* g) {
    uint32_t s = (uint32_t)__cvta_generic_to_shared(smp);
    asm volatile("cp.async.cg.shared.global [%0], [%1], 16;\n" :: "r"(s), "l"(g));
}
__device__ __forceinline__ void cp_commit() { asm volatile("cp.async.commit_group;\n"); }
__device__ __forceinline__ void cp_wait0()  { asm volatile("cp.async.wait_group 0;\n"); }

// bf16 mma (attention kernel)
__device__ __forceinline__ void mma16816(float* c,
    uint32_t a0, uint32_t a1, uint32_t a2, uint32_t a3, uint32_t b0, uint32_t b1)
{
    asm volatile(
        "mma.sync.aligned.m16n8k16.row.col.f32.bf16.bf16.f32 "
        "{%0,%1,%2,%3}, {%4,%5,%6,%7}, {%8,%9}, {%0,%1,%2,%3};\n"
        : "+f"(c[0]), "+f"(c[1]), "+f"(c[2]), "+f"(c[3])
        : "r"(a0), "r"(a1), "r"(a2), "r"(a3), "r"(b0), "r"(b1));
}
// fp16 mma (GEMMs)
__device__ __forceinline__ void mma16816h(float* c,
    uint32_t a0, uint32_t a1, uint32_t a2, uint32_t a3, uint32_t b0, uint32_t b1)
{
    asm volatile(
        "mma.sync.aligned.m16n8k16.row.col.f32.f16.f16.f32 "
        "{%0,%1,%2,%3}, {%4,%5,%6,%7}, {%8,%9}, {%0,%1,%2,%3};\n"
        : "+f"(c[0]), "+f"(c[1]), "+f"(c[2]), "+f"(c[3])
        : "r"(a0), "r"(a1), "r"(a2), "r"(a3), "r"(b0), "r"(b1));
}
__device__ __forceinline__ void ldsm_x4(uint32_t& r0, uint32_t& r1, uint32_t& r2, uint32_t& r3,
                                        uint32_t addr)
{
    asm volatile("ldmatrix.sync.aligned.m8n8.x4.shared.b16 {%0,%1,%2,%3}, [%4];"
                 : "=r"(r0), "=r"(r1), "=r"(r2), "=r"(r3) : "r"(addr));
}
__device__ __forceinline__ void ldsm_x2(uint32_t& r0, uint32_t& r1, uint32_t addr)
{
    asm volatile("ldmatrix.sync.aligned.m8n8.x2.shared.b16 {%0,%1}, [%2];"
                 : "=r"(r0), "=r"(r1) : "r"(addr));
}

// ---------------------------------------------------------------------------
// Pre-pass 1: elementwise fp16 split of x
// ---------------------------------------------------------------------------
__global__ __launch_bounds__(256) void convert_split_kernel(
    const float* __restrict__ src, f16* __restrict__ hi, f16* __restrict__ lo, int n4)
{
    int i = blockIdx.x * 256 + threadIdx.x;
    if (i >= n4) return;
    float4 v = ((const float4*)src)[i];
    f16 h0,h1,h2,h3,l0,l1,l2,l3;
    split_f16(v.x,h0,l0); split_f16(v.y,h1,l1);
    split_f16(v.z,h2,l2); split_f16(v.w,h3,l3);
    __half2* ph = (__half2*)hi;
    __half2* pl = (__half2*)lo;
    ph[2*i]   = __halves2half2(h0,h1);
    ph[2*i+1] = __halves2half2(h2,h3);
    pl[2*i]   = __halves2half2(l0,l1);
    pl[2*i+1] = __halves2half2(l2,l3);
}

// ---------------------------------------------------------------------------
// Pre-pass 2: transpose weights  src[K][N] fp32 -> dst[N][K] fp16 (hi only)
// ---------------------------------------------------------------------------
__global__ __launch_bounds__(256) void transpose_split_kernel(
    const float* __restrict__ src, f16* __restrict__ dh, int Kdim, int Ndim)
{
    __shared__ float t[32][33];
    int tx = threadIdx.x, ty = threadIdx.y;
    int n0 = blockIdx.x * 32, k0 = blockIdx.y * 32;
#pragma unroll
    for (int i = 0; i < 4; ++i)
        t[ty + 8*i][tx] = src[(size_t)(k0 + ty + 8*i) * Ndim + n0 + tx];
    __syncthreads();
#pragma unroll
    for (int i = 0; i < 4; ++i) {
        float v = t[tx][ty + 8*i];
        size_t o = (size_t)(n0 + ty + 8*i) * Kdim + k0 + tx;
        dh[o] = __float2half_rn(v);
    }
}

// ---------------------------------------------------------------------------
// Zero scratch for attention atomic merge
// ---------------------------------------------------------------------------
__global__ __launch_bounds__(256) void zero_scratch_kernel()
{
    int i = blockIdx.x * 256 + threadIdx.x;
    float4 z = make_float4(0.f, 0.f, 0.f, 0.f);
    if (i < MTOT*DD/4)     ((float4*)g_num)[i] = z;
    if (i < BB*HH*TT/4)    ((float4*)g_den)[i] = z;
}

// ---------------------------------------------------------------------------
// Worklist builder: one thread per (b,h).  Entries: bh|r|qt|kc|p|nch packed.
// ---------------------------------------------------------------------------
__global__ void worklist_kernel(const void* __restrict__ periods_raw)
{
    int tid = threadIdx.x;   // 32 threads
    if (tid == 0) g_nwork = 0;
    __syncthreads();

    const int* pw = (const int*)periods_raw;
    bool is64 = true;
#pragma unroll
    for (int k2 = 1; k2 < 32; k2 += 2) is64 = is64 && (pw[k2] == 0);
    int p = is64 ? pw[2*tid] : pw[tid];
    if (p < 1) p = 1;

    int cnt = 0;
    for (int r = 0; r < p; ++r) {
        int L = (TT - r + p - 1) / p;
        int qts = (L + 63) >> 6;
        for (int qt = 0; qt < qts; ++qt) {
            int m_max = min(qt*64 + 63, L - 1);
            cnt += (m_max >> 9) + 1;
        }
    }
    int base = atomicAdd(&g_nwork, cnt);
    for (int r = 0; r < p; ++r) {
        int L = (TT - r + p - 1) / p;
        int qts = (L + 63) >> 6;
        for (int qt = 0; qt < qts; ++qt) {
            int m_max = min(qt*64 + 63, L - 1);
            int nch = (m_max >> 9) + 1;
            for (int kc = 0; kc < nch; ++kc)
                g_work[base++] = (uint32_t)tid | ((uint32_t)r << 5) |
                                 ((uint32_t)qt << 9) | ((uint32_t)kc << 14) |
                                 ((uint32_t)p << 17) | ((uint32_t)nch << 21);
        }
    }
}

// ---------------------------------------------------------------------------
// GEMM core: 128x128 C-tile, fp16x2 split (A_hi.B_hi + A_lo.B_hi), BK=32,
// 2-stage cp.async pipeline, ldmatrix fragment loads.
// ---------------------------------------------------------------------------
#define ST_STRIDE 15360
#define OFF_AH 0
#define OFF_AL 5120
#define OFF_BH 10240
#define GEMM_SMEM_BYTES (2*ST_STRIDE*2)

__device__ __forceinline__ void gemm_issue_stage(
    f16* st, const f16* Ahi, const f16* Alo, const f16* BThi,
    int m0, int n0, int k0, int tid)
{
#pragma unroll
    for (int it = 0; it < 2; ++it) {
        int ch  = tid + it * 256;          // 0..511
        int row = ch >> 2;
        int c8  = (ch & 3) << 3;
        size_t ao = (size_t)(m0 + row) * KK + k0 + c8;
        size_t bo = (size_t)(n0 + row) * KK + k0 + c8;
        int so = row * 40 + c8;
        cp16(st + OFF_AH + so, Ahi  + ao);
        cp16(st + OFF_AL + so, Alo  + ao);
        cp16(st + OFF_BH + so, BThi + bo);
    }
}

__device__ __forceinline__ void gemm_core(
    const f16* __restrict__ Ahi, const f16* __restrict__ Alo,
    const f16* __restrict__ BThi,
    int m0, int n0, f16* sm, float c[4][4][4])
{
    const int tid  = threadIdx.x;
    const int lane = tid & 31;
    const int warp = tid >> 5;
    const int wm = warp >> 2;
    const int wn = warp & 3;

    // ldmatrix per-lane offsets (elements)
    const int a_lrow = lane & 15;
    const int a_lcol = (lane >> 4) << 3;
    const int b_lrow = lane & 7;
    const int b_lcol = ((lane >> 3) & 1) << 3;

#pragma unroll
    for (int i = 0; i < 4; ++i)
#pragma unroll
        for (int j = 0; j < 4; ++j)
#pragma unroll
            for (int q = 0; q < 4; ++q) c[i][j][q] = 0.f;

    gemm_issue_stage(sm, Ahi, Alo, BThi, m0, n0, 0, tid);
    cp_commit();

    const uint32_t sbase = smem_u32(sm);

    int s = 0;
    for (int k0 = 0; k0 < KK; k0 += 32, s ^= 1) {
        cp_wait0();
        __syncthreads();
        if (k0 + 32 < KK) {
            gemm_issue_stage(sm + (s^1)*ST_STRIDE, Ahi, Alo, BThi, m0, n0, k0 + 32, tid);
            cp_commit();
        }
        const uint32_t stb = sbase + (uint32_t)s * (ST_STRIDE * 2);   // bytes
#pragma unroll
        for (int ks = 0; ks < 2; ++ks) {
            const int kw = ks * 16;
            uint32_t bh[4][2];
#pragma unroll
            for (int ni = 0; ni < 4; ++ni) {
                uint32_t boff = (uint32_t)((wn*32 + ni*8 + b_lrow) * 40 + kw + b_lcol) * 2;
                ldsm_x2(bh[ni][0], bh[ni][1], stb + OFF_BH*2 + boff);
            }
#pragma unroll
            for (int mi = 0; mi < 4; ++mi) {
                uint32_t aoff = (uint32_t)((wm*64 + mi*16 + a_lrow) * 40 + kw + a_lcol) * 2;
                uint32_t ah0, ah1, ah2, ah3, al0, al1, al2, al3;
                ldsm_x4(ah0, ah1, ah2, ah3, stb + OFF_AH*2 + aoff);
                ldsm_x4(al0, al1, al2, al3, stb + OFF_AL*2 + aoff);
#pragma unroll
                for (int ni = 0; ni < 4; ++ni) {
                    mma16816h(c[mi][ni], ah0, ah1, ah2, ah3, bh[ni][0], bh[ni][1]);
                    mma16816h(c[mi][ni], al0, al1, al2, al3, bh[ni][0], bh[ni][1]);
                }
            }
        }
        __syncthreads();
    }
}

// ---------------------------------------------------------------------------
// Kernel 1: QKV GEMM; epilogue emits bf16 hi/lo q/k/v (q pre-scaled 1/8)
// ---------------------------------------------------------------------------
__global__ __launch_bounds__(256, 2) void qkv_gemm_f16(const float* __restrict__ bias)
{
    extern __shared__ __align__(16) f16 dyns[];
    float c[4][4][4];
    const int m0 = blockIdx.y * 128;
    const int n0 = blockIdx.x * 128;
    gemm_core(g_xhi, g_xlo, g_wqT_hi, m0, n0, dyns, c);

    const int tid  = threadIdx.x;
    const int lane = tid & 31;
    const int warp = tid >> 5;
    const int wm = warp >> 2, wn = warp & 3;
    const int ro = lane >> 2, co = (lane & 3) * 2;

    const int which = n0 >> 10;
    bf16* dhi = (which == 0) ? g_qhi : ((which == 1) ? g_khi : g_vhi);
    bf16* dlo = (which == 0) ? g_qlo : ((which == 1) ? g_klo : g_vlo);
    const float scl = (which == 0) ? 0.125f : 1.0f;

#pragma unroll
    for (int mi = 0; mi < 4; ++mi) {
#pragma unroll
        for (int ni = 0; ni < 4; ++ni) {
            int n_a = n0 + wn * 32 + ni * 8 + co;
            int nn = n_a & (DD - 1);
            int hh = nn >> 6;
            int hd = nn & (HD - 1);
            float b0v = bias[n_a], b1v = bias[n_a + 1];
#pragma unroll
            for (int half = 0; half < 2; ++half) {
                int m = m0 + wm * 64 + mi * 16 + ro + half * 8;
                int b_ = m >> 11;
                int t_ = m & (TT - 1);
                float v0 = (c[mi][ni][half*2]     + b0v) * scl;
                float v1 = (c[mi][ni][half*2 + 1] + b1v) * scl;
                bf16 h0,l0,h1,l1;
                split_bf16(v0, h0, l0);
                split_bf16(v1, h1, l1);
                size_t off = (((size_t)(b_ * HH + hh) * TT + t_) << 6) + hd;
                *(__nv_bfloat162*)(dhi + off) = __nv_bfloat162(h0, h1);
                *(__nv_bfloat162*)(dlo + off) = __nv_bfloat162(l0, l1);
            }
        }
    }
}

// ---------------------------------------------------------------------------
// Kernel 3: output projection -> d_out fp32
// ---------------------------------------------------------------------------
__global__ __launch_bounds__(256, 2) void out_gemm_f16(
    const float* __restrict__ bias, float* __restrict__ Y)
{
    extern __shared__ __align__(16) f16 dyns[];
    float c[4][4][4];
    const int m0 = blockIdx.y * 128;
    const int n0 = blockIdx.x * 128;
    gemm_core(g_atthi, g_attlo, g_woT_hi, m0, n0, dyns, c);

    const int tid  = threadIdx.x;
    const int lane = tid & 31;
    const int warp = tid >> 5;
    const int wm = warp >> 2, wn = warp & 3;
    const int ro = lane >> 2, co = (lane & 3) * 2;

#pragma unroll
    for (int mi = 0; mi < 4; ++mi) {
#pragma unroll
        for (int ni = 0; ni < 4; ++ni) {
            int n_a = n0 + wn * 32 + ni * 8 + co;
            float b0v = bias[n_a], b1v = bias[n_a + 1];
#pragma unroll
            for (int half = 0; half < 2; ++half) {
                int m = m0 + wm * 64 + mi * 16 + ro + half * 8;
                float2 v;
                v.x = c[mi][ni][half * 2]     + b0v;
                v.y = c[mi][ni][half * 2 + 1] + b1v;
                *(float2*)(Y + (size_t)m * DD + n_a) = v;
            }
        }
    }
}

// ---------------------------------------------------------------------------
// Kernel 2: periodic-sparse attention on mma.sync tensor cores (bf16x3).
// Output epilogue emits fp16 hi/lo for the out-projection GEMM.
// ---------------------------------------------------------------------------
__global__ __launch_bounds__(128) void attn_kernel()
{
    if ((int)blockIdx.x >= g_nwork) return;
    const uint32_t e = g_work[blockIdx.x];
    const int bh  = e & 31;
    const int r   = (e >> 5)  & 15;
    const int qt  = (e >> 9)  & 31;
    const int kc  = (e >> 14) & 7;
    const int p   = (e >> 17) & 15;
    const int nch = (e >> 21) & 7;

    const int b_ = bh >> 4;
    const int h  = bh & 15;
    const int L  = (TT - r + p - 1) / p;
    const int m0 = qt * 64;
    const int m_max = min(m0 + 63, L - 1);
    const int n_lo = kc << 9;
    const int n_hi = min(n_lo + 511, m_max);

    __shared__ __align__(16) bf16 Qh[64][72], Ql[64][72];
    __shared__ __align__(16) bf16 Kh[32][72], Kl[32][72];
    __shared__ __align__(16) bf16 VTh[64][40], VTl[64][40];

    const int tid  = threadIdx.x;
    const int warp = tid >> 5;
    const int lane = tid & 31;
    const int ro = lane >> 2;
    const int co = (lane & 3) * 2;

    const size_t hb = (size_t)bh * TT;

    {
        int row = tid >> 1, hf = tid & 1;
        int mq = min(m0 + row, m_max);
        size_t off = (hb + (size_t)(r + p * mq)) * HD + hf * 32;
        const uint4* sh = (const uint4*)(g_qhi + off);
        const uint4* sl = (const uint4*)(g_qlo + off);
        uint4* dh_ = (uint4*)&Qh[row][hf * 32];
        uint4* dl_ = (uint4*)&Ql[row][hf * 32];
#pragma unroll
        for (int q = 0; q < 4; ++q) { dh_[q] = sh[q]; dl_[q] = sl[q]; }
    }
    __syncthreads();

    uint32_t qh[4][4], ql[4][4];
    {
        const int mr = warp * 16 + ro;
#pragma unroll
        for (int ks = 0; ks < 4; ++ks) {
            int kw = ks * 16 + co;
            qh[ks][0] = *(const uint32_t*)&Qh[mr][kw];
            qh[ks][1] = *(const uint32_t*)&Qh[mr + 8][kw];
            qh[ks][2] = *(const uint32_t*)&Qh[mr][kw + 8];
            qh[ks][3] = *(const uint32_t*)&Qh[mr + 8][kw + 8];
            ql[ks][0] = *(const uint32_t*)&Ql[mr][kw];
            ql[ks][1] = *(const uint32_t*)&Ql[mr + 8][kw];
            ql[ks][2] = *(const uint32_t*)&Ql[mr][kw + 8];
            ql[ks][3] = *(const uint32_t*)&Ql[mr + 8][kw + 8];
        }
    }

    float o[8][4];
#pragma unroll
    for (int nd = 0; nd < 8; ++nd)
#pragma unroll
        for (int q = 0; q < 4; ++q) o[nd][q] = 0.f;
    float l0 = 0.f, l1 = 0.f;
    const int mq0 = m0 + warp * 16 + ro;
    const int mq1 = mq0 + 8;

    for (int tb = n_lo; tb <= n_hi; tb += 32) {
        __syncthreads();
        {
            int jrow = tid >> 2, q4 = tid & 3;
            int n = tb + jrow;
            if (n <= n_hi) {
                size_t off = (hb + (size_t)(r + p * n)) * HD + q4 * 16;
                const uint4* sh = (const uint4*)(g_khi + off);
                const uint4* sl = (const uint4*)(g_klo + off);
                *(uint4*)&Kh[jrow][q4*16]     = sh[0];
                *(uint4*)&Kh[jrow][q4*16 + 8] = sh[1];
                *(uint4*)&Kl[jrow][q4*16]     = sl[0];
                *(uint4*)&Kl[jrow][q4*16 + 8] = sl[1];
                const uint32_t* vh = (const uint32_t*)(g_vhi + off);
                const uint32_t* vl = (const uint32_t*)(g_vlo + off);
#pragma unroll
                for (int dd = 0; dd < 8; ++dd) {
                    uint32_t wh = vh[dd], wl = vl[dd];
                    int d = q4 * 16 + dd * 2;
                    __nv_bfloat162 th = *(__nv_bfloat162*)&wh;
                    __nv_bfloat162 tl = *(__nv_bfloat162*)&wl;
                    VTh[d][jrow]     = th.x;
                    VTh[d + 1][jrow] = th.y;
                    VTl[d][jrow]     = tl.x;
                    VTl[d + 1][jrow] = tl.y;
                }
            } else {
                uint4 z = make_uint4(0,0,0,0);
                *(uint4*)&Kh[jrow][q4*16]     = z;
                *(uint4*)&Kh[jrow][q4*16 + 8] = z;
                *(uint4*)&Kl[jrow][q4*16]     = z;
                *(uint4*)&Kl[jrow][q4*16 + 8] = z;
                bf16 zb = __float2bfloat16_rn(0.f);
#pragma unroll
                for (int dd = 0; dd < 16; ++dd) {
                    int d = q4 * 16 + dd;
                    VTh[d][jrow] = zb;
                    VTl[d][jrow] = zb;
                }
            }
        }
        __syncthreads();

        float sc[4][4];
#pragma unroll
        for (int ni = 0; ni < 4; ++ni)
#pragma unroll
            for (int q = 0; q < 4; ++q) sc[ni][q] = 0.f;
#pragma unroll
        for (int ks = 0; ks < 4; ++ks) {
            int kw = ks * 16 + co;
#pragma unroll
            for (int ni = 0; ni < 4; ++ni) {
                int nr = ni * 8 + ro;
                uint32_t bh0 = *(const uint32_t*)&Kh[nr][kw];
                uint32_t bh1 = *(const uint32_t*)&Kh[nr][kw + 8];
                uint32_t bl0 = *(const uint32_t*)&Kl[nr][kw];
                uint32_t bl1 = *(const uint32_t*)&Kl[nr][kw + 8];
                mma16816(sc[ni], qh[ks][0], qh[ks][1], qh[ks][2], qh[ks][3], bh0, bh1);
                mma16816(sc[ni], qh[ks][0], qh[ks][1], qh[ks][2], qh[ks][3], bl0, bl1);
                mma16816(sc[ni], ql[ks][0], ql[ks][1], ql[ks][2], ql[ks][3], bh0, bh1);
            }
        }

        uint32_t pah[2][4], pal[2][4];
        const int nlim0 = min(mq0, n_hi);
        const int nlim1 = min(mq1, n_hi);
#pragma unroll
        for (int ni = 0; ni < 4; ++ni) {
            int nb = tb + ni * 8 + co;
            float p0 = (nb     <= nlim0) ? __expf(sc[ni][0]) : 0.f;
            float p1 = (nb + 1 <= nlim0) ? __expf(sc[ni][1]) : 0.f;
            float p2 = (nb     <= nlim1) ? __expf(sc[ni][2]) : 0.f;
            float p3 = (nb + 1 <= nlim1) ? __expf(sc[ni][3]) : 0.f;
            l0 += p0 + p1;
            l1 += p2 + p3;
            bf16 h0,lo0,h1,lo1,h2,lo2,h3,lo3;
            split_bf16(p0, h0, lo0);
            split_bf16(p1, h1, lo1);
            split_bf16(p2, h2, lo2);
            split_bf16(p3, h3, lo3);
            int kp = ni >> 1;
            int i0 = (ni & 1) * 2;
            pah[kp][i0]     = pack_bf2(h0, h1);
            pah[kp][i0 + 1] = pack_bf2(h2, h3);
            pal[kp][i0]     = pack_bf2(lo0, lo1);
            pal[kp][i0 + 1] = pack_bf2(lo2, lo3);
        }

#pragma unroll
        for (int kp = 0; kp < 2; ++kp) {
            int kw = kp * 16 + co;
#pragma unroll
            for (int nd = 0; nd < 8; ++nd) {
                int nr = nd * 8 + ro;
                uint32_t vh0 = *(const uint32_t*)&VTh[nr][kw];
                uint32_t vh1 = *(const uint32_t*)&VTh[nr][kw + 8];
                uint32_t vl0 = *(const uint32_t*)&VTl[nr][kw];
                uint32_t vl1 = *(const uint32_t*)&VTl[nr][kw + 8];
                mma16816(o[nd], pah[kp][0], pah[kp][1], pah[kp][2], pah[kp][3], vh0, vh1);
                mma16816(o[nd], pah[kp][0], pah[kp][1], pah[kp][2], pah[kp][3], vl0, vl1);
                mma16816(o[nd], pal[kp][0], pal[kp][1], pal[kp][2], pal[kp][3], vh0, vh1);
            }
        }
    }

    l0 += __shfl_xor_sync(0xffffffffu, l0, 1);
    l0 += __shfl_xor_sync(0xffffffffu, l0, 2);
    l1 += __shfl_xor_sync(0xffffffffu, l1, 1);
    l1 += __shfl_xor_sync(0xffffffffu, l1, 2);

#pragma unroll
    for (int half = 0; half < 2; ++half) {
        int m = (half == 0) ? mq0 : mq1;
        if (m > m_max) continue;
        float lsum = (half == 0) ? l0 : l1;
        int i_glob = r + p * m;
        if (nch == 1) {
            float inv = 1.f / lsum;   // diagonal key always present
            size_t base = ((size_t)(b_ * TT + i_glob)) * DD + h * HD;
#pragma unroll
            for (int nd = 0; nd < 8; ++nd) {
                int d = nd * 8 + co;
                float v0 = o[nd][half * 2]     * inv;
                float v1 = o[nd][half * 2 + 1] * inv;
                f16 h0,lo0,h1,lo1;
                split_f16(v0, h0, lo0);
                split_f16(v1, h1, lo1);
                *(__half2*)(g_atthi + base + d) = __halves2half2(h0, h1);
                *(__half2*)(g_attlo + base + d) = __halves2half2(lo0, lo1);
            }
        } else {
            if ((lane & 3) == 0) atomicAdd(&g_den[bh * TT + i_glob], lsum);
            float* np = g_num + ((size_t)(b_ * TT + i_glob)) * DD + h * HD;
#pragma unroll
            for (int nd = 0; nd < 8; ++nd) {
                int d = nd * 8 + co;
                atomicAdd(np + d,     o[nd][half * 2]);
                atomicAdd(np + d + 1, o[nd][half * 2 + 1]);
            }
        }
    }
}

// ---------------------------------------------------------------------------
// Finalize: normalize multi-chunk queries (den>0) and write fp16 split
// ---------------------------------------------------------------------------
__global__ __launch_bounds__(256) void finalize_kernel()
{
    int g = blockIdx.x * 256 + threadIdx.x;     // one float4 of num
    if (g >= MTOT*DD/4) return;
    int q   = g >> 4;              // query id: bh*2048 + t
    int dg  = (g & 15) * 4;        // dim group within head (0..60)
    float den = g_den[q];
    if (den == 0.f) return;
    int bh = q >> 11, t = q & (TT - 1);
    int b_ = bh >> 4, h = bh & 15;
    size_t base = ((size_t)(b_ * TT + t)) * DD + h * HD + dg;
    float4 nm = *(const float4*)(g_num + base);
    float inv = 1.f / den;
    f16 h0,h1,h2,h3,l0,l1,l2,l3;
    split_f16(nm.x * inv, h0, l0);
    split_f16(nm.y * inv, h1, l1);
    split_f16(nm.z * inv, h2, l2);
    split_f16(nm.w * inv, h3, l3);
    __half2* oh = (__half2*)(g_atthi + base);
    __half2* ol = (__half2*)(g_attlo + base);
    oh[0] = __halves2half2(h0, h1);
    oh[1] = __halves2half2(h2, h3);
    ol[0] = __halves2half2(l0, l1);
    ol[1] = __halves2half2(l2, l3);
}

// ---------------------------------------------------------------------------
extern "C" void kernel_launch(void* const* d_in, const int* in_sizes, int n_in,
                              void* d_out, int out_size)
{
    const float* x      = (const float*)d_in[0];
    const void*  per    = d_in[1];                  // int32 or int64, detected on device
    const float* w_qkv  = (const float*)d_in[2];
    const float* b_qkv  = (const float*)d_in[3];
    const float* w_out  = (const float*)d_in[4];
    const float* b_out  = (const float*)d_in[5];
    float* out = (float*)d_out;

    f16 *xhi, *xlo, *wqh, *woh;
    cudaGetSymbolAddress((void**)&xhi, g_xhi);
    cudaGetSymbolAddress((void**)&xlo, g_xlo);
    cudaGetSymbolAddress((void**)&wqh, g_wqT_hi);
    cudaGetSymbolAddress((void**)&woh, g_woT_hi);

    cudaFuncSetAttribute(qkv_gemm_f16, cudaFuncAttributeMaxDynamicSharedMemorySize, GEMM_SMEM_BYTES);
    cudaFuncSetAttribute(out_gemm_f16, cudaFuncAttributeMaxDynamicSharedMemorySize, GEMM_SMEM_BYTES);

    // Pre-passes
    convert_split_kernel<<<(MTOT*DD/4 + 255)/256, 256>>>(x, xhi, xlo, MTOT*DD/4);
    {
        dim3 b(32, 8);
        dim3 gq(N3/32, KK/32);
        transpose_split_kernel<<<gq, b>>>(w_qkv, wqh, KK, N3);
        dim3 go(DD/32, KK/32);
        transpose_split_kernel<<<go, b>>>(w_out, woh, KK, DD);
    }
    zero_scratch_kernel<<<(MTOT*DD/4 + 255)/256, 256>>>();
    worklist_kernel<<<1, 32>>>(per);

    dim3 g1(N3/128, MTOT/128);        // 24 x 32
    qkv_gemm_f16<<<g1, 256, GEMM_SMEM_BYTES>>>(b_qkv);

    attn_kernel<<<2560, 128>>>();
    finalize_kernel<<<(MTOT*DD/4 + 255)/256, 256>>>();

    dim3 g3(DD/128, MTOT/128);        // 8 x 32
    out_gemm_f16<<<g3, 256, GEMM_SMEM_BYTES>>>(b_out, out);
}

// round 15
// speedup vs baseline: 4.7843x; 1.1739x over previous
#include <cuda_runtime.h>
#include <cuda_bf16.h>
#include <cuda_fp16.h>
#include <math.h>
#include <stdint.h>

// Problem constants
#define BB 2
#define TT 2048
#define DD 1024
#define HH 16
#define HD 64
#define N3 3072
#define MTOT (BB*TT)          // 4096
#define KK 1024

typedef __nv_bfloat16 bf16;
typedef __half f16;

// ---------------------------------------------------------------------------
// Device-global scratch (allocation-free contract)
// ---------------------------------------------------------------------------
__device__ f16   g_xhi[MTOT*DD];        // x split hi/lo (fp16), row-major [m][k]
__device__ f16   g_xlo[MTOT*DD];
__device__ f16   g_wqT_hi[N3*KK];       // w_qkv^T fp16 (hi only), [n][k]
__device__ f16   g_woT_hi[DD*KK];       // w_out^T fp16 (hi only), [n][k]
__device__ bf16  g_qhi[BB*HH*TT*HD];    // (b,h,t,hd) bf16 split, q pre-scaled 1/8
__device__ bf16  g_qlo[BB*HH*TT*HD];
__device__ bf16  g_khi[BB*HH*TT*HD];
__device__ bf16  g_klo[BB*HH*TT*HD];
__device__ bf16  g_vhi[BB*HH*TT*HD];
__device__ bf16  g_vlo[BB*HH*TT*HD];
__device__ f16   g_att[MTOT*DD];        // attention output (fp16), [m][d]
__device__ float g_num[MTOT*DD];        // multi-chunk partial numerator (b,t,d)
__device__ float g_den[BB*HH*TT];       // multi-chunk partial denominator [bh][t]
__device__ int      g_nwork;
__device__ uint32_t g_work[2600];

// ---------------------------------------------------------------------------
// helpers
// ---------------------------------------------------------------------------
__device__ __forceinline__ void split_bf16(float x, bf16& hi, bf16& lo) {
    hi = __float2bfloat16_rn(x);
    lo = __float2bfloat16_rn(x - __bfloat162float(hi));
}
__device__ __forceinline__ void split_f16(float x, f16& hi, f16& lo) {
    hi = __float2half_rn(x);
    lo = __float2half_rn(x - __half2float(hi));
}
__device__ __forceinline__ uint32_t pack_bf2(bf16 a, bf16 b) {
    __nv_bfloat162 t(a, b);
    return *(uint32_t*)&t;
}
__device__ __forceinline__ uint32_t smem_u32(const void* p) {
    uint32_t a;
    asm("{ .reg .u64 t; cvta.to.shared.u64 t, %1; cvt.u32.u64 %0, t; }" : "=r"(a) : "l"(p));
    return a;
}
__device__ __forceinline__ void cp16(void* smp, const void* g) {
    uint32_t s = (uint32_t)__cvta_generic_to_shared(smp);
    asm volatile("cp.async.cg.shared.global [%0], [%1], 16;\n" :: "r"(s), "l"(g));
}
__device__ __forceinline__ void cp_commit() { asm volatile("cp.async.commit_group;\n"); }
__device__ __forceinline__ void cp_wait0()  { asm volatile("cp.async.wait_group 0;\n"); }

// bf16 mma (attention kernel)
__device__ __forceinline__ void mma16816(float* c,
    uint32_t a0, uint32_t a1, uint32_t a2, uint32_t a3, uint32_t b0, uint32_t b1)
{
    asm volatile(
        "mma.sync.aligned.m16n8k16.row.col.f32.bf16.bf16.f32 "
        "{%0,%1,%2,%3}, {%4,%5,%6,%7}, {%8,%9}, {%0,%1,%2,%3};\n"
        : "+f"(c[0]), "+f"(c[1]), "+f"(c[2]), "+f"(c[3])
        : "r"(a0), "r"(a1), "r"(a2), "r"(a3), "r"(b0), "r"(b1));
}
// fp16 mma (GEMMs)
__device__ __forceinline__ void mma16816h(float* c,
    uint32_t a0, uint32_t a1, uint32_t a2, uint32_t a3, uint32_t b0, uint32_t b1)
{
    asm volatile(
        "mma.sync.aligned.m16n8k16.row.col.f32.f16.f16.f32 "
        "{%0,%1,%2,%3}, {%4,%5,%6,%7}, {%8,%9}, {%0,%1,%2,%3};\n"
        : "+f"(c[0]), "+f"(c[1]), "+f"(c[2]), "+f"(c[3])
        : "r"(a0), "r"(a1), "r"(a2), "r"(a3), "r"(b0), "r"(b1));
}
__device__ __forceinline__ void ldsm_x4(uint32_t& r0, uint32_t& r1, uint32_t& r2, uint32_t& r3,
                                        uint32_t addr)
{
    asm volatile("ldmatrix.sync.aligned.m8n8.x4.shared.b16 {%0,%1,%2,%3}, [%4];"
                 : "=r"(r0), "=r"(r1), "=r"(r2), "=r"(r3) : "r"(addr));
}
__device__ __forceinline__ void ldsm_x2(uint32_t& r0, uint32_t& r1, uint32_t addr)
{
    asm volatile("ldmatrix.sync.aligned.m8n8.x2.shared.b16 {%0,%1}, [%2];"
                 : "=r"(r0), "=r"(r1) : "r"(addr));
}

// ---------------------------------------------------------------------------
// FUSED pre-pass kernel: block ranges do independent jobs in one launch.
//   [0,4096)            : fp16 split of x -> g_xhi/g_xlo
//   [4096,7168)         : transpose w_qkv -> g_wqT_hi (fp16)
//   [7168,8192)         : transpose w_out -> g_woT_hi (fp16)
//   [8192,12288)        : zero g_num/g_den
//   12288               : worklist build
// ---------------------------------------------------------------------------
__global__ __launch_bounds__(256) void prepass_kernel(
    const float* __restrict__ x, const float* __restrict__ wqkv,
    const float* __restrict__ wout, const void* __restrict__ periods_raw)
{
    __shared__ float t[32][33];
    const int b   = blockIdx.x;
    const int tid = threadIdx.x;

    if (b < 4096) {
        // ---- convert/split x ----
        int i = b * 256 + tid;                    // one float4 per thread
        if (i < MTOT*DD/4) {
            float4 v = ((const float4*)x)[i];
            f16 h0,h1,h2,h3,l0,l1,l2,l3;
            split_f16(v.x,h0,l0); split_f16(v.y,h1,l1);
            split_f16(v.z,h2,l2); split_f16(v.w,h3,l3);
            __half2* ph = (__half2*)g_xhi;
            __half2* pl = (__half2*)g_xlo;
            ph[2*i]   = __halves2half2(h0,h1);
            ph[2*i+1] = __halves2half2(h2,h3);
            pl[2*i]   = __halves2half2(l0,l1);
            pl[2*i+1] = __halves2half2(l2,l3);
        }
    } else if (b < 8192) {
        // ---- weight transpose (fp16 hi only) ----
        const float* src; f16* dst; int Ndim, idx;
        if (b < 7168) { src = wqkv; dst = g_wqT_hi; Ndim = N3; idx = b - 4096; }
        else          { src = wout; dst = g_woT_hi; Ndim = DD; idx = b - 7168; }
        int nb = Ndim / 32;
        int bx = idx % nb, by = idx / nb;
        int n0 = bx * 32, k0 = by * 32;
        int tx = tid & 31, ty = tid >> 5;         // (32,8)
#pragma unroll
        for (int i = 0; i < 4; ++i)
            t[ty + 8*i][tx] = src[(size_t)(k0 + ty + 8*i) * Ndim + n0 + tx];
        __syncthreads();
#pragma unroll
        for (int i = 0; i < 4; ++i) {
            float v = t[tx][ty + 8*i];
            size_t o = (size_t)(n0 + ty + 8*i) * KK + k0 + tx;
            dst[o] = __float2half_rn(v);
        }
    } else if (b < 12288) {
        // ---- zero scratch ----
        int i = (b - 8192) * 256 + tid;
        float4 z = make_float4(0.f, 0.f, 0.f, 0.f);
        if (i < MTOT*DD/4)  ((float4*)g_num)[i] = z;
        if (i < BB*HH*TT/4) ((float4*)g_den)[i] = z;
    } else {
        // ---- worklist (32 active threads) ----
        if (tid == 0) g_nwork = 0;
        __syncthreads();
        if (tid < 32) {
            const int* pw = (const int*)periods_raw;
            bool is64 = true;
#pragma unroll
            for (int k2 = 1; k2 < 32; k2 += 2) is64 = is64 && (pw[k2] == 0);
            int p = is64 ? pw[2*tid] : pw[tid];
            if (p < 1) p = 1;

            int cnt = 0;
            for (int r = 0; r < p; ++r) {
                int L = (TT - r + p - 1) / p;
                int qts = (L + 63) >> 6;
                for (int qt = 0; qt < qts; ++qt) {
                    int m_max = min(qt*64 + 63, L - 1);
                    cnt += (m_max >> 9) + 1;
                }
            }
            int base = atomicAdd(&g_nwork, cnt);
            for (int r = 0; r < p; ++r) {
                int L = (TT - r + p - 1) / p;
                int qts = (L + 63) >> 6;
                for (int qt = 0; qt < qts; ++qt) {
                    int m_max = min(qt*64 + 63, L - 1);
                    int nch = (m_max >> 9) + 1;
                    for (int kc = 0; kc < nch; ++kc)
                        g_work[base++] = (uint32_t)tid | ((uint32_t)r << 5) |
                                         ((uint32_t)qt << 9) | ((uint32_t)kc << 14) |
                                         ((uint32_t)p << 17) | ((uint32_t)nch << 21);
                }
            }
        }
    }
}

// ---------------------------------------------------------------------------
// GEMM core: 128x128 C-tile, fp16, BK=32, 2-stage cp.async pipeline,
// ldmatrix fragment loads.  use_lo (block-uniform) adds the A_lo.B_hi term.
// ---------------------------------------------------------------------------
#define ST_STRIDE 15360
#define OFF_AH 0
#define OFF_AL 5120
#define OFF_BH 10240
#define GEMM_SMEM_BYTES (2*ST_STRIDE*2)

__device__ __forceinline__ void gemm_issue_stage(
    f16* st, const f16* Ahi, const f16* Alo, const f16* BThi,
    int m0, int n0, int k0, int tid, bool use_lo)
{
#pragma unroll
    for (int it = 0; it < 2; ++it) {
        int ch  = tid + it * 256;          // 0..511
        int row = ch >> 2;
        int c8  = (ch & 3) << 3;
        size_t ao = (size_t)(m0 + row) * KK + k0 + c8;
        size_t bo = (size_t)(n0 + row) * KK + k0 + c8;
        int so = row * 40 + c8;
        cp16(st + OFF_AH + so, Ahi  + ao);
        if (use_lo) cp16(st + OFF_AL + so, Alo + ao);
        cp16(st + OFF_BH + so, BThi + bo);
    }
}

__device__ __forceinline__ void gemm_core(
    const f16* __restrict__ Ahi, const f16* __restrict__ Alo,
    const f16* __restrict__ BThi,
    int m0, int n0, f16* sm, float c[4][4][4], bool use_lo)
{
    const int tid  = threadIdx.x;
    const int lane = tid & 31;
    const int warp = tid >> 5;
    const int wm = warp >> 2;
    const int wn = warp & 3;

    const int a_lrow = lane & 15;
    const int a_lcol = (lane >> 4) << 3;
    const int b_lrow = lane & 7;
    const int b_lcol = ((lane >> 3) & 1) << 3;

#pragma unroll
    for (int i = 0; i < 4; ++i)
#pragma unroll
        for (int j = 0; j < 4; ++j)
#pragma unroll
            for (int q = 0; q < 4; ++q) c[i][j][q] = 0.f;

    gemm_issue_stage(sm, Ahi, Alo, BThi, m0, n0, 0, tid, use_lo);
    cp_commit();

    const uint32_t sbase = smem_u32(sm);

    int s = 0;
    for (int k0 = 0; k0 < KK; k0 += 32, s ^= 1) {
        cp_wait0();
        __syncthreads();
        if (k0 + 32 < KK) {
            gemm_issue_stage(sm + (s^1)*ST_STRIDE, Ahi, Alo, BThi, m0, n0, k0 + 32, tid, use_lo);
            cp_commit();
        }
        const uint32_t stb = sbase + (uint32_t)s * (ST_STRIDE * 2);   // bytes
#pragma unroll
        for (int ks = 0; ks < 2; ++ks) {
            const int kw = ks * 16;
            uint32_t bh[4][2];
#pragma unroll
            for (int ni = 0; ni < 4; ++ni) {
                uint32_t boff = (uint32_t)((wn*32 + ni*8 + b_lrow) * 40 + kw + b_lcol) * 2;
                ldsm_x2(bh[ni][0], bh[ni][1], stb + OFF_BH*2 + boff);
            }
#pragma unroll
            for (int mi = 0; mi < 4; ++mi) {
                uint32_t aoff = (uint32_t)((wm*64 + mi*16 + a_lrow) * 40 + kw + a_lcol) * 2;
                uint32_t ah0, ah1, ah2, ah3;
                ldsm_x4(ah0, ah1, ah2, ah3, stb + OFF_AH*2 + aoff);
                if (use_lo) {
                    uint32_t al0, al1, al2, al3;
                    ldsm_x4(al0, al1, al2, al3, stb + OFF_AL*2 + aoff);
#pragma unroll
                    for (int ni = 0; ni < 4; ++ni) {
                        mma16816h(c[mi][ni], ah0, ah1, ah2, ah3, bh[ni][0], bh[ni][1]);
                        mma16816h(c[mi][ni], al0, al1, al2, al3, bh[ni][0], bh[ni][1]);
                    }
                } else {
#pragma unroll
                    for (int ni = 0; ni < 4; ++ni)
                        mma16816h(c[mi][ni], ah0, ah1, ah2, ah3, bh[ni][0], bh[ni][1]);
                }
            }
        }
        __syncthreads();
    }
}

// ---------------------------------------------------------------------------
// Kernel 1: QKV GEMM; epilogue emits bf16 hi/lo q/k/v (q pre-scaled 1/8).
// V tiles use the x1 (hi-only) path — V error passes linearly to output.
// ---------------------------------------------------------------------------
__global__ __launch_bounds__(256, 2) void qkv_gemm_f16(const float* __restrict__ bias)
{
    extern __shared__ __align__(16) f16 dyns[];
    float c[4][4][4];
    const int m0 = blockIdx.y * 128;
    const int n0 = blockIdx.x * 128;
    const int which = n0 >> 10;
    gemm_core(g_xhi, g_xlo, g_wqT_hi, m0, n0, dyns, c, which != 2);

    const int tid  = threadIdx.x;
    const int lane = tid & 31;
    const int warp = tid >> 5;
    const int wm = warp >> 2, wn = warp & 3;
    const int ro = lane >> 2, co = (lane & 3) * 2;

    bf16* dhi = (which == 0) ? g_qhi : ((which == 1) ? g_khi : g_vhi);
    bf16* dlo = (which == 0) ? g_qlo : ((which == 1) ? g_klo : g_vlo);
    const float scl = (which == 0) ? 0.125f : 1.0f;

#pragma unroll
    for (int mi = 0; mi < 4; ++mi) {
#pragma unroll
        for (int ni = 0; ni < 4; ++ni) {
            int n_a = n0 + wn * 32 + ni * 8 + co;
            int nn = n_a & (DD - 1);
            int hh = nn >> 6;
            int hd = nn & (HD - 1);
            float b0v = bias[n_a], b1v = bias[n_a + 1];
#pragma unroll
            for (int half = 0; half < 2; ++half) {
                int m = m0 + wm * 64 + mi * 16 + ro + half * 8;
                int b_ = m >> 11;
                int t_ = m & (TT - 1);
                float v0 = (c[mi][ni][half*2]     + b0v) * scl;
                float v1 = (c[mi][ni][half*2 + 1] + b1v) * scl;
                bf16 h0,l0,h1,l1;
                split_bf16(v0, h0, l0);
                split_bf16(v1, h1, l1);
                size_t off = (((size_t)(b_ * HH + hh) * TT + t_) << 6) + hd;
                *(__nv_bfloat162*)(dhi + off) = __nv_bfloat162(h0, h1);
                *(__nv_bfloat162*)(dlo + off) = __nv_bfloat162(l0, l1);
            }
        }
    }
}

// ---------------------------------------------------------------------------
// Kernel 3: output projection (x1 fp16) -> d_out fp32
// ---------------------------------------------------------------------------
__global__ __launch_bounds__(256, 2) void out_gemm_f16(
    const float* __restrict__ bias, float* __restrict__ Y)
{
    extern __shared__ __align__(16) f16 dyns[];
    float c[4][4][4];
    const int m0 = blockIdx.y * 128;
    const int n0 = blockIdx.x * 128;
    gemm_core(g_att, g_att, g_woT_hi, m0, n0, dyns, c, false);

    const int tid  = threadIdx.x;
    const int lane = tid & 31;
    const int warp = tid >> 5;
    const int wm = warp >> 2, wn = warp & 3;
    const int ro = lane >> 2, co = (lane & 3) * 2;

#pragma unroll
    for (int mi = 0; mi < 4; ++mi) {
#pragma unroll
        for (int ni = 0; ni < 4; ++ni) {
            int n_a = n0 + wn * 32 + ni * 8 + co;
            float b0v = bias[n_a], b1v = bias[n_a + 1];
#pragma unroll
            for (int half = 0; half < 2; ++half) {
                int m = m0 + wm * 64 + mi * 16 + ro + half * 8;
                float2 v;
                v.x = c[mi][ni][half * 2]     + b0v;
                v.y = c[mi][ni][half * 2 + 1] + b1v;
                *(float2*)(Y + (size_t)m * DD + n_a) = v;
            }
        }
    }
}

// ---------------------------------------------------------------------------
// Kernel 2: periodic-sparse attention on mma.sync tensor cores (bf16x3).
// Output epilogue emits single fp16 for the out-projection GEMM.
// ---------------------------------------------------------------------------
__global__ __launch_bounds__(128) void attn_kernel()
{
    if ((int)blockIdx.x >= g_nwork) return;
    const uint32_t e = g_work[blockIdx.x];
    const int bh  = e & 31;
    const int r   = (e >> 5)  & 15;
    const int qt  = (e >> 9)  & 31;
    const int kc  = (e >> 14) & 7;
    const int p   = (e >> 17) & 15;
    const int nch = (e >> 21) & 7;

    const int b_ = bh >> 4;
    const int h  = bh & 15;
    const int L  = (TT - r + p - 1) / p;
    const int m0 = qt * 64;
    const int m_max = min(m0 + 63, L - 1);
    const int n_lo = kc << 9;
    const int n_hi = min(n_lo + 511, m_max);

    __shared__ __align__(16) bf16 Qh[64][72], Ql[64][72];
    __shared__ __align__(16) bf16 Kh[32][72], Kl[32][72];
    __shared__ __align__(16) bf16 VTh[64][40], VTl[64][40];

    const int tid  = threadIdx.x;
    const int warp = tid >> 5;
    const int lane = tid & 31;
    const int ro = lane >> 2;
    const int co = (lane & 3) * 2;

    const size_t hb = (size_t)bh * TT;

    {
        int row = tid >> 1, hf = tid & 1;
        int mq = min(m0 + row, m_max);
        size_t off = (hb + (size_t)(r + p * mq)) * HD + hf * 32;
        const uint4* sh = (const uint4*)(g_qhi + off);
        const uint4* sl = (const uint4*)(g_qlo + off);
        uint4* dh_ = (uint4*)&Qh[row][hf * 32];
        uint4* dl_ = (uint4*)&Ql[row][hf * 32];
#pragma unroll
        for (int q = 0; q < 4; ++q) { dh_[q] = sh[q]; dl_[q] = sl[q]; }
    }
    __syncthreads();

    uint32_t qh[4][4], ql[4][4];
    {
        const int mr = warp * 16 + ro;
#pragma unroll
        for (int ks = 0; ks < 4; ++ks) {
            int kw = ks * 16 + co;
            qh[ks][0] = *(const uint32_t*)&Qh[mr][kw];
            qh[ks][1] = *(const uint32_t*)&Qh[mr + 8][kw];
            qh[ks][2] = *(const uint32_t*)&Qh[mr][kw + 8];
            qh[ks][3] = *(const uint32_t*)&Qh[mr + 8][kw + 8];
            ql[ks][0] = *(const uint32_t*)&Ql[mr][kw];
            ql[ks][1] = *(const uint32_t*)&Ql[mr + 8][kw];
            ql[ks][2] = *(const uint32_t*)&Ql[mr][kw + 8];
            ql[ks][3] = *(const uint32_t*)&Ql[mr + 8][kw + 8];
        }
    }

    float o[8][4];
#pragma unroll
    for (int nd = 0; nd < 8; ++nd)
#pragma unroll
        for (int q = 0; q < 4; ++q) o[nd][q] = 0.f;
    float l0 = 0.f, l1 = 0.f;
    const int mq0 = m0 + warp * 16 + ro;
    const int mq1 = mq0 + 8;

    for (int tb = n_lo; tb <= n_hi; tb += 32) {
        __syncthreads();
        {
            int jrow = tid >> 2, q4 = tid & 3;
            int n = tb + jrow;
            if (n <= n_hi) {
                size_t off = (hb + (size_t)(r + p * n)) * HD + q4 * 16;
                const uint4* sh = (const uint4*)(g_khi + off);
                const uint4* sl = (const uint4*)(g_klo + off);
                *(uint4*)&Kh[jrow][q4*16]     = sh[0];
                *(uint4*)&Kh[jrow][q4*16 + 8] = sh[1];
                *(uint4*)&Kl[jrow][q4*16]     = sl[0];
                *(uint4*)&Kl[jrow][q4*16 + 8] = sl[1];
                const uint32_t* vh = (const uint32_t*)(g_vhi + off);
                const uint32_t* vl = (const uint32_t*)(g_vlo + off);
#pragma unroll
                for (int dd = 0; dd < 8; ++dd) {
                    uint32_t wh = vh[dd], wl = vl[dd];
                    int d = q4 * 16 + dd * 2;
                    __nv_bfloat162 th = *(__nv_bfloat162*)&wh;
                    __nv_bfloat162 tl = *(__nv_bfloat162*)&wl;
                    VTh[d][jrow]     = th.x;
                    VTh[d + 1][jrow] = th.y;
                    VTl[d][jrow]     = tl.x;
                    VTl[d + 1][jrow] = tl.y;
                }
            } else {
                uint4 z = make_uint4(0,0,0,0);
                *(uint4*)&Kh[jrow][q4*16]     = z;
                *(uint4*)&Kh[jrow][q4*16 + 8] = z;
                *(uint4*)&Kl[jrow][q4*16]     = z;
                *(uint4*)&Kl[jrow][q4*16 + 8] = z;
                bf16 zb = __float2bfloat16_rn(0.f);
#pragma unroll
                for (int dd = 0; dd < 16; ++dd) {
                    int d = q4 * 16 + dd;
                    VTh[d][jrow] = zb;
                    VTl[d][jrow] = zb;
                }
            }
        }
        __syncthreads();

        float sc[4][4];
#pragma unroll
        for (int ni = 0; ni < 4; ++ni)
#pragma unroll
            for (int q = 0; q < 4; ++q) sc[ni][q] = 0.f;
#pragma unroll
        for (int ks = 0; ks < 4; ++ks) {
            int kw = ks * 16 + co;
#pragma unroll
            for (int ni = 0; ni < 4; ++ni) {
                int nr = ni * 8 + ro;
                uint32_t bh0 = *(const uint32_t*)&Kh[nr][kw];
                uint32_t bh1 = *(const uint32_t*)&Kh[nr][kw + 8];
                uint32_t bl0 = *(const uint32_t*)&Kl[nr][kw];
                uint32_t bl1 = *(const uint32_t*)&Kl[nr][kw + 8];
                mma16816(sc[ni], qh[ks][0], qh[ks][1], qh[ks][2], qh[ks][3], bh0, bh1);
                mma16816(sc[ni], qh[ks][0], qh[ks][1], qh[ks][2], qh[ks][3], bl0, bl1);
                mma16816(sc[ni], ql[ks][0], ql[ks][1], ql[ks][2], ql[ks][3], bh0, bh1);
            }
        }

        uint32_t pah[2][4], pal[2][4];
        const int nlim0 = min(mq0, n_hi);
        const int nlim1 = min(mq1, n_hi);
#pragma unroll
        for (int ni = 0; ni < 4; ++ni) {
            int nb = tb + ni * 8 + co;
            float p0 = (nb     <= nlim0) ? __expf(sc[ni][0]) : 0.f;
            float p1 = (nb + 1 <= nlim0) ? __expf(sc[ni][1]) : 0.f;
            float p2 = (nb     <= nlim1) ? __expf(sc[ni][2]) : 0.f;
            float p3 = (nb + 1 <= nlim1) ? __expf(sc[ni][3]) : 0.f;
            l0 += p0 + p1;
            l1 += p2 + p3;
            bf16 h0,lo0,h1,lo1,h2,lo2,h3,lo3;
            split_bf16(p0, h0, lo0);
            split_bf16(p1, h1, lo1);
            split_bf16(p2, h2, lo2);
            split_bf16(p3, h3, lo3);
            int kp = ni >> 1;
            int i0 = (ni & 1) * 2;
            pah[kp][i0]     = pack_bf2(h0, h1);
            pah[kp][i0 + 1] = pack_bf2(h2, h3);
            pal[kp][i0]     = pack_bf2(lo0, lo1);
            pal[kp][i0 + 1] = pack_bf2(lo2, lo3);
        }

#pragma unroll
        for (int kp = 0; kp < 2; ++kp) {
            int kw = kp * 16 + co;
#pragma unroll
            for (int nd = 0; nd < 8; ++nd) {
                int nr = nd * 8 + ro;
                uint32_t vh0 = *(const uint32_t*)&VTh[nr][kw];
                uint32_t vh1 = *(const uint32_t*)&VTh[nr][kw + 8];
                uint32_t vl0 = *(const uint32_t*)&VTl[nr][kw];
                uint32_t vl1 = *(const uint32_t*)&VTl[nr][kw + 8];
                mma16816(o[nd], pah[kp][0], pah[kp][1], pah[kp][2], pah[kp][3], vh0, vh1);
                mma16816(o[nd], pah[kp][0], pah[kp][1], pah[kp][2], pah[kp][3], vl0, vl1);
                mma16816(o[nd], pal[kp][0], pal[kp][1], pal[kp][2], pal[kp][3], vh0, vh1);
            }
        }
    }

    l0 += __shfl_xor_sync(0xffffffffu, l0, 1);
    l0 += __shfl_xor_sync(0xffffffffu, l0, 2);
    l1 += __shfl_xor_sync(0xffffffffu, l1, 1);
    l1 += __shfl_xor_sync(0xffffffffu, l1, 2);

#pragma unroll
    for (int half = 0; half < 2; ++half) {
        int m = (half == 0) ? mq0 : mq1;
        if (m > m_max) continue;
        float lsum = (half == 0) ? l0 : l1;
        int i_glob = r + p * m;
        if (nch == 1) {
            float inv = 1.f / lsum;   // diagonal key always present
            size_t base = ((size_t)(b_ * TT + i_glob)) * DD + h * HD;
#pragma unroll
            for (int nd = 0; nd < 8; ++nd) {
                int d = nd * 8 + co;
                float v0 = o[nd][half * 2]     * inv;
                float v1 = o[nd][half * 2 + 1] * inv;
                *(__half2*)(g_att + base + d) =
                    __halves2half2(__float2half_rn(v0), __float2half_rn(v1));
            }
        } else {
            if ((lane & 3) == 0) atomicAdd(&g_den[bh * TT + i_glob], lsum);
            float* np = g_num + ((size_t)(b_ * TT + i_glob)) * DD + h * HD;
#pragma unroll
            for (int nd = 0; nd < 8; ++nd) {
                int d = nd * 8 + co;
                atomicAdd(np + d,     o[nd][half * 2]);
                atomicAdd(np + d + 1, o[nd][half * 2 + 1]);
            }
        }
    }
}

// ---------------------------------------------------------------------------
// Finalize: normalize multi-chunk queries (den>0) and write fp16
// ---------------------------------------------------------------------------
__global__ __launch_bounds__(256) void finalize_kernel()
{
    int g = blockIdx.x * 256 + threadIdx.x;     // one float4 of num
    if (g >= MTOT*DD/4) return;
    int q   = g >> 4;              // query id: bh*2048 + t
    int dg  = (g & 15) * 4;        // dim group within head (0..60)
    float den = g_den[q];
    if (den == 0.f) return;
    int bh = q >> 11, t = q & (TT - 1);
    int b_ = bh >> 4, h = bh & 15;
    size_t base = ((size_t)(b_ * TT + t)) * DD + h * HD + dg;
    float4 nm = *(const float4*)(g_num + base);
    float inv = 1.f / den;
    __half2* oh = (__half2*)(g_att + base);
    oh[0] = __halves2half2(__float2half_rn(nm.x * inv), __float2half_rn(nm.y * inv));
    oh[1] = __halves2half2(__float2half_rn(nm.z * inv), __float2half_rn(nm.w * inv));
}

// ---------------------------------------------------------------------------
extern "C" void kernel_launch(void* const* d_in, const int* in_sizes, int n_in,
                              void* d_out, int out_size)
{
    const float* x      = (const float*)d_in[0];
    const void*  per    = d_in[1];                  // int32 or int64, detected on device
    const float* w_qkv  = (const float*)d_in[2];
    const float* b_qkv  = (const float*)d_in[3];
    const float* w_out  = (const float*)d_in[4];
    const float* b_out  = (const float*)d_in[5];
    float* out = (float*)d_out;

    cudaFuncSetAttribute(qkv_gemm_f16, cudaFuncAttributeMaxDynamicSharedMemorySize, GEMM_SMEM_BYTES);
    cudaFuncSetAttribute(out_gemm_f16, cudaFuncAttributeMaxDynamicSharedMemorySize, GEMM_SMEM_BYTES);

    // Fused pre-pass: split x, transpose weights, zero scratch, build worklist
    prepass_kernel<<<12289, 256>>>(x, w_qkv, w_out, per);

    dim3 g1(N3/128, MTOT/128);        // 24 x 32
    qkv_gemm_f16<<<g1, 256, GEMM_SMEM_BYTES>>>(b_qkv);

    attn_kernel<<<2560, 128>>>();
    finalize_kernel<<<(MTOT*DD/4 + 255)/256, 256>>>();

    dim3 g3(DD/128, MTOT/128);        // 8 x 32
    out_gemm_f16<<<g3, 256, GEMM_SMEM_BYTES>>>(b_out, out);
}

// round 16
// speedup vs baseline: 6.7661x; 1.4142x over previous
#include <cuda_runtime.h>
#include <cuda_bf16.h>
#include <cuda_fp16.h>
#include <math.h>
#include <stdint.h>

// Problem constants
#define BB 2
#define TT 2048
#define DD 1024
#define HH 16
#define HD 64
#define N3 3072
#define MTOT (BB*TT)          // 4096
#define KK 1024

typedef __half f16;

// ---------------------------------------------------------------------------
// Device-global scratch (allocation-free contract)
// ---------------------------------------------------------------------------
__device__ f16   g_x[MTOT*DD];          // x fp16, row-major [m][k]
__device__ f16   g_wqT[N3*KK];          // w_qkv^T fp16, [n][k]
__device__ f16   g_woT[DD*KK];          // w_out^T fp16, [n][k]
__device__ f16   g_q[BB*HH*TT*HD];      // (b,h,t,hd) fp16, q pre-scaled 1/8
__device__ f16   g_k[BB*HH*TT*HD];
__device__ f16   g_v[BB*HH*TT*HD];
__device__ f16   g_att[MTOT*DD];        // attention output (fp16), [m][d]
__device__ float g_num[MTOT*DD];        // multi-chunk partial numerator (b,t,d)
__device__ float g_den[BB*HH*TT];       // multi-chunk partial denominator [bh][t]
__device__ int      g_nwork;
__device__ uint32_t g_work[2600];

// ---------------------------------------------------------------------------
// helpers
// ---------------------------------------------------------------------------
__device__ __forceinline__ void split_f16(float x, f16& hi, f16& lo) {
    hi = __float2half_rn(x);
    lo = __float2half_rn(x - __half2float(hi));
}
__device__ __forceinline__ uint32_t pack_h2(f16 a, f16 b) {
    __half2 t = __halves2half2(a, b);
    return *(uint32_t*)&t;
}
__device__ __forceinline__ uint32_t smem_u32(const void* p) {
    uint32_t a;
    asm("{ .reg .u64 t; cvta.to.shared.u64 t, %1; cvt.u32.u64 %0, t; }" : "=r"(a) : "l"(p));
    return a;
}
__device__ __forceinline__ void cp16(void* smp, const void* g) {
    uint32_t s = (uint32_t)__cvta_generic_to_shared(smp);
    asm volatile("cp.async.cg.shared.global [%0], [%1], 16;\n" :: "r"(s), "l"(g));
}
__device__ __forceinline__ void cp_commit() { asm volatile("cp.async.commit_group;\n"); }
__device__ __forceinline__ void cp_wait0()  { asm volatile("cp.async.wait_group 0;\n"); }

// fp16 mma
__device__ __forceinline__ void mma16816h(float* c,
    uint32_t a0, uint32_t a1, uint32_t a2, uint32_t a3, uint32_t b0, uint32_t b1)
{
    asm volatile(
        "mma.sync.aligned.m16n8k16.row.col.f32.f16.f16.f32 "
        "{%0,%1,%2,%3}, {%4,%5,%6,%7}, {%8,%9}, {%0,%1,%2,%3};\n"
        : "+f"(c[0]), "+f"(c[1]), "+f"(c[2]), "+f"(c[3])
        : "r"(a0), "r"(a1), "r"(a2), "r"(a3), "r"(b0), "r"(b1));
}
__device__ __forceinline__ void ldsm_x4(uint32_t& r0, uint32_t& r1, uint32_t& r2, uint32_t& r3,
                                        uint32_t addr)
{
    asm volatile("ldmatrix.sync.aligned.m8n8.x4.shared.b16 {%0,%1,%2,%3}, [%4];"
                 : "=r"(r0), "=r"(r1), "=r"(r2), "=r"(r3) : "r"(addr));
}
__device__ __forceinline__ void ldsm_x2(uint32_t& r0, uint32_t& r1, uint32_t addr)
{
    asm volatile("ldmatrix.sync.aligned.m8n8.x2.shared.b16 {%0,%1}, [%2];"
                 : "=r"(r0), "=r"(r1) : "r"(addr));
}

// ---------------------------------------------------------------------------
// FUSED pre-pass kernel: block ranges do independent jobs in one launch.
//   [0,4096)     : fp16 convert of x -> g_x
//   [4096,7168)  : transpose w_qkv -> g_wqT (fp16)
//   [7168,8192)  : transpose w_out -> g_woT (fp16)
//   [8192,12288) : zero g_num/g_den
//   12288        : worklist build
// ---------------------------------------------------------------------------
__global__ __launch_bounds__(256) void prepass_kernel(
    const float* __restrict__ x, const float* __restrict__ wqkv,
    const float* __restrict__ wout, const void* __restrict__ periods_raw)
{
    __shared__ float t[32][33];
    const int b   = blockIdx.x;
    const int tid = threadIdx.x;

    if (b < 4096) {
        // ---- convert x to fp16 ----
        int i = b * 256 + tid;                    // one float4 per thread
        if (i < MTOT*DD/4) {
            float4 v = ((const float4*)x)[i];
            __half2* ph = (__half2*)g_x;
            ph[2*i]   = __halves2half2(__float2half_rn(v.x), __float2half_rn(v.y));
            ph[2*i+1] = __halves2half2(__float2half_rn(v.z), __float2half_rn(v.w));
        }
    } else if (b < 8192) {
        // ---- weight transpose (fp16) ----
        const float* src; f16* dst; int Ndim, idx;
        if (b < 7168) { src = wqkv; dst = g_wqT; Ndim = N3; idx = b - 4096; }
        else          { src = wout; dst = g_woT; Ndim = DD; idx = b - 7168; }
        int nb = Ndim / 32;
        int bx = idx % nb, by = idx / nb;
        int n0 = bx * 32, k0 = by * 32;
        int tx = tid & 31, ty = tid >> 5;         // (32,8)
#pragma unroll
        for (int i = 0; i < 4; ++i)
            t[ty + 8*i][tx] = src[(size_t)(k0 + ty + 8*i) * Ndim + n0 + tx];
        __syncthreads();
#pragma unroll
        for (int i = 0; i < 4; ++i) {
            float v = t[tx][ty + 8*i];
            size_t o = (size_t)(n0 + ty + 8*i) * KK + k0 + tx;
            dst[o] = __float2half_rn(v);
        }
    } else if (b < 12288) {
        // ---- zero scratch ----
        int i = (b - 8192) * 256 + tid;
        float4 z = make_float4(0.f, 0.f, 0.f, 0.f);
        if (i < MTOT*DD/4)  ((float4*)g_num)[i] = z;
        if (i < BB*HH*TT/4) ((float4*)g_den)[i] = z;
    } else {
        // ---- worklist (32 active threads) ----
        if (tid == 0) g_nwork = 0;
        __syncthreads();
        if (tid < 32) {
            const int* pw = (const int*)periods_raw;
            bool is64 = true;
#pragma unroll
            for (int k2 = 1; k2 < 32; k2 += 2) is64 = is64 && (pw[k2] == 0);
            int p = is64 ? pw[2*tid] : pw[tid];
            if (p < 1) p = 1;

            int cnt = 0;
            for (int r = 0; r < p; ++r) {
                int L = (TT - r + p - 1) / p;
                int qts = (L + 63) >> 6;
                for (int qt = 0; qt < qts; ++qt) {
                    int m_max = min(qt*64 + 63, L - 1);
                    cnt += (m_max >> 9) + 1;
                }
            }
            int base = atomicAdd(&g_nwork, cnt);
            for (int r = 0; r < p; ++r) {
                int L = (TT - r + p - 1) / p;
                int qts = (L + 63) >> 6;
                for (int qt = 0; qt < qts; ++qt) {
                    int m_max = min(qt*64 + 63, L - 1);
                    int nch = (m_max >> 9) + 1;
                    for (int kc = 0; kc < nch; ++kc)
                        g_work[base++] = (uint32_t)tid | ((uint32_t)r << 5) |
                                         ((uint32_t)qt << 9) | ((uint32_t)kc << 14) |
                                         ((uint32_t)p << 17) | ((uint32_t)nch << 21);
                }
            }
        }
    }
}

// ---------------------------------------------------------------------------
// GEMM core: 128x128 C-tile, fp16 x1, BK=32, 2-stage cp.async pipeline,
// ldmatrix fragment loads.
// ---------------------------------------------------------------------------
#define ST_STRIDE 10240
#define OFF_A 0
#define OFF_B 5120
#define GEMM_SMEM_BYTES (2*ST_STRIDE*2)

__device__ __forceinline__ void gemm_issue_stage(
    f16* st, const f16* A, const f16* BT, int m0, int n0, int k0, int tid)
{
#pragma unroll
    for (int it = 0; it < 2; ++it) {
        int ch  = tid + it * 256;          // 0..511
        int row = ch >> 2;
        int c8  = (ch & 3) << 3;
        size_t ao = (size_t)(m0 + row) * KK + k0 + c8;
        size_t bo = (size_t)(n0 + row) * KK + k0 + c8;
        int so = row * 40 + c8;
        cp16(st + OFF_A + so, A  + ao);
        cp16(st + OFF_B + so, BT + bo);
    }
}

__device__ __forceinline__ void gemm_core(
    const f16* __restrict__ A, const f16* __restrict__ BT,
    int m0, int n0, f16* sm, float c[4][4][4])
{
    const int tid  = threadIdx.x;
    const int lane = tid & 31;
    const int warp = tid >> 5;
    const int wm = warp >> 2;
    const int wn = warp & 3;

    const int a_lrow = lane & 15;
    const int a_lcol = (lane >> 4) << 3;
    const int b_lrow = lane & 7;
    const int b_lcol = ((lane >> 3) & 1) << 3;

#pragma unroll
    for (int i = 0; i < 4; ++i)
#pragma unroll
        for (int j = 0; j < 4; ++j)
#pragma unroll
            for (int q = 0; q < 4; ++q) c[i][j][q] = 0.f;

    gemm_issue_stage(sm, A, BT, m0, n0, 0, tid);
    cp_commit();

    const uint32_t sbase = smem_u32(sm);

    int s = 0;
    for (int k0 = 0; k0 < KK; k0 += 32, s ^= 1) {
        cp_wait0();
        __syncthreads();
        if (k0 + 32 < KK) {
            gemm_issue_stage(sm + (s^1)*ST_STRIDE, A, BT, m0, n0, k0 + 32, tid);
            cp_commit();
        }
        const uint32_t stb = sbase + (uint32_t)s * (ST_STRIDE * 2);   // bytes
#pragma unroll
        for (int ks = 0; ks < 2; ++ks) {
            const int kw = ks * 16;
            uint32_t bh[4][2];
#pragma unroll
            for (int ni = 0; ni < 4; ++ni) {
                uint32_t boff = (uint32_t)((wn*32 + ni*8 + b_lrow) * 40 + kw + b_lcol) * 2;
                ldsm_x2(bh[ni][0], bh[ni][1], stb + OFF_B*2 + boff);
            }
#pragma unroll
            for (int mi = 0; mi < 4; ++mi) {
                uint32_t aoff = (uint32_t)((wm*64 + mi*16 + a_lrow) * 40 + kw + a_lcol) * 2;
                uint32_t a0, a1, a2, a3;
                ldsm_x4(a0, a1, a2, a3, stb + OFF_A*2 + aoff);
#pragma unroll
                for (int ni = 0; ni < 4; ++ni)
                    mma16816h(c[mi][ni], a0, a1, a2, a3, bh[ni][0], bh[ni][1]);
            }
        }
        __syncthreads();
    }
}

// ---------------------------------------------------------------------------
// Kernel 1: QKV GEMM; epilogue emits single fp16 q/k/v (q pre-scaled 1/8)
// ---------------------------------------------------------------------------
__global__ __launch_bounds__(256, 2) void qkv_gemm_f16(const float* __restrict__ bias)
{
    extern __shared__ __align__(16) f16 dyns[];
    float c[4][4][4];
    const int m0 = blockIdx.y * 128;
    const int n0 = blockIdx.x * 128;
    gemm_core(g_x, g_wqT, m0, n0, dyns, c);

    const int tid  = threadIdx.x;
    const int lane = tid & 31;
    const int warp = tid >> 5;
    const int wm = warp >> 2, wn = warp & 3;
    const int ro = lane >> 2, co = (lane & 3) * 2;

    const int which = n0 >> 10;
    f16* dst = (which == 0) ? g_q : ((which == 1) ? g_k : g_v);
    const float scl = (which == 0) ? 0.125f : 1.0f;

#pragma unroll
    for (int mi = 0; mi < 4; ++mi) {
#pragma unroll
        for (int ni = 0; ni < 4; ++ni) {
            int n_a = n0 + wn * 32 + ni * 8 + co;
            int nn = n_a & (DD - 1);
            int hh = nn >> 6;
            int hd = nn & (HD - 1);
            float b0v = bias[n_a], b1v = bias[n_a + 1];
#pragma unroll
            for (int half = 0; half < 2; ++half) {
                int m = m0 + wm * 64 + mi * 16 + ro + half * 8;
                int b_ = m >> 11;
                int t_ = m & (TT - 1);
                float v0 = (c[mi][ni][half*2]     + b0v) * scl;
                float v1 = (c[mi][ni][half*2 + 1] + b1v) * scl;
                size_t off = (((size_t)(b_ * HH + hh) * TT + t_) << 6) + hd;
                *(__half2*)(dst + off) =
                    __halves2half2(__float2half_rn(v0), __float2half_rn(v1));
            }
        }
    }
}

// ---------------------------------------------------------------------------
// Kernel 3: output projection (x1 fp16) -> d_out fp32
// ---------------------------------------------------------------------------
__global__ __launch_bounds__(256, 2) void out_gemm_f16(
    const float* __restrict__ bias, float* __restrict__ Y)
{
    extern __shared__ __align__(16) f16 dyns[];
    float c[4][4][4];
    const int m0 = blockIdx.y * 128;
    const int n0 = blockIdx.x * 128;
    gemm_core(g_att, g_woT, m0, n0, dyns, c);

    const int tid  = threadIdx.x;
    const int lane = tid & 31;
    const int warp = tid >> 5;
    const int wm = warp >> 2, wn = warp & 3;
    const int ro = lane >> 2, co = (lane & 3) * 2;

#pragma unroll
    for (int mi = 0; mi < 4; ++mi) {
#pragma unroll
        for (int ni = 0; ni < 4; ++ni) {
            int n_a = n0 + wn * 32 + ni * 8 + co;
            float b0v = bias[n_a], b1v = bias[n_a + 1];
#pragma unroll
            for (int half = 0; half < 2; ++half) {
                int m = m0 + wm * 64 + mi * 16 + ro + half * 8;
                float2 v;
                v.x = c[mi][ni][half * 2]     + b0v;
                v.y = c[mi][ni][half * 2 + 1] + b1v;
                *(float2*)(Y + (size_t)m * DD + n_a) = v;
            }
        }
    }
}

// ---------------------------------------------------------------------------
// Kernel 2: periodic-sparse attention, fp16 tensor cores.
// QK^T: 1 MMA (q,k single fp16).  PV: 2 MMAs (p split hi/lo, v single fp16).
// ---------------------------------------------------------------------------
__global__ __launch_bounds__(128) void attn_kernel()
{
    if ((int)blockIdx.x >= g_nwork) return;
    const uint32_t e = g_work[blockIdx.x];
    const int bh  = e & 31;
    const int r   = (e >> 5)  & 15;
    const int qt  = (e >> 9)  & 31;
    const int kc  = (e >> 14) & 7;
    const int p   = (e >> 17) & 15;
    const int nch = (e >> 21) & 7;

    const int b_ = bh >> 4;
    const int h  = bh & 15;
    const int L  = (TT - r + p - 1) / p;
    const int m0 = qt * 64;
    const int m_max = min(m0 + 63, L - 1);
    const int n_lo = kc << 9;
    const int n_hi = min(n_lo + 511, m_max);

    __shared__ __align__(16) f16 Qs[64][72];
    __shared__ __align__(16) f16 Ks[32][72];
    __shared__ __align__(16) f16 VT[64][40];

    const int tid  = threadIdx.x;
    const int warp = tid >> 5;
    const int lane = tid & 31;
    const int ro = lane >> 2;
    const int co = (lane & 3) * 2;

    const size_t hb = (size_t)bh * TT;

    {   // stage Q tile (clamped rows for padded queries; masked later)
        int row = tid >> 1, hf = tid & 1;
        int mq = min(m0 + row, m_max);
        size_t off = (hb + (size_t)(r + p * mq)) * HD + hf * 32;
        const uint4* sq = (const uint4*)(g_q + off);
        uint4* dq = (uint4*)&Qs[row][hf * 32];
#pragma unroll
        for (int q = 0; q < 4; ++q) dq[q] = sq[q];
    }
    __syncthreads();

    // hoist Q fragments (A-frags, 4 k-steps covering 64 dims)
    uint32_t qf[4][4];
    {
        const int mr = warp * 16 + ro;
#pragma unroll
        for (int ks = 0; ks < 4; ++ks) {
            int kw = ks * 16 + co;
            qf[ks][0] = *(const uint32_t*)&Qs[mr][kw];
            qf[ks][1] = *(const uint32_t*)&Qs[mr + 8][kw];
            qf[ks][2] = *(const uint32_t*)&Qs[mr][kw + 8];
            qf[ks][3] = *(const uint32_t*)&Qs[mr + 8][kw + 8];
        }
    }

    float o[8][4];
#pragma unroll
    for (int nd = 0; nd < 8; ++nd)
#pragma unroll
        for (int q = 0; q < 4; ++q) o[nd][q] = 0.f;
    float l0 = 0.f, l1 = 0.f;
    const int mq0 = m0 + warp * 16 + ro;
    const int mq1 = mq0 + 8;

    for (int tb = n_lo; tb <= n_hi; tb += 32) {
        __syncthreads();
        {   // stage K rows + transpose V into VT
            int jrow = tid >> 2, q4 = tid & 3;
            int n = tb + jrow;
            if (n <= n_hi) {
                size_t off = (hb + (size_t)(r + p * n)) * HD + q4 * 16;
                const uint4* sk = (const uint4*)(g_k + off);
                *(uint4*)&Ks[jrow][q4*16]     = sk[0];
                *(uint4*)&Ks[jrow][q4*16 + 8] = sk[1];
                const uint32_t* vv = (const uint32_t*)(g_v + off);
#pragma unroll
                for (int dd = 0; dd < 8; ++dd) {
                    uint32_t w = vv[dd];
                    int d = q4 * 16 + dd * 2;
                    __half2 th = *(__half2*)&w;
                    VT[d][jrow]     = __low2half(th);
                    VT[d + 1][jrow] = __high2half(th);
                }
            } else {
                uint4 z = make_uint4(0,0,0,0);
                *(uint4*)&Ks[jrow][q4*16]     = z;
                *(uint4*)&Ks[jrow][q4*16 + 8] = z;
                f16 zh = __float2half_rn(0.f);
#pragma unroll
                for (int dd = 0; dd < 16; ++dd)
                    VT[q4 * 16 + dd][jrow] = zh;
            }
        }
        __syncthreads();

        // ---- S = Q.K^T (single fp16 MMA per fragment) ----
        float sc[4][4];
#pragma unroll
        for (int ni = 0; ni < 4; ++ni)
#pragma unroll
            for (int q = 0; q < 4; ++q) sc[ni][q] = 0.f;
#pragma unroll
        for (int ks = 0; ks < 4; ++ks) {
            int kw = ks * 16 + co;
#pragma unroll
            for (int ni = 0; ni < 4; ++ni) {
                int nr = ni * 8 + ro;
                uint32_t b0 = *(const uint32_t*)&Ks[nr][kw];
                uint32_t b1 = *(const uint32_t*)&Ks[nr][kw + 8];
                mma16816h(sc[ni], qf[ks][0], qf[ks][1], qf[ks][2], qf[ks][3], b0, b1);
            }
        }

        // ---- mask + exp + pack P fragments (fp16 hi/lo) ----
        uint32_t pah[2][4], pal[2][4];
        const int nlim0 = min(mq0, n_hi);
        const int nlim1 = min(mq1, n_hi);
#pragma unroll
        for (int ni = 0; ni < 4; ++ni) {
            int nb = tb + ni * 8 + co;
            float p0 = (nb     <= nlim0) ? __expf(sc[ni][0]) : 0.f;
            float p1 = (nb + 1 <= nlim0) ? __expf(sc[ni][1]) : 0.f;
            float p2 = (nb     <= nlim1) ? __expf(sc[ni][2]) : 0.f;
            float p3 = (nb + 1 <= nlim1) ? __expf(sc[ni][3]) : 0.f;
            l0 += p0 + p1;
            l1 += p2 + p3;
            f16 h0,lo0,h1,lo1,h2,lo2,h3,lo3;
            split_f16(p0, h0, lo0);
            split_f16(p1, h1, lo1);
            split_f16(p2, h2, lo2);
            split_f16(p3, h3, lo3);
            int kp = ni >> 1;
            int i0 = (ni & 1) * 2;
            pah[kp][i0]     = pack_h2(h0, h1);
            pah[kp][i0 + 1] = pack_h2(h2, h3);
            pal[kp][i0]     = pack_h2(lo0, lo1);
            pal[kp][i0 + 1] = pack_h2(lo2, lo3);
        }

        // ---- O += P.V (p hi/lo x single v) ----
#pragma unroll
        for (int kp = 0; kp < 2; ++kp) {
            int kw = kp * 16 + co;
#pragma unroll
            for (int nd = 0; nd < 8; ++nd) {
                int nr = nd * 8 + ro;
                uint32_t v0 = *(const uint32_t*)&VT[nr][kw];
                uint32_t v1 = *(const uint32_t*)&VT[nr][kw + 8];
                mma16816h(o[nd], pah[kp][0], pah[kp][1], pah[kp][2], pah[kp][3], v0, v1);
                mma16816h(o[nd], pal[kp][0], pal[kp][1], pal[kp][2], pal[kp][3], v0, v1);
            }
        }
    }

    l0 += __shfl_xor_sync(0xffffffffu, l0, 1);
    l0 += __shfl_xor_sync(0xffffffffu, l0, 2);
    l1 += __shfl_xor_sync(0xffffffffu, l1, 1);
    l1 += __shfl_xor_sync(0xffffffffu, l1, 2);

#pragma unroll
    for (int half = 0; half < 2; ++half) {
        int m = (half == 0) ? mq0 : mq1;
        if (m > m_max) continue;
        float lsum = (half == 0) ? l0 : l1;
        int i_glob = r + p * m;
        if (nch == 1) {
            float inv = 1.f / lsum;   // diagonal key always present
            size_t base = ((size_t)(b_ * TT + i_glob)) * DD + h * HD;
#pragma unroll
            for (int nd = 0; nd < 8; ++nd) {
                int d = nd * 8 + co;
                float v0 = o[nd][half * 2]     * inv;
                float v1 = o[nd][half * 2 + 1] * inv;
                *(__half2*)(g_att + base + d) =
                    __halves2half2(__float2half_rn(v0), __float2half_rn(v1));
            }
        } else {
            if ((lane & 3) == 0) atomicAdd(&g_den[bh * TT + i_glob], lsum);
            float* np = g_num + ((size_t)(b_ * TT + i_glob)) * DD + h * HD;
#pragma unroll
            for (int nd = 0; nd < 8; ++nd) {
                int d = nd * 8 + co;
                atomicAdd(np + d,     o[nd][half * 2]);
                atomicAdd(np + d + 1, o[nd][half * 2 + 1]);
            }
        }
    }
}

// ---------------------------------------------------------------------------
// Finalize: normalize multi-chunk queries (den>0) and write fp16
// ---------------------------------------------------------------------------
__global__ __launch_bounds__(256) void finalize_kernel()
{
    int g = blockIdx.x * 256 + threadIdx.x;     // one float4 of num
    if (g >= MTOT*DD/4) return;
    int q   = g >> 4;              // query id: bh*2048 + t
    int dg  = (g & 15) * 4;        // dim group within head (0..60)
    float den = g_den[q];
    if (den == 0.f) return;
    int bh = q >> 11, t = q & (TT - 1);
    int b_ = bh >> 4, h = bh & 15;
    size_t base = ((size_t)(b_ * TT + t)) * DD + h * HD + dg;
    float4 nm = *(const float4*)(g_num + base);
    float inv = 1.f / den;
    __half2* oh = (__half2*)(g_att + base);
    oh[0] = __halves2half2(__float2half_rn(nm.x * inv), __float2half_rn(nm.y * inv));
    oh[1] = __halves2half2(__float2half_rn(nm.z * inv), __float2half_rn(nm.w * inv));
}

// ---------------------------------------------------------------------------
extern "C" void kernel_launch(void* const* d_in, const int* in_sizes, int n_in,
                              void* d_out, int out_size)
{
    const float* x      = (const float*)d_in[0];
    const void*  per    = d_in[1];                  // int32 or int64, detected on device
    const float* w_qkv  = (const float*)d_in[2];
    const float* b_qkv  = (const float*)d_in[3];
    const float* w_out  = (const float*)d_in[4];
    const float* b_out  = (const float*)d_in[5];
    float* out = (float*)d_out;

    cudaFuncSetAttribute(qkv_gemm_f16, cudaFuncAttributeMaxDynamicSharedMemorySize, GEMM_SMEM_BYTES);
    cudaFuncSetAttribute(out_gemm_f16, cudaFuncAttributeMaxDynamicSharedMemorySize, GEMM_SMEM_BYTES);

    // Fused pre-pass: convert x, transpose weights, zero scratch, build worklist
    prepass_kernel<<<12289, 256>>>(x, w_qkv, w_out, per);

    dim3 g1(N3/128, MTOT/128);        // 24 x 32
    qkv_gemm_f16<<<g1, 256, GEMM_SMEM_BYTES>>>(b_qkv);

    attn_kernel<<<2560, 128>>>();
    finalize_kernel<<<(MTOT*DD/4 + 255)/256, 256>>>();

    dim3 g3(DD/128, MTOT/128);        // 8 x 32
    out_gemm_f16<<<g3, 256, GEMM_SMEM_BYTES>>>(b_out, out);
}

// round 17
// speedup vs baseline: 7.2224x; 1.0674x over previous
#include <cuda_runtime.h>
#include <cuda_bf16.h>
#include <cuda_fp16.h>
#include <math.h>
#include <stdint.h>

// Problem constants
#define BB 2
#define TT 2048
#define DD 1024
#define HH 16
#define HD 64
#define N3 3072
#define MTOT (BB*TT)          // 4096
#define KK 1024

typedef __half f16;

// ---------------------------------------------------------------------------
// Device-global scratch (allocation-free contract)
// ---------------------------------------------------------------------------
__device__ f16   g_x[MTOT*DD];          // x fp16, row-major [m][k]
__device__ f16   g_wqT[N3*KK];          // w_qkv^T fp16, [n][k]
__device__ f16   g_woT[DD*KK];          // w_out^T fp16, [n][k]
__device__ f16   g_q[BB*HH*TT*HD];      // (b,h,t,hd) fp16, q pre-scaled 1/8
__device__ f16   g_k[BB*HH*TT*HD];
__device__ f16   g_v[BB*HH*TT*HD];
__device__ f16   g_att[MTOT*DD];        // attention output (fp16), [m][d]
__device__ float g_num[MTOT*DD];        // multi-chunk partial numerator (b,t,d)
__device__ float g_den[BB*HH*TT];       // multi-chunk partial denominator [bh][t]
__device__ int      g_nwork;
__device__ uint32_t g_work[2600];

// ---------------------------------------------------------------------------
// helpers
// ---------------------------------------------------------------------------
__device__ __forceinline__ uint32_t smem_u32(const void* p) {
    uint32_t a;
    asm("{ .reg .u64 t; cvta.to.shared.u64 t, %1; cvt.u32.u64 %0, t; }" : "=r"(a) : "l"(p));
    return a;
}
__device__ __forceinline__ void cp16(void* smp, const void* g) {
    uint32_t s = (uint32_t)__cvta_generic_to_shared(smp);
    asm volatile("cp.async.cg.shared.global [%0], [%1], 16;\n" :: "r"(s), "l"(g));
}
__device__ __forceinline__ void cp_commit() { asm volatile("cp.async.commit_group;\n"); }
__device__ __forceinline__ void cp_wait0()  { asm volatile("cp.async.wait_group 0;\n"); }

// fp16 mma
__device__ __forceinline__ void mma16816h(float* c,
    uint32_t a0, uint32_t a1, uint32_t a2, uint32_t a3, uint32_t b0, uint32_t b1)
{
    asm volatile(
        "mma.sync.aligned.m16n8k16.row.col.f32.f16.f16.f32 "
        "{%0,%1,%2,%3}, {%4,%5,%6,%7}, {%8,%9}, {%0,%1,%2,%3};\n"
        : "+f"(c[0]), "+f"(c[1]), "+f"(c[2]), "+f"(c[3])
        : "r"(a0), "r"(a1), "r"(a2), "r"(a3), "r"(b0), "r"(b1));
}
__device__ __forceinline__ void ldsm_x4(uint32_t& r0, uint32_t& r1, uint32_t& r2, uint32_t& r3,
                                        uint32_t addr)
{
    asm volatile("ldmatrix.sync.aligned.m8n8.x4.shared.b16 {%0,%1,%2,%3}, [%4];"
                 : "=r"(r0), "=r"(r1), "=r"(r2), "=r"(r3) : "r"(addr));
}
__device__ __forceinline__ void ldsm_x2(uint32_t& r0, uint32_t& r1, uint32_t addr)
{
    asm volatile("ldmatrix.sync.aligned.m8n8.x2.shared.b16 {%0,%1}, [%2];"
                 : "=r"(r0), "=r"(r1) : "r"(addr));
}
__device__ __forceinline__ void ldsm_x2_t(uint32_t& r0, uint32_t& r1, uint32_t addr)
{
    asm volatile("ldmatrix.sync.aligned.m8n8.x2.trans.shared.b16 {%0,%1}, [%2];"
                 : "=r"(r0), "=r"(r1) : "r"(addr));
}

// ---------------------------------------------------------------------------
// FUSED pre-pass kernel: block ranges do independent jobs in one launch.
//   [0,4096)     : fp16 convert of x -> g_x
//   [4096,7168)  : transpose w_qkv -> g_wqT (fp16)
//   [7168,8192)  : transpose w_out -> g_woT (fp16)
//   [8192,12288) : zero g_num/g_den
//   12288        : worklist build
// ---------------------------------------------------------------------------
__global__ __launch_bounds__(256) void prepass_kernel(
    const float* __restrict__ x, const float* __restrict__ wqkv,
    const float* __restrict__ wout, const void* __restrict__ periods_raw)
{
    __shared__ float t[32][33];
    const int b   = blockIdx.x;
    const int tid = threadIdx.x;

    if (b < 4096) {
        // ---- convert x to fp16 ----
        int i = b * 256 + tid;                    // one float4 per thread
        if (i < MTOT*DD/4) {
            float4 v = ((const float4*)x)[i];
            __half2* ph = (__half2*)g_x;
            ph[2*i]   = __halves2half2(__float2half_rn(v.x), __float2half_rn(v.y));
            ph[2*i+1] = __halves2half2(__float2half_rn(v.z), __float2half_rn(v.w));
        }
    } else if (b < 8192) {
        // ---- weight transpose (fp16) ----
        const float* src; f16* dst; int Ndim, idx;
        if (b < 7168) { src = wqkv; dst = g_wqT; Ndim = N3; idx = b - 4096; }
        else          { src = wout; dst = g_woT; Ndim = DD; idx = b - 7168; }
        int nb = Ndim / 32;
        int bx = idx % nb, by = idx / nb;
        int n0 = bx * 32, k0 = by * 32;
        int tx = tid & 31, ty = tid >> 5;         // (32,8)
#pragma unroll
        for (int i = 0; i < 4; ++i)
            t[ty + 8*i][tx] = src[(size_t)(k0 + ty + 8*i) * Ndim + n0 + tx];
        __syncthreads();
#pragma unroll
        for (int i = 0; i < 4; ++i) {
            float v = t[tx][ty + 8*i];
            size_t o = (size_t)(n0 + ty + 8*i) * KK + k0 + tx;
            dst[o] = __float2half_rn(v);
        }
    } else if (b < 12288) {
        // ---- zero scratch ----
        int i = (b - 8192) * 256 + tid;
        float4 z = make_float4(0.f, 0.f, 0.f, 0.f);
        if (i < MTOT*DD/4)  ((float4*)g_num)[i] = z;
        if (i < BB*HH*TT/4) ((float4*)g_den)[i] = z;
    } else {
        // ---- worklist (32 active threads) ----
        if (tid == 0) g_nwork = 0;
        __syncthreads();
        if (tid < 32) {
            const int* pw = (const int*)periods_raw;
            bool is64 = true;
#pragma unroll
            for (int k2 = 1; k2 < 32; k2 += 2) is64 = is64 && (pw[k2] == 0);
            int p = is64 ? pw[2*tid] : pw[tid];
            if (p < 1) p = 1;

            int cnt = 0;
            for (int r = 0; r < p; ++r) {
                int L = (TT - r + p - 1) / p;
                int qts = (L + 63) >> 6;
                for (int qt = 0; qt < qts; ++qt) {
                    int m_max = min(qt*64 + 63, L - 1);
                    cnt += (m_max >> 9) + 1;
                }
            }
            int base = atomicAdd(&g_nwork, cnt);
            for (int r = 0; r < p; ++r) {
                int L = (TT - r + p - 1) / p;
                int qts = (L + 63) >> 6;
                for (int qt = 0; qt < qts; ++qt) {
                    int m_max = min(qt*64 + 63, L - 1);
                    int nch = (m_max >> 9) + 1;
                    for (int kc = 0; kc < nch; ++kc)
                        g_work[base++] = (uint32_t)tid | ((uint32_t)r << 5) |
                                         ((uint32_t)qt << 9) | ((uint32_t)kc << 14) |
                                         ((uint32_t)p << 17) | ((uint32_t)nch << 21);
                }
            }
        }
    }
}

// ---------------------------------------------------------------------------
// GEMM core: 128x128 C-tile, fp16 x1, BK=32, 2-stage cp.async pipeline,
// ldmatrix fragment loads.
// ---------------------------------------------------------------------------
#define ST_STRIDE 10240
#define OFF_A 0
#define OFF_B 5120
#define GEMM_SMEM_BYTES (2*ST_STRIDE*2)

__device__ __forceinline__ void gemm_issue_stage(
    f16* st, const f16* A, const f16* BT, int m0, int n0, int k0, int tid)
{
#pragma unroll
    for (int it = 0; it < 2; ++it) {
        int ch  = tid + it * 256;          // 0..511
        int row = ch >> 2;
        int c8  = (ch & 3) << 3;
        size_t ao = (size_t)(m0 + row) * KK + k0 + c8;
        size_t bo = (size_t)(n0 + row) * KK + k0 + c8;
        int so = row * 40 + c8;
        cp16(st + OFF_A + so, A  + ao);
        cp16(st + OFF_B + so, BT + bo);
    }
}

__device__ __forceinline__ void gemm_core(
    const f16* __restrict__ A, const f16* __restrict__ BT,
    int m0, int n0, f16* sm, float c[4][4][4])
{
    const int tid  = threadIdx.x;
    const int lane = tid & 31;
    const int warp = tid >> 5;
    const int wm = warp >> 2;
    const int wn = warp & 3;

    const int a_lrow = lane & 15;
    const int a_lcol = (lane >> 4) << 3;
    const int b_lrow = lane & 7;
    const int b_lcol = ((lane >> 3) & 1) << 3;

#pragma unroll
    for (int i = 0; i < 4; ++i)
#pragma unroll
        for (int j = 0; j < 4; ++j)
#pragma unroll
            for (int q = 0; q < 4; ++q) c[i][j][q] = 0.f;

    gemm_issue_stage(sm, A, BT, m0, n0, 0, tid);
    cp_commit();

    const uint32_t sbase = smem_u32(sm);

    int s = 0;
    for (int k0 = 0; k0 < KK; k0 += 32, s ^= 1) {
        cp_wait0();
        __syncthreads();
        if (k0 + 32 < KK) {
            gemm_issue_stage(sm + (s^1)*ST_STRIDE, A, BT, m0, n0, k0 + 32, tid);
            cp_commit();
        }
        const uint32_t stb = sbase + (uint32_t)s * (ST_STRIDE * 2);   // bytes
#pragma unroll
        for (int ks = 0; ks < 2; ++ks) {
            const int kw = ks * 16;
            uint32_t bh[4][2];
#pragma unroll
            for (int ni = 0; ni < 4; ++ni) {
                uint32_t boff = (uint32_t)((wn*32 + ni*8 + b_lrow) * 40 + kw + b_lcol) * 2;
                ldsm_x2(bh[ni][0], bh[ni][1], stb + OFF_B*2 + boff);
            }
#pragma unroll
            for (int mi = 0; mi < 4; ++mi) {
                uint32_t aoff = (uint32_t)((wm*64 + mi*16 + a_lrow) * 40 + kw + a_lcol) * 2;
                uint32_t a0, a1, a2, a3;
                ldsm_x4(a0, a1, a2, a3, stb + OFF_A*2 + aoff);
#pragma unroll
                for (int ni = 0; ni < 4; ++ni)
                    mma16816h(c[mi][ni], a0, a1, a2, a3, bh[ni][0], bh[ni][1]);
            }
        }
        __syncthreads();
    }
}

// ---------------------------------------------------------------------------
// Kernel 1: QKV GEMM; epilogue emits single fp16 q/k/v (q pre-scaled 1/8)
// ---------------------------------------------------------------------------
__global__ __launch_bounds__(256, 2) void qkv_gemm_f16(const float* __restrict__ bias)
{
    extern __shared__ __align__(16) f16 dyns[];
    float c[4][4][4];
    const int m0 = blockIdx.y * 128;
    const int n0 = blockIdx.x * 128;
    gemm_core(g_x, g_wqT, m0, n0, dyns, c);

    const int tid  = threadIdx.x;
    const int lane = tid & 31;
    const int warp = tid >> 5;
    const int wm = warp >> 2, wn = warp & 3;
    const int ro = lane >> 2, co = (lane & 3) * 2;

    const int which = n0 >> 10;
    f16* dst = (which == 0) ? g_q : ((which == 1) ? g_k : g_v);
    const float scl = (which == 0) ? 0.125f : 1.0f;

#pragma unroll
    for (int mi = 0; mi < 4; ++mi) {
#pragma unroll
        for (int ni = 0; ni < 4; ++ni) {
            int n_a = n0 + wn * 32 + ni * 8 + co;
            int nn = n_a & (DD - 1);
            int hh = nn >> 6;
            int hd = nn & (HD - 1);
            float b0v = bias[n_a], b1v = bias[n_a + 1];
#pragma unroll
            for (int half = 0; half < 2; ++half) {
                int m = m0 + wm * 64 + mi * 16 + ro + half * 8;
                int b_ = m >> 11;
                int t_ = m & (TT - 1);
                float v0 = (c[mi][ni][half*2]     + b0v) * scl;
                float v1 = (c[mi][ni][half*2 + 1] + b1v) * scl;
                size_t off = (((size_t)(b_ * HH + hh) * TT + t_) << 6) + hd;
                *(__half2*)(dst + off) =
                    __halves2half2(__float2half_rn(v0), __float2half_rn(v1));
            }
        }
    }
}

// ---------------------------------------------------------------------------
// Kernel 3: output projection (x1 fp16) -> d_out fp32
// ---------------------------------------------------------------------------
__global__ __launch_bounds__(256, 2) void out_gemm_f16(
    const float* __restrict__ bias, float* __restrict__ Y)
{
    extern __shared__ __align__(16) f16 dyns[];
    float c[4][4][4];
    const int m0 = blockIdx.y * 128;
    const int n0 = blockIdx.x * 128;
    gemm_core(g_att, g_woT, m0, n0, dyns, c);

    const int tid  = threadIdx.x;
    const int lane = tid & 31;
    const int warp = tid >> 5;
    const int wm = warp >> 2, wn = warp & 3;
    const int ro = lane >> 2, co = (lane & 3) * 2;

#pragma unroll
    for (int mi = 0; mi < 4; ++mi) {
#pragma unroll
        for (int ni = 0; ni < 4; ++ni) {
            int n_a = n0 + wn * 32 + ni * 8 + co;
            float b0v = bias[n_a], b1v = bias[n_a + 1];
#pragma unroll
            for (int half = 0; half < 2; ++half) {
                int m = m0 + wm * 64 + mi * 16 + ro + half * 8;
                float2 v;
                v.x = c[mi][ni][half * 2]     + b0v;
                v.y = c[mi][ni][half * 2 + 1] + b1v;
                *(float2*)(Y + (size_t)m * DD + n_a) = v;
            }
        }
    }
}

// ---------------------------------------------------------------------------
// Kernel 2: periodic-sparse attention, fp16 tensor cores.
// QK^T: 1 MMA (q,k fp16).  PV: 1 MMA (p fp16 direct; independent rounding
// errors average out in the normalized sum).  V staged [key][d] like K;
// PV B-fragments via ldmatrix.x2.trans (no scalar transpose).
// ---------------------------------------------------------------------------
__global__ __launch_bounds__(128) void attn_kernel()
{
    if ((int)blockIdx.x >= g_nwork) return;
    const uint32_t e = g_work[blockIdx.x];
    const int bh  = e & 31;
    const int r   = (e >> 5)  & 15;
    const int qt  = (e >> 9)  & 31;
    const int kc  = (e >> 14) & 7;
    const int p   = (e >> 17) & 15;
    const int nch = (e >> 21) & 7;

    const int b_ = bh >> 4;
    const int h  = bh & 15;
    const int L  = (TT - r + p - 1) / p;
    const int m0 = qt * 64;
    const int m_max = min(m0 + 63, L - 1);
    const int n_lo = kc << 9;
    const int n_hi = min(n_lo + 511, m_max);

    __shared__ __align__(16) f16 Qs[64][72];
    __shared__ __align__(16) f16 Ks[32][72];
    __shared__ __align__(16) f16 Vs[32][72];

    const int tid  = threadIdx.x;
    const int warp = tid >> 5;
    const int lane = tid & 31;
    const int ro = lane >> 2;
    const int co = (lane & 3) * 2;

    const size_t hb = (size_t)bh * TT;
    const uint32_t sVs = smem_u32(&Vs[0][0]);

    {   // stage Q tile (clamped rows for padded queries; masked later)
        int row = tid >> 1, hf = tid & 1;
        int mq = min(m0 + row, m_max);
        size_t off = (hb + (size_t)(r + p * mq)) * HD + hf * 32;
        const uint4* sq = (const uint4*)(g_q + off);
        uint4* dq = (uint4*)&Qs[row][hf * 32];
#pragma unroll
        for (int q = 0; q < 4; ++q) dq[q] = sq[q];
    }
    __syncthreads();

    // hoist Q fragments (A-frags, 4 k-steps covering 64 dims)
    uint32_t qf[4][4];
    {
        const int mr = warp * 16 + ro;
#pragma unroll
        for (int ks = 0; ks < 4; ++ks) {
            int kw = ks * 16 + co;
            qf[ks][0] = *(const uint32_t*)&Qs[mr][kw];
            qf[ks][1] = *(const uint32_t*)&Qs[mr + 8][kw];
            qf[ks][2] = *(const uint32_t*)&Qs[mr][kw + 8];
            qf[ks][3] = *(const uint32_t*)&Qs[mr + 8][kw + 8];
        }
    }

    float o[8][4];
#pragma unroll
    for (int nd = 0; nd < 8; ++nd)
#pragma unroll
        for (int q = 0; q < 4; ++q) o[nd][q] = 0.f;
    float l0 = 0.f, l1 = 0.f;
    const int mq0 = m0 + warp * 16 + ro;
    const int mq1 = mq0 + 8;

    for (int tb = n_lo; tb <= n_hi; tb += 32) {
        __syncthreads();
        {   // stage K and V rows (both [key][d], vector copies)
            int jrow = tid >> 2, q4 = tid & 3;
            int n = tb + jrow;
            if (n <= n_hi) {
                size_t off = (hb + (size_t)(r + p * n)) * HD + q4 * 16;
                const uint4* sk = (const uint4*)(g_k + off);
                const uint4* sv = (const uint4*)(g_v + off);
                *(uint4*)&Ks[jrow][q4*16]     = sk[0];
                *(uint4*)&Ks[jrow][q4*16 + 8] = sk[1];
                *(uint4*)&Vs[jrow][q4*16]     = sv[0];
                *(uint4*)&Vs[jrow][q4*16 + 8] = sv[1];
            } else {
                uint4 z = make_uint4(0,0,0,0);
                *(uint4*)&Ks[jrow][q4*16]     = z;
                *(uint4*)&Ks[jrow][q4*16 + 8] = z;
                *(uint4*)&Vs[jrow][q4*16]     = z;
                *(uint4*)&Vs[jrow][q4*16 + 8] = z;
            }
        }
        __syncthreads();

        // ---- S = Q.K^T (single fp16 MMA per fragment) ----
        float sc[4][4];
#pragma unroll
        for (int ni = 0; ni < 4; ++ni)
#pragma unroll
            for (int q = 0; q < 4; ++q) sc[ni][q] = 0.f;
#pragma unroll
        for (int ks = 0; ks < 4; ++ks) {
            int kw = ks * 16 + co;
#pragma unroll
            for (int ni = 0; ni < 4; ++ni) {
                int nr = ni * 8 + ro;
                uint32_t b0 = *(const uint32_t*)&Ks[nr][kw];
                uint32_t b1 = *(const uint32_t*)&Ks[nr][kw + 8];
                mma16816h(sc[ni], qf[ks][0], qf[ks][1], qf[ks][2], qf[ks][3], b0, b1);
            }
        }

        // ---- mask + exp + pack P fragments (single fp16) ----
        uint32_t pa[2][4];
        const int nlim0 = min(mq0, n_hi);
        const int nlim1 = min(mq1, n_hi);
#pragma unroll
        for (int ni = 0; ni < 4; ++ni) {
            int nb = tb + ni * 8 + co;
            float p0 = (nb     <= nlim0) ? __expf(sc[ni][0]) : 0.f;
            float p1 = (nb + 1 <= nlim0) ? __expf(sc[ni][1]) : 0.f;
            float p2 = (nb     <= nlim1) ? __expf(sc[ni][2]) : 0.f;
            float p3 = (nb + 1 <= nlim1) ? __expf(sc[ni][3]) : 0.f;
            l0 += p0 + p1;
            l1 += p2 + p3;
            int kp = ni >> 1;
            int i0 = (ni & 1) * 2;
            __half2 h01 = __halves2half2(__float2half_rn(p0), __float2half_rn(p1));
            __half2 h23 = __halves2half2(__float2half_rn(p2), __float2half_rn(p3));
            pa[kp][i0]     = *(uint32_t*)&h01;
            pa[kp][i0 + 1] = *(uint32_t*)&h23;
        }

        // ---- O += P.V  (B-fragments via ldmatrix.trans on Vs[key][d]) ----
#pragma unroll
        for (int kp = 0; kp < 2; ++kp) {
            uint32_t vaddr = sVs + (uint32_t)((kp * 16 + (lane & 15)) * 72) * 2;
#pragma unroll
            for (int nd = 0; nd < 8; ++nd) {
                uint32_t v0, v1;
                ldsm_x2_t(v0, v1, vaddr + (uint32_t)(nd * 16));
                mma16816h(o[nd], pa[kp][0], pa[kp][1], pa[kp][2], pa[kp][3], v0, v1);
            }
        }
    }

    l0 += __shfl_xor_sync(0xffffffffu, l0, 1);
    l0 += __shfl_xor_sync(0xffffffffu, l0, 2);
    l1 += __shfl_xor_sync(0xffffffffu, l1, 1);
    l1 += __shfl_xor_sync(0xffffffffu, l1, 2);

#pragma unroll
    for (int half = 0; half < 2; ++half) {
        int m = (half == 0) ? mq0 : mq1;
        if (m > m_max) continue;
        float lsum = (half == 0) ? l0 : l1;
        int i_glob = r + p * m;
        if (nch == 1) {
            float inv = 1.f / lsum;   // diagonal key always present
            size_t base = ((size_t)(b_ * TT + i_glob)) * DD + h * HD;
#pragma unroll
            for (int nd = 0; nd < 8; ++nd) {
                int d = nd * 8 + co;
                float v0 = o[nd][half * 2]     * inv;
                float v1 = o[nd][half * 2 + 1] * inv;
                *(__half2*)(g_att + base + d) =
                    __halves2half2(__float2half_rn(v0), __float2half_rn(v1));
            }
        } else {
            if ((lane & 3) == 0) atomicAdd(&g_den[bh * TT + i_glob], lsum);
            float* np = g_num + ((size_t)(b_ * TT + i_glob)) * DD + h * HD;
#pragma unroll
            for (int nd = 0; nd < 8; ++nd) {
                int d = nd * 8 + co;
                atomicAdd(np + d,     o[nd][half * 2]);
                atomicAdd(np + d + 1, o[nd][half * 2 + 1]);
            }
        }
    }
}

// ---------------------------------------------------------------------------
// Finalize: normalize multi-chunk queries (den>0) and write fp16
// ---------------------------------------------------------------------------
__global__ __launch_bounds__(256) void finalize_kernel()
{
    int g = blockIdx.x * 256 + threadIdx.x;     // one float4 of num
    if (g >= MTOT*DD/4) return;
    int q   = g >> 4;              // query id: bh*2048 + t
    int dg  = (g & 15) * 4;        // dim group within head (0..60)
    float den = g_den[q];
    if (den == 0.f) return;
    int bh = q >> 11, t = q & (TT - 1);
    int b_ = bh >> 4, h = bh & 15;
    size_t base = ((size_t)(b_ * TT + t)) * DD + h * HD + dg;
    float4 nm = *(const float4*)(g_num + base);
    float inv = 1.f / den;
    __half2* oh = (__half2*)(g_att + base);
    oh[0] = __halves2half2(__float2half_rn(nm.x * inv), __float2half_rn(nm.y * inv));
    oh[1] = __halves2half2(__float2half_rn(nm.z * inv), __float2half_rn(nm.w * inv));
}

// ---------------------------------------------------------------------------
extern "C" void kernel_launch(void* const* d_in, const int* in_sizes, int n_in,
                              void* d_out, int out_size)
{
    const float* x      = (const float*)d_in[0];
    const void*  per    = d_in[1];                  // int32 or int64, detected on device
    const float* w_qkv  = (const float*)d_in[2];
    const float* b_qkv  = (const float*)d_in[3];
    const float* w_out  = (const float*)d_in[4];
    const float* b_out  = (const float*)d_in[5];
    float* out = (float*)d_out;

    cudaFuncSetAttribute(qkv_gemm_f16, cudaFuncAttributeMaxDynamicSharedMemorySize, GEMM_SMEM_BYTES);
    cudaFuncSetAttribute(out_gemm_f16, cudaFuncAttributeMaxDynamicSharedMemorySize, GEMM_SMEM_BYTES);

    // Fused pre-pass: convert x, transpose weights, zero scratch, build worklist
    prepass_kernel<<<12289, 256>>>(x, w_qkv, w_out, per);

    dim3 g1(N3/128, MTOT/128);        // 24 x 32
    qkv_gemm_f16<<<g1, 256, GEMM_SMEM_BYTES>>>(b_qkv);

    attn_kernel<<<2560, 128>>>();
    finalize_kernel<<<(MTOT*DD/4 + 255)/256, 256>>>();

    dim3 g3(DD/128, MTOT/128);        // 8 x 32
    out_gemm_f16<<<g3, 256, GEMM_SMEM_BYTES>>>(b_out, out);
}